// round 5
// baseline (speedup 1.0000x reference)
#include <cuda_runtime.h>
#include <math.h>

// ---------------- problem constants ----------------
#define BSZ     8
#define PAIRS   5
#define CCH     2
#define PGRID   8          // P
#define RRES    16         // R
#define HWDIM   128        // P*R
#define SEQ     640        // PAIRS*2*P*P
#define DMODEL  512
#define NHEAD   8
#define DHEAD   64
#define DFFN    2048
#define NLAYER  6
#define NTOK    (BSZ*SEQ)  // 5120
#define NSEL    (BSZ*PAIRS*PGRID*PGRID)  // 2560

// ---------------- scratch (device globals; no allocation allowed) ----------
__device__ float g_x  [NTOK*DMODEL];      // token stream f
__device__ float g_qkv[NTOK*3*DMODEL];    // qkv (also reused as patchified X)
__device__ float g_a  [NTOK*DMODEL];      // attention output / gathered rows
__device__ float g_h  [NTOK*DFFN];        // FF hidden
__device__ float g_o  [NTOK*DMODEL];      // generic gemm output

// ---------------- patchify: (init,end) -> X[5120, 512] ----------------
__global__ void patchify_kernel(const float* __restrict__ initp,
                                const float* __restrict__ endp,
                                float* __restrict__ X)
{
    int idx = blockIdx.x * blockDim.x + threadIdx.x;   // NTOK*DMODEL threads
    int fi = idx & 511;
    int n  = idx >> 9;
    int b  = n / SEQ;
    int s  = n - b * SEQ;
    int fn = s >> 6;            // pair*2 + io
    int patch = s & 63;
    int pair = fn >> 1, io = fn & 1;
    int pr = patch >> 3, pc = patch & 7;
    int ch = fi >> 8;
    int rem = fi & 255;
    int i = rem >> 4, j = rem & 15;
    const float* src = io ? endp : initp;
    int h = pr * RRES + i, w = pc * RRES + j;
    X[idx] = src[((((size_t)b * PAIRS + pair) * CCH + ch) * HWDIM + h) * HWDIM + w];
}

// ---------------- positional add ----------------
__global__ void add_pos_kernel(float* __restrict__ x,
                               const float* __restrict__ patch_pos,
                               const float* __restrict__ func_pos)
{
    int idx = blockIdx.x * blockDim.x + threadIdx.x;
    int d = idx & 511;
    int n = idx >> 9;
    int s = n % SEQ;
    int fn = s >> 6;
    int patch = s & 63;
    x[idx] += patch_pos[patch * DMODEL + d] + func_pos[fn * DMODEL + d];
}

// ---------------- generic 128x128x8 SGEMM: C = A[N,K] @ W[J,K]^T + bias ----
// act: 0 = none, 1 = exact GELU
__global__ __launch_bounds__(256)
void gemm_kernel(const float* __restrict__ A, const float* __restrict__ W,
                 const float* __restrict__ bias, float* __restrict__ C,
                 int K, int J, int act)
{
    __shared__ float As[8][128];
    __shared__ float Ws[8][128];
    int t  = threadIdx.x;
    int n0 = blockIdx.y * 128;
    int j0 = blockIdx.x * 128;
    int tx = t & 15, ty = t >> 4;

    float acc[8][8];
#pragma unroll
    for (int i = 0; i < 8; i++)
#pragma unroll
        for (int j = 0; j < 8; j++) acc[i][j] = 0.0f;

    int lr = t >> 1;           // 0..127
    int lk = (t & 1) * 4;      // 0 or 4
    const float* Aptr = A + (size_t)(n0 + lr) * K + lk;
    const float* Wptr = W + (size_t)(j0 + lr) * K + lk;

    for (int kt = 0; kt < K; kt += 8) {
        float4 a4 = *(const float4*)(Aptr + kt);
        float4 w4 = *(const float4*)(Wptr + kt);
        __syncthreads();
        As[lk + 0][lr] = a4.x; As[lk + 1][lr] = a4.y;
        As[lk + 2][lr] = a4.z; As[lk + 3][lr] = a4.w;
        Ws[lk + 0][lr] = w4.x; Ws[lk + 1][lr] = w4.y;
        Ws[lk + 2][lr] = w4.z; Ws[lk + 3][lr] = w4.w;
        __syncthreads();
#pragma unroll
        for (int kk = 0; kk < 8; kk++) {
            float4 a0 = *(float4*)&As[kk][ty * 8];
            float4 a1 = *(float4*)&As[kk][ty * 8 + 4];
            float4 b0 = *(float4*)&Ws[kk][tx * 8];
            float4 b1 = *(float4*)&Ws[kk][tx * 8 + 4];
            float av[8] = {a0.x, a0.y, a0.z, a0.w, a1.x, a1.y, a1.z, a1.w};
            float bv[8] = {b0.x, b0.y, b0.z, b0.w, b1.x, b1.y, b1.z, b1.w};
#pragma unroll
            for (int i = 0; i < 8; i++)
#pragma unroll
                for (int j = 0; j < 8; j++)
                    acc[i][j] += av[i] * bv[j];
        }
    }

    int rbase = n0 + ty * 8;
    int cbase = j0 + tx * 8;
    float bv2[8];
#pragma unroll
    for (int j = 0; j < 8; j++) bv2[j] = bias[cbase + j];
#pragma unroll
    for (int i = 0; i < 8; i++) {
        float vals[8];
#pragma unroll
        for (int j = 0; j < 8; j++) {
            float v = acc[i][j] + bv2[j];
            if (act == 1) v = 0.5f * v * (1.0f + erff(v * 0.70710678118654752f));
            vals[j] = v;
        }
        float* cp = C + (size_t)(rbase + i) * J + cbase;
        *(float4*)(cp + 0) = make_float4(vals[0], vals[1], vals[2], vals[3]);
        *(float4*)(cp + 4) = make_float4(vals[4], vals[5], vals[6], vals[7]);
    }
}

// ---------------- flash attention, block-causal (64-token blocks) --------
// qkv layout: [b, s, 3*D], q at h*64, k at 512+h*64, v at 1024+h*64
// out layout: [b, s, D] with feature = h*64 + d
__global__ __launch_bounds__(256)
void flash_kernel(const float* __restrict__ qkv, float* __restrict__ out)
{
    __shared__ float Qs[64][64];   // [d][m]
    __shared__ float KP[64][64];   // [d][n] for K; reused as P[m][k2]
    __shared__ float Vs[64][64];   // [n][d]

    int qb = blockIdx.x, h = blockIdx.y, b = blockIdx.z;
    int t = threadIdx.x;
    int m = t >> 2;
    int dbase = 16 * (t & 3);

    // load Q tile transposed
    {
        const float* qrow = qkv + ((size_t)(b * SEQ + qb * 64 + m)) * (3 * DMODEL) + h * DHEAD;
#pragma unroll
        for (int u = 0; u < 4; u++) {
            int d0 = dbase + 4 * u;
            float4 v = *(const float4*)(qrow + d0);
            Qs[d0 + 0][m] = v.x; Qs[d0 + 1][m] = v.y;
            Qs[d0 + 2][m] = v.z; Qs[d0 + 3][m] = v.w;
        }
    }

    int r = (t >> 4) << 2;     // row group (4 rows)
    int c = (t & 15) << 2;     // col group (4 cols)
    float acc[4][4];
#pragma unroll
    for (int i = 0; i < 4; i++)
#pragma unroll
        for (int j = 0; j < 4; j++) acc[i][j] = 0.0f;
    float mrow[4] = {-INFINITY, -INFINITY, -INFINITY, -INFINITY};
    float lrow[4] = {0.0f, 0.0f, 0.0f, 0.0f};

    for (int kb = 0; kb <= qb; kb++) {
        __syncthreads();   // protect KP/Vs from previous iteration readers
        {
            const float* krow = qkv + ((size_t)(b * SEQ + kb * 64 + m)) * (3 * DMODEL)
                                + DMODEL + h * DHEAD;
            const float* vrow = krow + DMODEL;
#pragma unroll
            for (int u = 0; u < 4; u++) {
                int d0 = dbase + 4 * u;
                float4 kv = *(const float4*)(krow + d0);
                KP[d0 + 0][m] = kv.x; KP[d0 + 1][m] = kv.y;
                KP[d0 + 2][m] = kv.z; KP[d0 + 3][m] = kv.w;
                *(float4*)&Vs[m][d0] = *(const float4*)(vrow + d0);
            }
        }
        __syncthreads();

        // S = Q @ K^T (64x64x64), thread computes 4x4
        float s[4][4];
#pragma unroll
        for (int i = 0; i < 4; i++)
#pragma unroll
            for (int j = 0; j < 4; j++) s[i][j] = 0.0f;
#pragma unroll
        for (int kk = 0; kk < 64; kk++) {
            float4 q4 = *(float4*)&Qs[kk][r];
            float4 k4 = *(float4*)&KP[kk][c];
            float qa[4] = {q4.x, q4.y, q4.z, q4.w};
            float kv[4] = {k4.x, k4.y, k4.z, k4.w};
#pragma unroll
            for (int i = 0; i < 4; i++)
#pragma unroll
                for (int j = 0; j < 4; j++)
                    s[i][j] += qa[i] * kv[j];
        }

        float pr_[4][4];
#pragma unroll
        for (int i = 0; i < 4; i++) {
#pragma unroll
            for (int j = 0; j < 4; j++) s[i][j] *= 0.125f;   // 1/sqrt(64)
            float mx = fmaxf(fmaxf(s[i][0], s[i][1]), fmaxf(s[i][2], s[i][3]));
#pragma unroll
            for (int off = 8; off; off >>= 1)
                mx = fmaxf(mx, __shfl_xor_sync(0xffffffffu, mx, off));
            float mnew = fmaxf(mrow[i], mx);
            float al = expf(mrow[i] - mnew);
            float rs = 0.0f;
#pragma unroll
            for (int j = 0; j < 4; j++) {
                pr_[i][j] = expf(s[i][j] - mnew);
                rs += pr_[i][j];
            }
#pragma unroll
            for (int off = 8; off; off >>= 1)
                rs += __shfl_xor_sync(0xffffffffu, rs, off);
            lrow[i] = lrow[i] * al + rs;
            mrow[i] = mnew;
#pragma unroll
            for (int j = 0; j < 4; j++) acc[i][j] *= al;
        }

        __syncthreads();   // all done reading KP as K
#pragma unroll
        for (int i = 0; i < 4; i++)
            *(float4*)&KP[r + i][c] = make_float4(pr_[i][0], pr_[i][1], pr_[i][2], pr_[i][3]);
        __syncthreads();

        // O += P @ V  (64x64x64)
#pragma unroll
        for (int kk = 0; kk < 64; kk++) {
            float p0 = KP[r + 0][kk], p1 = KP[r + 1][kk];
            float p2 = KP[r + 2][kk], p3 = KP[r + 3][kk];
            float4 v4 = *(float4*)&Vs[kk][c];
            acc[0][0] += p0 * v4.x; acc[0][1] += p0 * v4.y; acc[0][2] += p0 * v4.z; acc[0][3] += p0 * v4.w;
            acc[1][0] += p1 * v4.x; acc[1][1] += p1 * v4.y; acc[1][2] += p1 * v4.z; acc[1][3] += p1 * v4.w;
            acc[2][0] += p2 * v4.x; acc[2][1] += p2 * v4.y; acc[2][2] += p2 * v4.z; acc[2][3] += p2 * v4.w;
            acc[3][0] += p3 * v4.x; acc[3][1] += p3 * v4.y; acc[3][2] += p3 * v4.z; acc[3][3] += p3 * v4.w;
        }
    }

#pragma unroll
    for (int i = 0; i < 4; i++) {
        float inv = 1.0f / lrow[i];
        float4 o4 = make_float4(acc[i][0] * inv, acc[i][1] * inv,
                                acc[i][2] * inv, acc[i][3] * inv);
        *(float4*)(out + ((size_t)(b * SEQ + qb * 64 + r + i)) * DMODEL + h * DHEAD + c) = o4;
    }
}

// ---------------- residual add + LayerNorm (in place on x) ----------------
__global__ __launch_bounds__(256)
void add_ln_kernel(float* __restrict__ x, const float* __restrict__ o,
                   const float* __restrict__ sc, const float* __restrict__ bi)
{
    int tok = blockIdx.x;
    int t = threadIdx.x;
    size_t base = (size_t)tok * DMODEL;
    float v0 = x[base + t]       + o[base + t];
    float v1 = x[base + t + 256] + o[base + t + 256];

    __shared__ float red[8];
    int warp = t >> 5, lane = t & 31;

    float s = v0 + v1;
#pragma unroll
    for (int off = 16; off; off >>= 1) s += __shfl_xor_sync(0xffffffffu, s, off);
    if (lane == 0) red[warp] = s;
    __syncthreads();
    float tot = 0.0f;
#pragma unroll
    for (int w = 0; w < 8; w++) tot += red[w];
    float mean = tot * (1.0f / 512.0f);

    float d0 = v0 - mean, d1 = v1 - mean;
    float q = d0 * d0 + d1 * d1;
#pragma unroll
    for (int off = 16; off; off >>= 1) q += __shfl_xor_sync(0xffffffffu, q, off);
    __syncthreads();
    if (lane == 0) red[warp] = q;
    __syncthreads();
    float tq = 0.0f;
#pragma unroll
    for (int w = 0; w < 8; w++) tq += red[w];
    float inv = rsqrtf(tq * (1.0f / 512.0f) + 1e-5f);

    x[base + t]       = d0 * inv * sc[t]       + bi[t];
    x[base + t + 256] = d1 * inv * sc[t + 256] + bi[t + 256];
}

// ---------------- gather init slots: f[:, :, 0] -> [2560, 512] -----------
__global__ void gather_kernel(const float* __restrict__ x, float* __restrict__ y)
{
    int idx = blockIdx.x * blockDim.x + threadIdx.x;   // NSEL*DMODEL
    int d = idx & 511;
    int row = idx >> 9;
    int b = row / (PAIRS * 64);
    int r2 = row - b * (PAIRS * 64);
    int pair = r2 >> 6;
    int patch = r2 & 63;
    int s = pair * 128 + patch;     // io = 0
    y[idx] = x[((size_t)(b * SEQ + s)) * DMODEL + d];
}

// ---------------- depatchify to output --------------------------------
__global__ void depatch_kernel(const float* __restrict__ y, float* __restrict__ out)
{
    int idx = blockIdx.x * blockDim.x + threadIdx.x;   // BSZ*PAIRS*CCH*HW*HW
    int w = idx & 127;
    int h = (idx >> 7) & 127;
    int ch = (idx >> 14) & 1;
    int rest = idx >> 15;             // b*PAIRS + pair
    int pr = h >> 4, i = h & 15;
    int pc = w >> 4, j = w & 15;
    int row = rest * 64 + pr * 8 + pc;
    int fi = ch * 256 + i * 16 + j;
    out[idx] = y[(size_t)row * DMODEL + fi];
}

// ---------------- host launcher ----------------------------------------
extern "C" void kernel_launch(void* const* d_in, const int* in_sizes, int n_in,
                              void* d_out, int out_size)
{
    const float* initp     = (const float*)d_in[0];
    const float* endp      = (const float*)d_in[1];
    // d_in[2] = c_mask (bool) — unused by the reference forward
    const float* pre_W     = (const float*)d_in[3];
    const float* pre_b     = (const float*)d_in[4];
    const float* post_W    = (const float*)d_in[5];
    const float* post_b    = (const float*)d_in[6];
    const float* patch_pos = (const float*)d_in[7];
    const float* func_pos  = (const float*)d_in[8];
    const float* Wqkv      = (const float*)d_in[9];
    const float* bqkv      = (const float*)d_in[10];
    const float* Wo        = (const float*)d_in[11];
    const float* bo        = (const float*)d_in[12];
    const float* ln1s      = (const float*)d_in[13];
    const float* ln1b      = (const float*)d_in[14];
    const float* ln2s      = (const float*)d_in[15];
    const float* ln2b      = (const float*)d_in[16];
    const float* W1        = (const float*)d_in[17];
    const float* b1        = (const float*)d_in[18];
    const float* W2        = (const float*)d_in[19];
    const float* b2        = (const float*)d_in[20];
    float* out = (float*)d_out;

    float *px, *pqkv, *pa, *ph, *po;
    cudaGetSymbolAddress((void**)&px,   g_x);
    cudaGetSymbolAddress((void**)&pqkv, g_qkv);
    cudaGetSymbolAddress((void**)&pa,   g_a);
    cudaGetSymbolAddress((void**)&ph,   g_h);
    cudaGetSymbolAddress((void**)&po,   g_o);

    const int TOKELEM = NTOK * DMODEL;        // 2,621,440

    // embed: patchify -> pre projection -> positional encodings
    patchify_kernel<<<TOKELEM / 256, 256>>>(initp, endp, pqkv);
    gemm_kernel<<<dim3(DMODEL / 128, NTOK / 128), 256>>>(pqkv, pre_W, pre_b, px, 512, DMODEL, 0);
    add_pos_kernel<<<TOKELEM / 256, 256>>>(px, patch_pos, func_pos);

    for (int l = 0; l < NLAYER; l++) {
        const float* Wqkv_l = Wqkv + (size_t)l * 3 * DMODEL * DMODEL;
        const float* bqkv_l = bqkv + (size_t)l * 3 * DMODEL;
        const float* Wo_l   = Wo   + (size_t)l * DMODEL * DMODEL;
        const float* bo_l   = bo   + (size_t)l * DMODEL;
        const float* W1_l   = W1   + (size_t)l * DFFN * DMODEL;
        const float* b1_l   = b1   + (size_t)l * DFFN;
        const float* W2_l   = W2   + (size_t)l * DMODEL * DFFN;
        const float* b2_l   = b2   + (size_t)l * DMODEL;

        gemm_kernel<<<dim3(3 * DMODEL / 128, NTOK / 128), 256>>>(px, Wqkv_l, bqkv_l, pqkv, 512, 3 * DMODEL, 0);
        flash_kernel<<<dim3(SEQ / 64, NHEAD, BSZ), 256>>>(pqkv, pa);
        gemm_kernel<<<dim3(DMODEL / 128, NTOK / 128), 256>>>(pa, Wo_l, bo_l, po, 512, DMODEL, 0);
        add_ln_kernel<<<NTOK, 256>>>(px, po, ln1s + (size_t)l * DMODEL, ln1b + (size_t)l * DMODEL);
        gemm_kernel<<<dim3(DFFN / 128, NTOK / 128), 256>>>(px, W1_l, b1_l, ph, 512, DFFN, 1);
        gemm_kernel<<<dim3(DMODEL / 128, NTOK / 128), 256>>>(ph, W2_l, b2_l, po, 2048, DMODEL, 0);
        add_ln_kernel<<<NTOK, 256>>>(px, po, ln2s + (size_t)l * DMODEL, ln2b + (size_t)l * DMODEL);
    }

    // output head: select init slots, project, depatchify
    gather_kernel<<<(NSEL * DMODEL) / 256, 256>>>(px, pa);
    gemm_kernel<<<dim3(DMODEL / 128, NSEL / 128), 256>>>(pa, post_W, post_b, po, 512, DMODEL, 0);
    depatch_kernel<<<(BSZ * PAIRS * CCH * HWDIM * HWDIM) / 256, 256>>>(po, out);
}

// round 11
// speedup vs baseline: 1.7530x; 1.7530x over previous
#include <cuda_runtime.h>
#include <cuda_bf16.h>
#include <math.h>
#include <stdint.h>

// ---------------- problem constants ----------------
#define BSZ     8
#define PAIRS   5
#define CCH     2
#define PGRID   8          // P
#define RRES    16         // R
#define HWDIM   128        // P*R
#define SEQ     640        // PAIRS*2*P*P
#define DMODEL  512
#define NHEAD   8
#define DHEAD   64
#define DFFN    2048
#define NLAYER  6
#define NTOK    (BSZ*SEQ)  // 5120
#define NSEL    (BSZ*PAIRS*PGRID*PGRID)  // 2560

// ---------------- scratch (device globals; no allocation allowed) ----------
__device__ float g_x  [NTOK*DMODEL];      // token stream f
__device__ float g_qkv[NTOK*3*DMODEL];    // qkv (also reused as patchified X)
__device__ float g_a  [NTOK*DMODEL];      // attention output / gathered rows
__device__ float g_h  [NTOK*DFFN];        // FF hidden
__device__ float g_o  [NTOK*DMODEL];      // generic gemm output

// ================= helpers =================
__device__ __forceinline__ uint32_t smem_u32(const void* p) {
    uint32_t a;
    asm("{ .reg .u64 t; cvta.to.shared.u64 t, %1; cvt.u32.u64 %0, t; }" : "=r"(a) : "l"(p));
    return a;
}

// split a float4 into hi/lo bf16 pairs (packed as 2x uint32 each)
__device__ __forceinline__ void split4(const float4 f, uint32_t& h0, uint32_t& h1,
                                       uint32_t& l0, uint32_t& l1)
{
    __nv_bfloat162 hp0 = __floats2bfloat162_rn(f.x, f.y);
    __nv_bfloat162 hp1 = __floats2bfloat162_rn(f.z, f.w);
    float r0 = f.x - __bfloat162float(hp0.x);
    float r1 = f.y - __bfloat162float(hp0.y);
    float r2 = f.z - __bfloat162float(hp1.x);
    float r3 = f.w - __bfloat162float(hp1.y);
    __nv_bfloat162 lp0 = __floats2bfloat162_rn(r0, r1);
    __nv_bfloat162 lp1 = __floats2bfloat162_rn(r2, r3);
    h0 = *(uint32_t*)&hp0; h1 = *(uint32_t*)&hp1;
    l0 = *(uint32_t*)&lp0; l1 = *(uint32_t*)&lp1;
}

#define LDM_X4(r, addr) \
    asm volatile("ldmatrix.sync.aligned.m8n8.x4.shared.b16 {%0,%1,%2,%3}, [%4];" \
        : "=r"((r)[0]), "=r"((r)[1]), "=r"((r)[2]), "=r"((r)[3]) : "r"(addr))

#define MMA16816(c, a, b) \
    asm volatile("mma.sync.aligned.m16n8k16.row.col.f32.bf16.bf16.f32 " \
        "{%0,%1,%2,%3}, {%4,%5,%6,%7}, {%8,%9}, {%0,%1,%2,%3};" \
        : "+f"((c)[0]), "+f"((c)[1]), "+f"((c)[2]), "+f"((c)[3]) \
        : "r"((a)[0]), "r"((a)[1]), "r"((a)[2]), "r"((a)[3]), "r"((b)[0]), "r"((b)[1]))

// ---------------- patchify: (init,end) -> X[5120, 512] ----------------
__global__ void patchify_kernel(const float* __restrict__ initp,
                                const float* __restrict__ endp,
                                float* __restrict__ X)
{
    int idx = blockIdx.x * blockDim.x + threadIdx.x;   // NTOK*DMODEL threads
    int fi = idx & 511;
    int n  = idx >> 9;
    int b  = n / SEQ;
    int s  = n - b * SEQ;
    int fn = s >> 6;            // pair*2 + io
    int patch = s & 63;
    int pair = fn >> 1, io = fn & 1;
    int pr = patch >> 3, pc = patch & 7;
    int ch = fi >> 8;
    int rem = fi & 255;
    int i = rem >> 4, j = rem & 15;
    const float* src = io ? endp : initp;
    int h = pr * RRES + i, w = pc * RRES + j;
    X[idx] = src[((((size_t)b * PAIRS + pair) * CCH + ch) * HWDIM + h) * HWDIM + w];
}

// ---------------- positional add ----------------
__global__ void add_pos_kernel(float* __restrict__ x,
                               const float* __restrict__ patch_pos,
                               const float* __restrict__ func_pos)
{
    int idx = blockIdx.x * blockDim.x + threadIdx.x;
    int d = idx & 511;
    int n = idx >> 9;
    int s = n % SEQ;
    int fn = s >> 6;
    int patch = s & 63;
    x[idx] += patch_pos[patch * DMODEL + d] + func_pos[fn * DMODEL + d];
}

// =============== warp-MMA GEMM: C[N,J] = A[N,K] @ W[J,K]^T + bias ===========
// bf16 hi/lo split, 3 passes: AhWh + AhWl + AlWh -> ~2^-16 relative accuracy.
// Block tile 128x128, 8 warps (2x4), warp tile 64x32, K-chunk 32.
// smem bf16 tiles padded to stride 40 (80B rows -> conflict-free ldmatrix).
#define GSA 40   // padded smem stride (bf16 elements)

__global__ __launch_bounds__(256, 1)
void gemm_mma(const float* __restrict__ A, const float* __restrict__ W,
              const float* __restrict__ bias, float* __restrict__ C,
              int K, int J, int act)
{
    __shared__ __nv_bfloat16 sAh[128 * GSA], sAl[128 * GSA];
    __shared__ __nv_bfloat16 sWh[128 * GSA], sWl[128 * GSA];

    const int t = threadIdx.x;
    const int lane = t & 31, wid = t >> 5;
    const int wr = wid >> 2, wc = wid & 3;        // warp grid 2 x 4
    const int n0 = blockIdx.y * 128, j0 = blockIdx.x * 128;

    float acc[4][4][4];
#pragma unroll
    for (int mi = 0; mi < 4; mi++)
#pragma unroll
        for (int ni = 0; ni < 4; ni++)
#pragma unroll
            for (int e = 0; e < 4; e++) acc[mi][ni][e] = 0.0f;

    const int lrow = t >> 1;              // 0..127
    const int lkh  = (t & 1) * 16;        // 0 or 16
    const float* Ap = A + (size_t)(n0 + lrow) * K + lkh;
    const float* Wp = W + (size_t)(j0 + lrow) * K + lkh;

    const uint32_t uAh = smem_u32(sAh), uAl = smem_u32(sAl);
    const uint32_t uWh = smem_u32(sWh), uWl = smem_u32(sWl);

    // ldmatrix lane address offsets (bytes)
    // A (m16k16, .x4): row = wr*64 + mi*16 + (lane&15), col = ks + (lane>>4)*8
    const int aoff = ((wr * 64 + (lane & 15)) * GSA + ((lane >> 4) << 3)) * 2;
    // B (two n8k16 tiles per .x4): row = wc*32 + pi*16 + (lane&7) + ((lane>>4)<<3),
    //                              col = ks + ((lane>>3)&1)*8
    const int boff = ((wc * 32 + (lane & 7) + ((lane >> 4) << 3)) * GSA
                      + (((lane >> 3) & 1) << 3)) * 2;
    const int sto = (lrow * GSA + lkh) * 2;   // byte offset for smem stores

    for (int kc = 0; kc < K; kc += 32) {
        // prefetch 16 k-values of A and W per thread
        float4 ra[4], rw[4];
#pragma unroll
        for (int u = 0; u < 4; u++) {
            ra[u] = *(const float4*)(Ap + kc + u * 4);
            rw[u] = *(const float4*)(Wp + kc + u * 4);
        }
        __syncthreads();   // previous chunk's ldmatrix reads done
        {
            uint32_t h[8], l[8];
#pragma unroll
            for (int u = 0; u < 4; u++)
                split4(ra[u], h[2*u], h[2*u+1], l[2*u], l[2*u+1]);
            *(uint4*)((char*)sAh + sto)      = make_uint4(h[0], h[1], h[2], h[3]);
            *(uint4*)((char*)sAh + sto + 16) = make_uint4(h[4], h[5], h[6], h[7]);
            *(uint4*)((char*)sAl + sto)      = make_uint4(l[0], l[1], l[2], l[3]);
            *(uint4*)((char*)sAl + sto + 16) = make_uint4(l[4], l[5], l[6], l[7]);
#pragma unroll
            for (int u = 0; u < 4; u++)
                split4(rw[u], h[2*u], h[2*u+1], l[2*u], l[2*u+1]);
            *(uint4*)((char*)sWh + sto)      = make_uint4(h[0], h[1], h[2], h[3]);
            *(uint4*)((char*)sWh + sto + 16) = make_uint4(h[4], h[5], h[6], h[7]);
            *(uint4*)((char*)sWl + sto)      = make_uint4(l[0], l[1], l[2], l[3]);
            *(uint4*)((char*)sWl + sto + 16) = make_uint4(l[4], l[5], l[6], l[7]);
        }
        __syncthreads();

#pragma unroll
        for (int ks = 0; ks < 32; ks += 16) {
            uint32_t Ah[4][4], Al[4][4], Bh[4][2], Bl[4][2];
#pragma unroll
            for (int mi = 0; mi < 4; mi++) {
                int d = (mi * 16 * GSA + ks) * 2;
                LDM_X4(Ah[mi], uAh + aoff + d);
                LDM_X4(Al[mi], uAl + aoff + d);
            }
#pragma unroll
            for (int pi = 0; pi < 2; pi++) {
                int d = (pi * 16 * GSA + ks) * 2;
                uint32_t r[4];
                LDM_X4(r, uWh + boff + d);
                Bh[2*pi][0] = r[0]; Bh[2*pi][1] = r[1];
                Bh[2*pi+1][0] = r[2]; Bh[2*pi+1][1] = r[3];
                LDM_X4(r, uWl + boff + d);
                Bl[2*pi][0] = r[0]; Bl[2*pi][1] = r[1];
                Bl[2*pi+1][0] = r[2]; Bl[2*pi+1][1] = r[3];
            }
#pragma unroll
            for (int mi = 0; mi < 4; mi++)
#pragma unroll
                for (int ni = 0; ni < 4; ni++) {
                    MMA16816(acc[mi][ni], Ah[mi], Bh[ni]);
                    MMA16816(acc[mi][ni], Ah[mi], Bl[ni]);
                    MMA16816(acc[mi][ni], Al[mi], Bh[ni]);
                }
        }
    }

    // epilogue: bias (+ optional exact GELU), fp32 store
#pragma unroll
    for (int mi = 0; mi < 4; mi++) {
        int r0 = n0 + wr * 64 + mi * 16 + (lane >> 2);
#pragma unroll
        for (int ni = 0; ni < 4; ni++) {
            int col = j0 + wc * 32 + ni * 8 + (lane & 3) * 2;
            float b0v = bias[col], b1v = bias[col + 1];
            float v0 = acc[mi][ni][0] + b0v;
            float v1 = acc[mi][ni][1] + b1v;
            float v2 = acc[mi][ni][2] + b0v;
            float v3 = acc[mi][ni][3] + b1v;
            if (act == 1) {
                v0 = 0.5f * v0 * (1.0f + erff(v0 * 0.70710678118654752f));
                v1 = 0.5f * v1 * (1.0f + erff(v1 * 0.70710678118654752f));
                v2 = 0.5f * v2 * (1.0f + erff(v2 * 0.70710678118654752f));
                v3 = 0.5f * v3 * (1.0f + erff(v3 * 0.70710678118654752f));
            }
            *(float2*)(C + (size_t)r0 * J + col)       = make_float2(v0, v1);
            *(float2*)(C + (size_t)(r0 + 8) * J + col) = make_float2(v2, v3);
        }
    }
}

// ---------------- flash attention, block-causal (64-token blocks) --------
// qkv layout: [b, s, 3*D], q at h*64, k at 512+h*64, v at 1024+h*64
__global__ __launch_bounds__(256)
void flash_kernel(const float* __restrict__ qkv, float* __restrict__ out)
{
    __shared__ float Qs[64][64];   // [d][m]
    __shared__ float KP[64][64];   // [d][n] for K; reused as P[m][k2]
    __shared__ float Vs[64][64];   // [n][d]

    int qb = blockIdx.x, h = blockIdx.y, b = blockIdx.z;
    int t = threadIdx.x;
    int m = t >> 2;
    int dbase = 16 * (t & 3);

    {
        const float* qrow = qkv + ((size_t)(b * SEQ + qb * 64 + m)) * (3 * DMODEL) + h * DHEAD;
#pragma unroll
        for (int u = 0; u < 4; u++) {
            int d0 = dbase + 4 * u;
            float4 v = *(const float4*)(qrow + d0);
            Qs[d0 + 0][m] = v.x; Qs[d0 + 1][m] = v.y;
            Qs[d0 + 2][m] = v.z; Qs[d0 + 3][m] = v.w;
        }
    }

    int r = (t >> 4) << 2;
    int c = (t & 15) << 2;
    float acc[4][4];
#pragma unroll
    for (int i = 0; i < 4; i++)
#pragma unroll
        for (int j = 0; j < 4; j++) acc[i][j] = 0.0f;
    float mrow[4] = {-INFINITY, -INFINITY, -INFINITY, -INFINITY};
    float lrow[4] = {0.0f, 0.0f, 0.0f, 0.0f};

    for (int kb = 0; kb <= qb; kb++) {
        __syncthreads();
        {
            const float* krow = qkv + ((size_t)(b * SEQ + kb * 64 + m)) * (3 * DMODEL)
                                + DMODEL + h * DHEAD;
            const float* vrow = krow + DMODEL;
#pragma unroll
            for (int u = 0; u < 4; u++) {
                int d0 = dbase + 4 * u;
                float4 kv = *(const float4*)(krow + d0);
                KP[d0 + 0][m] = kv.x; KP[d0 + 1][m] = kv.y;
                KP[d0 + 2][m] = kv.z; KP[d0 + 3][m] = kv.w;
                *(float4*)&Vs[m][d0] = *(const float4*)(vrow + d0);
            }
        }
        __syncthreads();

        float s[4][4];
#pragma unroll
        for (int i = 0; i < 4; i++)
#pragma unroll
            for (int j = 0; j < 4; j++) s[i][j] = 0.0f;
#pragma unroll
        for (int kk = 0; kk < 64; kk++) {
            float4 q4 = *(float4*)&Qs[kk][r];
            float4 k4 = *(float4*)&KP[kk][c];
            float qa[4] = {q4.x, q4.y, q4.z, q4.w};
            float kv[4] = {k4.x, k4.y, k4.z, k4.w};
#pragma unroll
            for (int i = 0; i < 4; i++)
#pragma unroll
                for (int j = 0; j < 4; j++)
                    s[i][j] += qa[i] * kv[j];
        }

        float pr_[4][4];
#pragma unroll
        for (int i = 0; i < 4; i++) {
#pragma unroll
            for (int j = 0; j < 4; j++) s[i][j] *= 0.125f;
            float mx = fmaxf(fmaxf(s[i][0], s[i][1]), fmaxf(s[i][2], s[i][3]));
#pragma unroll
            for (int off = 8; off; off >>= 1)
                mx = fmaxf(mx, __shfl_xor_sync(0xffffffffu, mx, off));
            float mnew = fmaxf(mrow[i], mx);
            float al = expf(mrow[i] - mnew);
            float rs = 0.0f;
#pragma unroll
            for (int j = 0; j < 4; j++) {
                pr_[i][j] = expf(s[i][j] - mnew);
                rs += pr_[i][j];
            }
#pragma unroll
            for (int off = 8; off; off >>= 1)
                rs += __shfl_xor_sync(0xffffffffu, rs, off);
            lrow[i] = lrow[i] * al + rs;
            mrow[i] = mnew;
#pragma unroll
            for (int j = 0; j < 4; j++) acc[i][j] *= al;
        }

        __syncthreads();
#pragma unroll
        for (int i = 0; i < 4; i++)
            *(float4*)&KP[r + i][c] = make_float4(pr_[i][0], pr_[i][1], pr_[i][2], pr_[i][3]);
        __syncthreads();

#pragma unroll
        for (int kk = 0; kk < 64; kk++) {
            float p0 = KP[r + 0][kk], p1 = KP[r + 1][kk];
            float p2 = KP[r + 2][kk], p3 = KP[r + 3][kk];
            float4 v4 = *(float4*)&Vs[kk][c];
            acc[0][0] += p0 * v4.x; acc[0][1] += p0 * v4.y; acc[0][2] += p0 * v4.z; acc[0][3] += p0 * v4.w;
            acc[1][0] += p1 * v4.x; acc[1][1] += p1 * v4.y; acc[1][2] += p1 * v4.z; acc[1][3] += p1 * v4.w;
            acc[2][0] += p2 * v4.x; acc[2][1] += p2 * v4.y; acc[2][2] += p2 * v4.z; acc[2][3] += p2 * v4.w;
            acc[3][0] += p3 * v4.x; acc[3][1] += p3 * v4.y; acc[3][2] += p3 * v4.z; acc[3][3] += p3 * v4.w;
        }
    }

#pragma unroll
    for (int i = 0; i < 4; i++) {
        float inv = 1.0f / lrow[i];
        float4 o4 = make_float4(acc[i][0] * inv, acc[i][1] * inv,
                                acc[i][2] * inv, acc[i][3] * inv);
        *(float4*)(out + ((size_t)(b * SEQ + qb * 64 + r + i)) * DMODEL + h * DHEAD + c) = o4;
    }
}

// ---------------- residual add + LayerNorm (in place on x) ----------------
__global__ __launch_bounds__(256)
void add_ln_kernel(float* __restrict__ x, const float* __restrict__ o,
                   const float* __restrict__ sc, const float* __restrict__ bi)
{
    int tok = blockIdx.x;
    int t = threadIdx.x;
    size_t base = (size_t)tok * DMODEL;
    float v0 = x[base + t]       + o[base + t];
    float v1 = x[base + t + 256] + o[base + t + 256];

    __shared__ float red[8];
    int warp = t >> 5, lane = t & 31;

    float s = v0 + v1;
#pragma unroll
    for (int off = 16; off; off >>= 1) s += __shfl_xor_sync(0xffffffffu, s, off);
    if (lane == 0) red[warp] = s;
    __syncthreads();
    float tot = 0.0f;
#pragma unroll
    for (int w = 0; w < 8; w++) tot += red[w];
    float mean = tot * (1.0f / 512.0f);

    float d0 = v0 - mean, d1 = v1 - mean;
    float q = d0 * d0 + d1 * d1;
#pragma unroll
    for (int off = 16; off; off >>= 1) q += __shfl_xor_sync(0xffffffffu, q, off);
    __syncthreads();
    if (lane == 0) red[warp] = q;
    __syncthreads();
    float tq = 0.0f;
#pragma unroll
    for (int w = 0; w < 8; w++) tq += red[w];
    float inv = rsqrtf(tq * (1.0f / 512.0f) + 1e-5f);

    x[base + t]       = d0 * inv * sc[t]       + bi[t];
    x[base + t + 256] = d1 * inv * sc[t + 256] + bi[t + 256];
}

// ---------------- gather init slots: f[:, :, 0] -> [2560, 512] -----------
__global__ void gather_kernel(const float* __restrict__ x, float* __restrict__ y)
{
    int idx = blockIdx.x * blockDim.x + threadIdx.x;   // NSEL*DMODEL
    int d = idx & 511;
    int row = idx >> 9;
    int b = row / (PAIRS * 64);
    int r2 = row - b * (PAIRS * 64);
    int pair = r2 >> 6;
    int patch = r2 & 63;
    int s = pair * 128 + patch;
    y[idx] = x[((size_t)(b * SEQ + s)) * DMODEL + d];
}

// ---------------- depatchify to output --------------------------------
__global__ void depatch_kernel(const float* __restrict__ y, float* __restrict__ out)
{
    int idx = blockIdx.x * blockDim.x + threadIdx.x;   // BSZ*PAIRS*CCH*HW*HW
    int w = idx & 127;
    int h = (idx >> 7) & 127;
    int ch = (idx >> 14) & 1;
    int rest = idx >> 15;
    int pr = h >> 4, i = h & 15;
    int pc = w >> 4, j = w & 15;
    int row = rest * 64 + pr * 8 + pc;
    int fi = ch * 256 + i * 16 + j;
    out[idx] = y[(size_t)row * DMODEL + fi];
}

// ---------------- host launcher ----------------------------------------
extern "C" void kernel_launch(void* const* d_in, const int* in_sizes, int n_in,
                              void* d_out, int out_size)
{
    const float* initp     = (const float*)d_in[0];
    const float* endp      = (const float*)d_in[1];
    // d_in[2] = c_mask (bool) — unused by the reference forward
    const float* pre_W     = (const float*)d_in[3];
    const float* pre_b     = (const float*)d_in[4];
    const float* post_W    = (const float*)d_in[5];
    const float* post_b    = (const float*)d_in[6];
    const float* patch_pos = (const float*)d_in[7];
    const float* func_pos  = (const float*)d_in[8];
    const float* Wqkv      = (const float*)d_in[9];
    const float* bqkv      = (const float*)d_in[10];
    const float* Wo        = (const float*)d_in[11];
    const float* bo        = (const float*)d_in[12];
    const float* ln1s      = (const float*)d_in[13];
    const float* ln1b      = (const float*)d_in[14];
    const float* ln2s      = (const float*)d_in[15];
    const float* ln2b      = (const float*)d_in[16];
    const float* W1        = (const float*)d_in[17];
    const float* b1        = (const float*)d_in[18];
    const float* W2        = (const float*)d_in[19];
    const float* b2        = (const float*)d_in[20];
    float* out = (float*)d_out;

    float *px, *pqkv, *pa, *ph, *po;
    cudaGetSymbolAddress((void**)&px,   g_x);
    cudaGetSymbolAddress((void**)&pqkv, g_qkv);
    cudaGetSymbolAddress((void**)&pa,   g_a);
    cudaGetSymbolAddress((void**)&ph,   g_h);
    cudaGetSymbolAddress((void**)&po,   g_o);

    const int TOKELEM = NTOK * DMODEL;        // 2,621,440

    // embed: patchify -> pre projection -> positional encodings
    patchify_kernel<<<TOKELEM / 256, 256>>>(initp, endp, pqkv);
    gemm_mma<<<dim3(DMODEL / 128, NTOK / 128), 256>>>(pqkv, pre_W, pre_b, px, 512, DMODEL, 0);
    add_pos_kernel<<<TOKELEM / 256, 256>>>(px, patch_pos, func_pos);

    for (int l = 0; l < NLAYER; l++) {
        const float* Wqkv_l = Wqkv + (size_t)l * 3 * DMODEL * DMODEL;
        const float* bqkv_l = bqkv + (size_t)l * 3 * DMODEL;
        const float* Wo_l   = Wo   + (size_t)l * DMODEL * DMODEL;
        const float* bo_l   = bo   + (size_t)l * DMODEL;
        const float* W1_l   = W1   + (size_t)l * DFFN * DMODEL;
        const float* b1_l   = b1   + (size_t)l * DFFN;
        const float* W2_l   = W2   + (size_t)l * DMODEL * DFFN;
        const float* b2_l   = b2   + (size_t)l * DMODEL;

        gemm_mma<<<dim3(3 * DMODEL / 128, NTOK / 128), 256>>>(px, Wqkv_l, bqkv_l, pqkv, 512, 3 * DMODEL, 0);
        flash_kernel<<<dim3(SEQ / 64, NHEAD, BSZ), 256>>>(pqkv, pa);
        gemm_mma<<<dim3(DMODEL / 128, NTOK / 128), 256>>>(pa, Wo_l, bo_l, po, 512, DMODEL, 0);
        add_ln_kernel<<<NTOK, 256>>>(px, po, ln1s + (size_t)l * DMODEL, ln1b + (size_t)l * DMODEL);
        gemm_mma<<<dim3(DFFN / 128, NTOK / 128), 256>>>(px, W1_l, b1_l, ph, 512, DFFN, 1);
        gemm_mma<<<dim3(DMODEL / 128, NTOK / 128), 256>>>(ph, W2_l, b2_l, po, 2048, DMODEL, 0);
        add_ln_kernel<<<NTOK, 256>>>(px, po, ln2s + (size_t)l * DMODEL, ln2b + (size_t)l * DMODEL);
    }

    // output head: select init slots, project, depatchify
    gather_kernel<<<(NSEL * DMODEL) / 256, 256>>>(px, pa);
    gemm_mma<<<dim3(DMODEL / 128, NSEL / 128), 256>>>(pa, post_W, post_b, po, 512, DMODEL, 0);
    depatch_kernel<<<(BSZ * PAIRS * CCH * HWDIM * HWDIM) / 256, 256>>>(po, out);
}

// round 12
// speedup vs baseline: 1.8171x; 1.0366x over previous
#include <cuda_runtime.h>
#include <cuda_bf16.h>
#include <math.h>
#include <stdint.h>

// ---------------- problem constants ----------------
#define BSZ     8
#define PAIRS   5
#define CCH     2
#define PGRID   8          // P
#define RRES    16         // R
#define HWDIM   128        // P*R
#define SEQ     640        // PAIRS*2*P*P
#define DMODEL  512
#define NHEAD   8
#define DHEAD   64
#define DFFN    2048
#define NLAYER  6
#define NTOK    (BSZ*SEQ)  // 5120
#define NSEL    (BSZ*PAIRS*PGRID*PGRID)  // 2560

// ---------------- weight hi/lo buffer offsets ----------------
#define W_PRE   0
#define W_QKV   (W_PRE  + 512*512)            // 262144
#define W_WO    (W_QKV  + 6*1536*512)         // 4980736
#define W_W1    (W_WO   + 6*512*512)          // 6553600
#define W_W2    (W_W1   + 6*2048*512)         // 12845056
#define W_POST  (W_W2   + 6*512*2048)         // 19136512
#define W_TOT   (W_POST + 512*512)            // 19398656

// ---------------- scratch (device globals; no allocation allowed) ----------
__device__ float g_x  [NTOK*DMODEL];          // token stream f (fp32, residual)
__device__ float g_qkv[NTOK*3*DMODEL];        // qkv fp32 (flash input)
__device__ float g_o  [NTOK*DMODEL];          // gemm fp32 output (Wo / W2 / post)
__device__ __nv_bfloat16 g_wh[W_TOT], g_wl[W_TOT];            // weights hi/lo
__device__ __nv_bfloat16 g_inh[NTOK*DMODEL], g_inl[NTOK*DMODEL];  // patchify / gather out
__device__ __nv_bfloat16 g_xh [NTOK*DMODEL], g_xl [NTOK*DMODEL];  // x hi/lo
__device__ __nv_bfloat16 g_ah [NTOK*DMODEL], g_al [NTOK*DMODEL];  // attention out hi/lo
__device__ __nv_bfloat16 g_hh [NTOK*DFFN],   g_hl [NTOK*DFFN];    // FF hidden hi/lo

// ================= helpers =================
__device__ __forceinline__ uint32_t smem_u32(const void* p) {
    uint32_t a;
    asm("{ .reg .u64 t; cvta.to.shared.u64 t, %1; cvt.u32.u64 %0, t; }" : "=r"(a) : "l"(p));
    return a;
}

__device__ __forceinline__ void split2(float a, float b,
                                       __nv_bfloat162& h, __nv_bfloat162& l)
{
    h = __floats2bfloat162_rn(a, b);
    l = __floats2bfloat162_rn(a - __bfloat162float(h.x), b - __bfloat162float(h.y));
}

#define LDM_X4(r, addr) \
    asm volatile("ldmatrix.sync.aligned.m8n8.x4.shared.b16 {%0,%1,%2,%3}, [%4];" \
        : "=r"((r)[0]), "=r"((r)[1]), "=r"((r)[2]), "=r"((r)[3]) : "r"(addr))

#define MMA16816(c, a, b) \
    asm volatile("mma.sync.aligned.m16n8k16.row.col.f32.bf16.bf16.f32 " \
        "{%0,%1,%2,%3}, {%4,%5,%6,%7}, {%8,%9}, {%0,%1,%2,%3};" \
        : "+f"((c)[0]), "+f"((c)[1]), "+f"((c)[2]), "+f"((c)[3]) \
        : "r"((a)[0]), "r"((a)[1]), "r"((a)[2]), "r"((a)[3]), "r"((b)[0]), "r"((b)[1]))

#define CP16(saddr, gptr) \
    asm volatile("cp.async.cg.shared.global [%0], [%1], 16;" :: "r"(saddr), "l"(gptr) : "memory")
#define CP_COMMIT() asm volatile("cp.async.commit_group;" ::: "memory")

// ---------------- weight fp32 -> bf16 hi/lo converter ----------------
__global__ void cvt_w(const float* __restrict__ src, __nv_bfloat16* __restrict__ dh,
                      __nv_bfloat16* __restrict__ dl, int n4)
{
    int i = blockIdx.x * 256 + threadIdx.x;
    if (i >= n4) return;
    float4 v = ((const float4*)src)[i];
    __nv_bfloat162 h0, l0, h1, l1;
    split2(v.x, v.y, h0, l0);
    split2(v.z, v.w, h1, l1);
    *(__nv_bfloat162*)(dh + 4 * (size_t)i)     = h0;
    *(__nv_bfloat162*)(dh + 4 * (size_t)i + 2) = h1;
    *(__nv_bfloat162*)(dl + 4 * (size_t)i)     = l0;
    *(__nv_bfloat162*)(dl + 4 * (size_t)i + 2) = l1;
}

// ---------------- patchify: (init,end) -> hi/lo bf16 [5120, 512] -----------
__global__ void patchify_kernel(const float* __restrict__ initp,
                                const float* __restrict__ endp,
                                __nv_bfloat16* __restrict__ Xh,
                                __nv_bfloat16* __restrict__ Xl)
{
    int idx = blockIdx.x * blockDim.x + threadIdx.x;   // NTOK*DMODEL threads
    int fi = idx & 511;
    int n  = idx >> 9;
    int b  = n / SEQ;
    int s  = n - b * SEQ;
    int fn = s >> 6;
    int patch = s & 63;
    int pair = fn >> 1, io = fn & 1;
    int pr = patch >> 3, pc = patch & 7;
    int ch = fi >> 8;
    int rem = fi & 255;
    int i = rem >> 4, j = rem & 15;
    const float* src = io ? endp : initp;
    int h = pr * RRES + i, w = pc * RRES + j;
    float v = src[((((size_t)b * PAIRS + pair) * CCH + ch) * HWDIM + h) * HWDIM + w];
    __nv_bfloat16 hb = __float2bfloat16_rn(v);
    Xh[idx] = hb;
    Xl[idx] = __float2bfloat16_rn(v - __bfloat162float(hb));
}

// ---------------- positional add (updates fp32 x, emits hi/lo) -------------
__global__ void add_pos_kernel(float* __restrict__ x,
                               const float* __restrict__ patch_pos,
                               const float* __restrict__ func_pos,
                               __nv_bfloat16* __restrict__ xh,
                               __nv_bfloat16* __restrict__ xl)
{
    int idx = blockIdx.x * blockDim.x + threadIdx.x;
    int d = idx & 511;
    int n = idx >> 9;
    int s = n % SEQ;
    int fn = s >> 6;
    int patch = s & 63;
    float v = x[idx] + patch_pos[patch * DMODEL + d] + func_pos[fn * DMODEL + d];
    x[idx] = v;
    __nv_bfloat16 hb = __float2bfloat16_rn(v);
    xh[idx] = hb;
    xl[idx] = __float2bfloat16_rn(v - __bfloat162float(hb));
}

// =============== bf16 hi/lo MMA GEMM: C = A[N,K] @ W[J,K]^T + bias ========
// A, W given as pre-split bf16 hi/lo. 3 passes: AhWh + AhWl + AlWh.
// Block tile 128x128, 8 warps (2x4), warp 64x32, K-chunk 32.
// cp.async double-buffered. smem stride 40 bf16 (80B, conflict-free ldmatrix).
// mode 0: fp32 out. mode 2: exact GELU + bf16 hi/lo out.
#define GS     40
#define TILE_B (128 * GS * 2)     // 10240 bytes per tile
#define STAGE  (4 * TILE_B)       // 40960 bytes per stage
#define GB_SMEM (2 * STAGE)       // 81920 bytes

__global__ __launch_bounds__(256, 1)
void gemm_bf(const __nv_bfloat16* __restrict__ Ah, const __nv_bfloat16* __restrict__ Al,
             const __nv_bfloat16* __restrict__ Wh, const __nv_bfloat16* __restrict__ Wl,
             const float* __restrict__ bias,
             float* __restrict__ Cf,
             __nv_bfloat16* __restrict__ Ch, __nv_bfloat16* __restrict__ Cl,
             int K, int J, int mode)
{
    extern __shared__ char smem[];
    const uint32_t sbase = smem_u32(smem);
    const int t = threadIdx.x;
    const int lane = t & 31, wid = t >> 5;
    const int wr = wid >> 2, wc = wid & 3;
    const int n0 = blockIdx.y * 128, j0 = blockIdx.x * 128;

    float acc[4][4][4];
#pragma unroll
    for (int mi = 0; mi < 4; mi++)
#pragma unroll
        for (int ni = 0; ni < 4; ni++)
#pragma unroll
            for (int e = 0; e < 4; e++) acc[mi][ni][e] = 0.0f;

    // cp.async: thread covers one row-half; 2 x 16B per tile
    const int lrow = t >> 1;
    const int lseg = (t & 1) * 16;                   // bf16 elements
    const size_t arow = (size_t)(n0 + lrow) * K + lseg;
    const size_t wrow = (size_t)(j0 + lrow) * K + lseg;
    const uint32_t sto = (uint32_t)(lrow * GS + lseg) * 2;

    // ldmatrix lane offsets (bytes)
    const int aoff = ((wr * 64 + (lane & 15)) * GS + ((lane >> 4) << 3)) * 2;
    const int boff = ((wc * 32 + (lane & 7) + ((lane >> 4) << 3)) * GS
                      + (((lane >> 3) & 1) << 3)) * 2;

    const int NC = K >> 5;

    auto issue = [&](int c) {
        uint32_t st = sbase + (uint32_t)(c & 1) * STAGE + sto;
        const __nv_bfloat16* pAh = Ah + arow + c * 32;
        const __nv_bfloat16* pAl = Al + arow + c * 32;
        const __nv_bfloat16* pWh = Wh + wrow + c * 32;
        const __nv_bfloat16* pWl = Wl + wrow + c * 32;
        CP16(st,                pAh); CP16(st + 16,              pAh + 8);
        CP16(st + TILE_B,       pAl); CP16(st + TILE_B + 16,     pAl + 8);
        CP16(st + 2 * TILE_B,   pWh); CP16(st + 2 * TILE_B + 16, pWh + 8);
        CP16(st + 3 * TILE_B,   pWl); CP16(st + 3 * TILE_B + 16, pWl + 8);
        CP_COMMIT();
    };

    issue(0);
    for (int c = 0; c < NC; c++) {
        if (c + 1 < NC) {
            issue(c + 1);
            asm volatile("cp.async.wait_group 1;" ::: "memory");
        } else {
            asm volatile("cp.async.wait_group 0;" ::: "memory");
        }
        __syncthreads();

        const uint32_t sb = sbase + (uint32_t)(c & 1) * STAGE;
        const uint32_t uAh = sb, uAl = sb + TILE_B;
        const uint32_t uWh = sb + 2 * TILE_B, uWl = sb + 3 * TILE_B;

#pragma unroll
        for (int ks = 0; ks < 32; ks += 16) {
            uint32_t Ahf[4][4], Alf[4][4], Bhf[4][2], Blf[4][2];
#pragma unroll
            for (int mi = 0; mi < 4; mi++) {
                int d = (mi * 16 * GS + ks) * 2;
                LDM_X4(Ahf[mi], uAh + aoff + d);
                LDM_X4(Alf[mi], uAl + aoff + d);
            }
#pragma unroll
            for (int pi = 0; pi < 2; pi++) {
                int d = (pi * 16 * GS + ks) * 2;
                uint32_t r[4];
                LDM_X4(r, uWh + boff + d);
                Bhf[2*pi][0] = r[0]; Bhf[2*pi][1] = r[1];
                Bhf[2*pi+1][0] = r[2]; Bhf[2*pi+1][1] = r[3];
                LDM_X4(r, uWl + boff + d);
                Blf[2*pi][0] = r[0]; Blf[2*pi][1] = r[1];
                Blf[2*pi+1][0] = r[2]; Blf[2*pi+1][1] = r[3];
            }
#pragma unroll
            for (int mi = 0; mi < 4; mi++)
#pragma unroll
                for (int ni = 0; ni < 4; ni++) {
                    MMA16816(acc[mi][ni], Ahf[mi], Bhf[ni]);
                    MMA16816(acc[mi][ni], Ahf[mi], Blf[ni]);
                    MMA16816(acc[mi][ni], Alf[mi], Bhf[ni]);
                }
        }
        __syncthreads();
    }

    // epilogue
#pragma unroll
    for (int mi = 0; mi < 4; mi++) {
        int r0 = n0 + wr * 64 + mi * 16 + (lane >> 2);
#pragma unroll
        for (int ni = 0; ni < 4; ni++) {
            int col = j0 + wc * 32 + ni * 8 + (lane & 3) * 2;
            float b0v = bias[col], b1v = bias[col + 1];
            float v0 = acc[mi][ni][0] + b0v;
            float v1 = acc[mi][ni][1] + b1v;
            float v2 = acc[mi][ni][2] + b0v;
            float v3 = acc[mi][ni][3] + b1v;
            if (mode == 2) {
                v0 = 0.5f * v0 * (1.0f + erff(v0 * 0.70710678118654752f));
                v1 = 0.5f * v1 * (1.0f + erff(v1 * 0.70710678118654752f));
                v2 = 0.5f * v2 * (1.0f + erff(v2 * 0.70710678118654752f));
                v3 = 0.5f * v3 * (1.0f + erff(v3 * 0.70710678118654752f));
                __nv_bfloat162 h01, l01, h23, l23;
                split2(v0, v1, h01, l01);
                split2(v2, v3, h23, l23);
                *(__nv_bfloat162*)(Ch + (size_t)r0 * J + col)       = h01;
                *(__nv_bfloat162*)(Cl + (size_t)r0 * J + col)       = l01;
                *(__nv_bfloat162*)(Ch + (size_t)(r0 + 8) * J + col) = h23;
                *(__nv_bfloat162*)(Cl + (size_t)(r0 + 8) * J + col) = l23;
            } else {
                *(float2*)(Cf + (size_t)r0 * J + col)       = make_float2(v0, v1);
                *(float2*)(Cf + (size_t)(r0 + 8) * J + col) = make_float2(v2, v3);
            }
        }
    }
}

// ---------------- flash attention, block-causal (64-token blocks) --------
// qkv layout: [b, s, 3*D], q at h*64, k at 512+h*64, v at 1024+h*64
// output: bf16 hi/lo (Wo GEMM input), feature = h*64 + d
__global__ __launch_bounds__(256)
void flash_kernel(const float* __restrict__ qkv,
                  __nv_bfloat16* __restrict__ outh, __nv_bfloat16* __restrict__ outl)
{
    __shared__ float Qs[64][64];   // [d][m]
    __shared__ float KP[64][64];   // [d][n] for K; reused as P[m][k2]
    __shared__ float Vs[64][64];   // [n][d]

    int qb = blockIdx.x, h = blockIdx.y, b = blockIdx.z;
    int t = threadIdx.x;
    int m = t >> 2;
    int dbase = 16 * (t & 3);

    {
        const float* qrow = qkv + ((size_t)(b * SEQ + qb * 64 + m)) * (3 * DMODEL) + h * DHEAD;
#pragma unroll
        for (int u = 0; u < 4; u++) {
            int d0 = dbase + 4 * u;
            float4 v = *(const float4*)(qrow + d0);
            Qs[d0 + 0][m] = v.x; Qs[d0 + 1][m] = v.y;
            Qs[d0 + 2][m] = v.z; Qs[d0 + 3][m] = v.w;
        }
    }

    int r = (t >> 4) << 2;
    int c = (t & 15) << 2;
    float acc[4][4];
#pragma unroll
    for (int i = 0; i < 4; i++)
#pragma unroll
        for (int j = 0; j < 4; j++) acc[i][j] = 0.0f;
    float mrow[4] = {-INFINITY, -INFINITY, -INFINITY, -INFINITY};
    float lrow[4] = {0.0f, 0.0f, 0.0f, 0.0f};

    for (int kb = 0; kb <= qb; kb++) {
        __syncthreads();
        {
            const float* krow = qkv + ((size_t)(b * SEQ + kb * 64 + m)) * (3 * DMODEL)
                                + DMODEL + h * DHEAD;
            const float* vrow = krow + DMODEL;
#pragma unroll
            for (int u = 0; u < 4; u++) {
                int d0 = dbase + 4 * u;
                float4 kv = *(const float4*)(krow + d0);
                KP[d0 + 0][m] = kv.x; KP[d0 + 1][m] = kv.y;
                KP[d0 + 2][m] = kv.z; KP[d0 + 3][m] = kv.w;
                *(float4*)&Vs[m][d0] = *(const float4*)(vrow + d0);
            }
        }
        __syncthreads();

        float s[4][4];
#pragma unroll
        for (int i = 0; i < 4; i++)
#pragma unroll
            for (int j = 0; j < 4; j++) s[i][j] = 0.0f;
#pragma unroll
        for (int kk = 0; kk < 64; kk++) {
            float4 q4 = *(float4*)&Qs[kk][r];
            float4 k4 = *(float4*)&KP[kk][c];
            float qa[4] = {q4.x, q4.y, q4.z, q4.w};
            float kv[4] = {k4.x, k4.y, k4.z, k4.w};
#pragma unroll
            for (int i = 0; i < 4; i++)
#pragma unroll
                for (int j = 0; j < 4; j++)
                    s[i][j] += qa[i] * kv[j];
        }

        float pr_[4][4];
#pragma unroll
        for (int i = 0; i < 4; i++) {
#pragma unroll
            for (int j = 0; j < 4; j++) s[i][j] *= 0.125f;
            float mx = fmaxf(fmaxf(s[i][0], s[i][1]), fmaxf(s[i][2], s[i][3]));
#pragma unroll
            for (int off = 8; off; off >>= 1)
                mx = fmaxf(mx, __shfl_xor_sync(0xffffffffu, mx, off));
            float mnew = fmaxf(mrow[i], mx);
            float al = expf(mrow[i] - mnew);
            float rs = 0.0f;
#pragma unroll
            for (int j = 0; j < 4; j++) {
                pr_[i][j] = expf(s[i][j] - mnew);
                rs += pr_[i][j];
            }
#pragma unroll
            for (int off = 8; off; off >>= 1)
                rs += __shfl_xor_sync(0xffffffffu, rs, off);
            lrow[i] = lrow[i] * al + rs;
            mrow[i] = mnew;
#pragma unroll
            for (int j = 0; j < 4; j++) acc[i][j] *= al;
        }

        __syncthreads();
#pragma unroll
        for (int i = 0; i < 4; i++)
            *(float4*)&KP[r + i][c] = make_float4(pr_[i][0], pr_[i][1], pr_[i][2], pr_[i][3]);
        __syncthreads();

#pragma unroll
        for (int kk = 0; kk < 64; kk++) {
            float p0 = KP[r + 0][kk], p1 = KP[r + 1][kk];
            float p2 = KP[r + 2][kk], p3 = KP[r + 3][kk];
            float4 v4 = *(float4*)&Vs[kk][c];
            acc[0][0] += p0 * v4.x; acc[0][1] += p0 * v4.y; acc[0][2] += p0 * v4.z; acc[0][3] += p0 * v4.w;
            acc[1][0] += p1 * v4.x; acc[1][1] += p1 * v4.y; acc[1][2] += p1 * v4.z; acc[1][3] += p1 * v4.w;
            acc[2][0] += p2 * v4.x; acc[2][1] += p2 * v4.y; acc[2][2] += p2 * v4.z; acc[2][3] += p2 * v4.w;
            acc[3][0] += p3 * v4.x; acc[3][1] += p3 * v4.y; acc[3][2] += p3 * v4.z; acc[3][3] += p3 * v4.w;
        }
    }

#pragma unroll
    for (int i = 0; i < 4; i++) {
        float inv = 1.0f / lrow[i];
        float o0 = acc[i][0] * inv, o1 = acc[i][1] * inv;
        float o2 = acc[i][2] * inv, o3 = acc[i][3] * inv;
        __nv_bfloat162 h01, l01, h23, l23;
        split2(o0, o1, h01, l01);
        split2(o2, o3, h23, l23);
        size_t base = ((size_t)(b * SEQ + qb * 64 + r + i)) * DMODEL + h * DHEAD + c;
        *(__nv_bfloat162*)(outh + base)     = h01;
        *(__nv_bfloat162*)(outh + base + 2) = h23;
        *(__nv_bfloat162*)(outl + base)     = l01;
        *(__nv_bfloat162*)(outl + base + 2) = l23;
    }
}

// -------- residual add + LayerNorm (in place on x; emits hi/lo) ----------
__global__ __launch_bounds__(256)
void add_ln_kernel(float* __restrict__ x, const float* __restrict__ o,
                   const float* __restrict__ sc, const float* __restrict__ bi,
                   __nv_bfloat16* __restrict__ xh, __nv_bfloat16* __restrict__ xl)
{
    int tok = blockIdx.x;
    int t = threadIdx.x;
    size_t base = (size_t)tok * DMODEL;
    float v0 = x[base + t]       + o[base + t];
    float v1 = x[base + t + 256] + o[base + t + 256];

    __shared__ float red[8];
    int warp = t >> 5, lane = t & 31;

    float s = v0 + v1;
#pragma unroll
    for (int off = 16; off; off >>= 1) s += __shfl_xor_sync(0xffffffffu, s, off);
    if (lane == 0) red[warp] = s;
    __syncthreads();
    float tot = 0.0f;
#pragma unroll
    for (int w = 0; w < 8; w++) tot += red[w];
    float mean = tot * (1.0f / 512.0f);

    float d0 = v0 - mean, d1 = v1 - mean;
    float q = d0 * d0 + d1 * d1;
#pragma unroll
    for (int off = 16; off; off >>= 1) q += __shfl_xor_sync(0xffffffffu, q, off);
    __syncthreads();
    if (lane == 0) red[warp] = q;
    __syncthreads();
    float tq = 0.0f;
#pragma unroll
    for (int w = 0; w < 8; w++) tq += red[w];
    float inv = rsqrtf(tq * (1.0f / 512.0f) + 1e-5f);

    float y0 = d0 * inv * sc[t]       + bi[t];
    float y1 = d1 * inv * sc[t + 256] + bi[t + 256];
    x[base + t]       = y0;
    x[base + t + 256] = y1;
    __nv_bfloat16 h0 = __float2bfloat16_rn(y0);
    __nv_bfloat16 h1 = __float2bfloat16_rn(y1);
    xh[base + t]       = h0;
    xh[base + t + 256] = h1;
    xl[base + t]       = __float2bfloat16_rn(y0 - __bfloat162float(h0));
    xl[base + t + 256] = __float2bfloat16_rn(y1 - __bfloat162float(h1));
}

// ------- gather init slots -> hi/lo bf16 [2560, 512] (post GEMM input) ----
__global__ void gather_kernel(const float* __restrict__ x,
                              __nv_bfloat16* __restrict__ yh,
                              __nv_bfloat16* __restrict__ yl)
{
    int idx = blockIdx.x * blockDim.x + threadIdx.x;   // NSEL*DMODEL
    int d = idx & 511;
    int row = idx >> 9;
    int b = row / (PAIRS * 64);
    int r2 = row - b * (PAIRS * 64);
    int pair = r2 >> 6;
    int patch = r2 & 63;
    int s = pair * 128 + patch;
    float v = x[((size_t)(b * SEQ + s)) * DMODEL + d];
    __nv_bfloat16 hb = __float2bfloat16_rn(v);
    yh[idx] = hb;
    yl[idx] = __float2bfloat16_rn(v - __bfloat162float(hb));
}

// ---------------- depatchify to output --------------------------------
__global__ void depatch_kernel(const float* __restrict__ y, float* __restrict__ out)
{
    int idx = blockIdx.x * blockDim.x + threadIdx.x;   // BSZ*PAIRS*CCH*HW*HW
    int w = idx & 127;
    int h = (idx >> 7) & 127;
    int ch = (idx >> 14) & 1;
    int rest = idx >> 15;
    int pr = h >> 4, i = h & 15;
    int pc = w >> 4, j = w & 15;
    int row = rest * 64 + pr * 8 + pc;
    int fi = ch * 256 + i * 16 + j;
    out[idx] = y[(size_t)row * DMODEL + fi];
}

// ---------------- host launcher ----------------------------------------
extern "C" void kernel_launch(void* const* d_in, const int* in_sizes, int n_in,
                              void* d_out, int out_size)
{
    const float* initp     = (const float*)d_in[0];
    const float* endp      = (const float*)d_in[1];
    // d_in[2] = c_mask (bool) — unused by the reference forward
    const float* pre_W     = (const float*)d_in[3];
    const float* pre_b     = (const float*)d_in[4];
    const float* post_W    = (const float*)d_in[5];
    const float* post_b    = (const float*)d_in[6];
    const float* patch_pos = (const float*)d_in[7];
    const float* func_pos  = (const float*)d_in[8];
    const float* Wqkv      = (const float*)d_in[9];
    const float* bqkv      = (const float*)d_in[10];
    const float* Wo        = (const float*)d_in[11];
    const float* bo        = (const float*)d_in[12];
    const float* ln1s      = (const float*)d_in[13];
    const float* ln1b      = (const float*)d_in[14];
    const float* ln2s      = (const float*)d_in[15];
    const float* ln2b      = (const float*)d_in[16];
    const float* W1        = (const float*)d_in[17];
    const float* b1        = (const float*)d_in[18];
    const float* W2        = (const float*)d_in[19];
    const float* b2        = (const float*)d_in[20];
    float* out = (float*)d_out;

    float *px, *pqkv, *po;
    __nv_bfloat16 *wh, *wl, *inh, *inl, *xh, *xl, *ah, *al, *hh, *hl;
    cudaGetSymbolAddress((void**)&px,   g_x);
    cudaGetSymbolAddress((void**)&pqkv, g_qkv);
    cudaGetSymbolAddress((void**)&po,   g_o);
    cudaGetSymbolAddress((void**)&wh,   g_wh);
    cudaGetSymbolAddress((void**)&wl,   g_wl);
    cudaGetSymbolAddress((void**)&inh,  g_inh);
    cudaGetSymbolAddress((void**)&inl,  g_inl);
    cudaGetSymbolAddress((void**)&xh,   g_xh);
    cudaGetSymbolAddress((void**)&xl,   g_xl);
    cudaGetSymbolAddress((void**)&ah,   g_ah);
    cudaGetSymbolAddress((void**)&al,   g_al);
    cudaGetSymbolAddress((void**)&hh,   g_hh);
    cudaGetSymbolAddress((void**)&hl,   g_hl);

    static bool attr_set = false;
    if (!attr_set) {
        cudaFuncSetAttribute(gemm_bf, cudaFuncAttributeMaxDynamicSharedMemorySize, GB_SMEM);
        attr_set = true;
    }

    const int TOKELEM = NTOK * DMODEL;        // 2,621,440

    // ---- weight hi/lo conversion (one pass over all weights) ----
    {
        struct { const float* s; int off; int n; } wjobs[6] = {
            {pre_W,  W_PRE,  512*512},
            {Wqkv,   W_QKV,  6*1536*512},
            {Wo,     W_WO,   6*512*512},
            {W1,     W_W1,   6*2048*512},
            {W2,     W_W2,   6*512*2048},
            {post_W, W_POST, 512*512},
        };
        for (int i = 0; i < 6; i++) {
            int n4 = wjobs[i].n >> 2;
            cvt_w<<<(n4 + 255) / 256, 256>>>(wjobs[i].s, wh + wjobs[i].off, wl + wjobs[i].off, n4);
        }
    }

    // embed: patchify -> pre projection -> positional encodings
    patchify_kernel<<<TOKELEM / 256, 256>>>(initp, endp, inh, inl);
    gemm_bf<<<dim3(DMODEL / 128, NTOK / 128), 256, GB_SMEM>>>(
        inh, inl, wh + W_PRE, wl + W_PRE, pre_b, px, nullptr, nullptr, 512, DMODEL, 0);
    add_pos_kernel<<<TOKELEM / 256, 256>>>(px, patch_pos, func_pos, xh, xl);

    for (int l = 0; l < NLAYER; l++) {
        const __nv_bfloat16* qh = wh + W_QKV + (size_t)l * 1536 * 512;
        const __nv_bfloat16* ql = wl + W_QKV + (size_t)l * 1536 * 512;
        const __nv_bfloat16* oh = wh + W_WO  + (size_t)l * 512 * 512;
        const __nv_bfloat16* ol = wl + W_WO  + (size_t)l * 512 * 512;
        const __nv_bfloat16* f1h = wh + W_W1 + (size_t)l * 2048 * 512;
        const __nv_bfloat16* f1l = wl + W_W1 + (size_t)l * 2048 * 512;
        const __nv_bfloat16* f2h = wh + W_W2 + (size_t)l * 512 * 2048;
        const __nv_bfloat16* f2l = wl + W_W2 + (size_t)l * 512 * 2048;
        const float* bqkv_l = bqkv + (size_t)l * 1536;
        const float* bo_l   = bo   + (size_t)l * DMODEL;
        const float* b1_l   = b1   + (size_t)l * DFFN;
        const float* b2_l   = b2   + (size_t)l * DMODEL;

        gemm_bf<<<dim3(1536 / 128, NTOK / 128), 256, GB_SMEM>>>(
            xh, xl, qh, ql, bqkv_l, pqkv, nullptr, nullptr, 512, 1536, 0);
        flash_kernel<<<dim3(SEQ / 64, NHEAD, BSZ), 256>>>(pqkv, ah, al);
        gemm_bf<<<dim3(DMODEL / 128, NTOK / 128), 256, GB_SMEM>>>(
            ah, al, oh, ol, bo_l, po, nullptr, nullptr, 512, DMODEL, 0);
        add_ln_kernel<<<NTOK, 256>>>(px, po, ln1s + (size_t)l * DMODEL,
                                     ln1b + (size_t)l * DMODEL, xh, xl);
        gemm_bf<<<dim3(DFFN / 128, NTOK / 128), 256, GB_SMEM>>>(
            xh, xl, f1h, f1l, b1_l, nullptr, hh, hl, 512, DFFN, 2);
        gemm_bf<<<dim3(DMODEL / 128, NTOK / 128), 256, GB_SMEM>>>(
            hh, hl, f2h, f2l, b2_l, po, nullptr, nullptr, 2048, DMODEL, 0);
        add_ln_kernel<<<NTOK, 256>>>(px, po, ln2s + (size_t)l * DMODEL,
                                     ln2b + (size_t)l * DMODEL, xh, xl);
    }

    // output head: select init slots, project, depatchify
    gather_kernel<<<(NSEL * DMODEL) / 256, 256>>>(px, inh, inl);
    gemm_bf<<<dim3(DMODEL / 128, NSEL / 128), 256, GB_SMEM>>>(
        inh, inl, wh + W_POST, wl + W_POST, post_b, po, nullptr, nullptr, 512, DMODEL, 0);
    depatch_kernel<<<(BSZ * PAIRS * CCH * HWDIM * HWDIM) / 256, 256>>>(po, out);
}

// round 13
// speedup vs baseline: 2.0894x; 1.1499x over previous
#include <cuda_runtime.h>
#include <cuda_bf16.h>
#include <math.h>
#include <stdint.h>

// ---------------- problem constants ----------------
#define BSZ     8
#define PAIRS   5
#define CCH     2
#define PGRID   8          // P
#define RRES    16         // R
#define HWDIM   128        // P*R
#define SEQ     640        // PAIRS*2*P*P
#define DMODEL  512
#define NHEAD   8
#define DHEAD   64
#define DFFN    2048
#define NLAYER  6
#define NTOK    (BSZ*SEQ)  // 5120
#define NSEL    (BSZ*PAIRS*PGRID*PGRID)  // 2560

// ---------------- weight hi/lo buffer offsets ----------------
#define W_PRE   0
#define W_QKV   (W_PRE  + 512*512)
#define W_WO    (W_QKV  + 6*1536*512)
#define W_W1    (W_WO   + 6*512*512)
#define W_W2    (W_W1   + 6*2048*512)
#define W_POST  (W_W2   + 6*512*2048)
#define W_TOT   (W_POST + 512*512)

// ---------------- scratch (device globals; no allocation allowed) ----------
__device__ float g_x  [NTOK*DMODEL];          // token stream f (fp32, residual)
__device__ float g_qkv[NTOK*3*DMODEL];        // qkv fp32 (flash input)
__device__ float g_o  [NTOK*DMODEL];          // gemm fp32 output (Wo / W2 / post)
__device__ __nv_bfloat16 g_wh[W_TOT], g_wl[W_TOT];            // weights hi/lo
__device__ __nv_bfloat16 g_inh[NTOK*DMODEL], g_inl[NTOK*DMODEL];  // patchify / gather out
__device__ __nv_bfloat16 g_xh [NTOK*DMODEL], g_xl [NTOK*DMODEL];  // x hi/lo
__device__ __nv_bfloat16 g_ah [NTOK*DMODEL], g_al [NTOK*DMODEL];  // attention out hi/lo
__device__ __nv_bfloat16 g_hh [NTOK*DFFN],   g_hl [NTOK*DFFN];    // FF hidden hi/lo

// ================= helpers =================
__device__ __forceinline__ uint32_t smem_u32(const void* p) {
    uint32_t a;
    asm("{ .reg .u64 t; cvta.to.shared.u64 t, %1; cvt.u32.u64 %0, t; }" : "=r"(a) : "l"(p));
    return a;
}

__device__ __forceinline__ void split2(float a, float b,
                                       __nv_bfloat162& h, __nv_bfloat162& l)
{
    h = __floats2bfloat162_rn(a, b);
    l = __floats2bfloat162_rn(a - __bfloat162float(h.x), b - __bfloat162float(h.y));
}

#define LDM_X4(r, addr) \
    asm volatile("ldmatrix.sync.aligned.m8n8.x4.shared.b16 {%0,%1,%2,%3}, [%4];" \
        : "=r"((r)[0]), "=r"((r)[1]), "=r"((r)[2]), "=r"((r)[3]) : "r"(addr))

#define LDM_X4_T(r, addr) \
    asm volatile("ldmatrix.sync.aligned.m8n8.x4.trans.shared.b16 {%0,%1,%2,%3}, [%4];" \
        : "=r"((r)[0]), "=r"((r)[1]), "=r"((r)[2]), "=r"((r)[3]) : "r"(addr))

#define MMA16816(c, a, b) \
    asm volatile("mma.sync.aligned.m16n8k16.row.col.f32.bf16.bf16.f32 " \
        "{%0,%1,%2,%3}, {%4,%5,%6,%7}, {%8,%9}, {%0,%1,%2,%3};" \
        : "+f"((c)[0]), "+f"((c)[1]), "+f"((c)[2]), "+f"((c)[3]) \
        : "r"((a)[0]), "r"((a)[1]), "r"((a)[2]), "r"((a)[3]), "r"((b)[0]), "r"((b)[1]))

#define CP16(saddr, gptr) \
    asm volatile("cp.async.cg.shared.global [%0], [%1], 16;" :: "r"(saddr), "l"(gptr) : "memory")
#define CP_COMMIT() asm volatile("cp.async.commit_group;" ::: "memory")

// ---------------- weight fp32 -> bf16 hi/lo converter ----------------
__global__ void cvt_w(const float* __restrict__ src, __nv_bfloat16* __restrict__ dh,
                      __nv_bfloat16* __restrict__ dl, int n4)
{
    int i = blockIdx.x * 256 + threadIdx.x;
    if (i >= n4) return;
    float4 v = ((const float4*)src)[i];
    __nv_bfloat162 h0, l0, h1, l1;
    split2(v.x, v.y, h0, l0);
    split2(v.z, v.w, h1, l1);
    *(__nv_bfloat162*)(dh + 4 * (size_t)i)     = h0;
    *(__nv_bfloat162*)(dh + 4 * (size_t)i + 2) = h1;
    *(__nv_bfloat162*)(dl + 4 * (size_t)i)     = l0;
    *(__nv_bfloat162*)(dl + 4 * (size_t)i + 2) = l1;
}

// ---------------- patchify: (init,end) -> hi/lo bf16 [5120, 512] -----------
__global__ void patchify_kernel(const float* __restrict__ initp,
                                const float* __restrict__ endp,
                                __nv_bfloat16* __restrict__ Xh,
                                __nv_bfloat16* __restrict__ Xl)
{
    int idx = blockIdx.x * blockDim.x + threadIdx.x;
    int fi = idx & 511;
    int n  = idx >> 9;
    int b  = n / SEQ;
    int s  = n - b * SEQ;
    int fn = s >> 6;
    int patch = s & 63;
    int pair = fn >> 1, io = fn & 1;
    int pr = patch >> 3, pc = patch & 7;
    int ch = fi >> 8;
    int rem = fi & 255;
    int i = rem >> 4, j = rem & 15;
    const float* src = io ? endp : initp;
    int h = pr * RRES + i, w = pc * RRES + j;
    float v = src[((((size_t)b * PAIRS + pair) * CCH + ch) * HWDIM + h) * HWDIM + w];
    __nv_bfloat16 hb = __float2bfloat16_rn(v);
    Xh[idx] = hb;
    Xl[idx] = __float2bfloat16_rn(v - __bfloat162float(hb));
}

// ---------------- positional add (updates fp32 x, emits hi/lo) -------------
__global__ void add_pos_kernel(float* __restrict__ x,
                               const float* __restrict__ patch_pos,
                               const float* __restrict__ func_pos,
                               __nv_bfloat16* __restrict__ xh,
                               __nv_bfloat16* __restrict__ xl)
{
    int idx = blockIdx.x * blockDim.x + threadIdx.x;
    int d = idx & 511;
    int n = idx >> 9;
    int s = n % SEQ;
    int fn = s >> 6;
    int patch = s & 63;
    float v = x[idx] + patch_pos[patch * DMODEL + d] + func_pos[fn * DMODEL + d];
    x[idx] = v;
    __nv_bfloat16 hb = __float2bfloat16_rn(v);
    xh[idx] = hb;
    xl[idx] = __float2bfloat16_rn(v - __bfloat162float(hb));
}

// =============== bf16 hi/lo MMA GEMM: C = A[N,K] @ W[J,K]^T + bias ========
#define GS     40
#define TILE_B (128 * GS * 2)
#define STAGE  (4 * TILE_B)
#define GB_SMEM (2 * STAGE)

__global__ __launch_bounds__(256, 1)
void gemm_bf(const __nv_bfloat16* __restrict__ Ah, const __nv_bfloat16* __restrict__ Al,
             const __nv_bfloat16* __restrict__ Wh, const __nv_bfloat16* __restrict__ Wl,
             const float* __restrict__ bias,
             float* __restrict__ Cf,
             __nv_bfloat16* __restrict__ Ch, __nv_bfloat16* __restrict__ Cl,
             int K, int J, int mode)
{
    extern __shared__ char smem[];
    const uint32_t sbase = smem_u32(smem);
    const int t = threadIdx.x;
    const int lane = t & 31, wid = t >> 5;
    const int wr = wid >> 2, wc = wid & 3;
    const int n0 = blockIdx.y * 128, j0 = blockIdx.x * 128;

    float acc[4][4][4];
#pragma unroll
    for (int mi = 0; mi < 4; mi++)
#pragma unroll
        for (int ni = 0; ni < 4; ni++)
#pragma unroll
            for (int e = 0; e < 4; e++) acc[mi][ni][e] = 0.0f;

    const int lrow = t >> 1;
    const int lseg = (t & 1) * 16;
    const size_t arow = (size_t)(n0 + lrow) * K + lseg;
    const size_t wrow = (size_t)(j0 + lrow) * K + lseg;
    const uint32_t sto = (uint32_t)(lrow * GS + lseg) * 2;

    const int aoff = ((wr * 64 + (lane & 15)) * GS + ((lane >> 4) << 3)) * 2;
    const int boff = ((wc * 32 + (lane & 7) + ((lane >> 4) << 3)) * GS
                      + (((lane >> 3) & 1) << 3)) * 2;

    const int NC = K >> 5;

    auto issue = [&](int c) {
        uint32_t st = sbase + (uint32_t)(c & 1) * STAGE + sto;
        const __nv_bfloat16* pAh = Ah + arow + c * 32;
        const __nv_bfloat16* pAl = Al + arow + c * 32;
        const __nv_bfloat16* pWh = Wh + wrow + c * 32;
        const __nv_bfloat16* pWl = Wl + wrow + c * 32;
        CP16(st,                pAh); CP16(st + 16,              pAh + 8);
        CP16(st + TILE_B,       pAl); CP16(st + TILE_B + 16,     pAl + 8);
        CP16(st + 2 * TILE_B,   pWh); CP16(st + 2 * TILE_B + 16, pWh + 8);
        CP16(st + 3 * TILE_B,   pWl); CP16(st + 3 * TILE_B + 16, pWl + 8);
        CP_COMMIT();
    };

    issue(0);
    for (int c = 0; c < NC; c++) {
        if (c + 1 < NC) {
            issue(c + 1);
            asm volatile("cp.async.wait_group 1;" ::: "memory");
        } else {
            asm volatile("cp.async.wait_group 0;" ::: "memory");
        }
        __syncthreads();

        const uint32_t sb = sbase + (uint32_t)(c & 1) * STAGE;
        const uint32_t uAh = sb, uAl = sb + TILE_B;
        const uint32_t uWh = sb + 2 * TILE_B, uWl = sb + 3 * TILE_B;

#pragma unroll
        for (int ks = 0; ks < 32; ks += 16) {
            uint32_t Ahf[4][4], Alf[4][4], Bhf[4][2], Blf[4][2];
#pragma unroll
            for (int mi = 0; mi < 4; mi++) {
                int d = (mi * 16 * GS + ks) * 2;
                LDM_X4(Ahf[mi], uAh + aoff + d);
                LDM_X4(Alf[mi], uAl + aoff + d);
            }
#pragma unroll
            for (int pi = 0; pi < 2; pi++) {
                int d = (pi * 16 * GS + ks) * 2;
                uint32_t r[4];
                LDM_X4(r, uWh + boff + d);
                Bhf[2*pi][0] = r[0]; Bhf[2*pi][1] = r[1];
                Bhf[2*pi+1][0] = r[2]; Bhf[2*pi+1][1] = r[3];
                LDM_X4(r, uWl + boff + d);
                Blf[2*pi][0] = r[0]; Blf[2*pi][1] = r[1];
                Blf[2*pi+1][0] = r[2]; Blf[2*pi+1][1] = r[3];
            }
#pragma unroll
            for (int mi = 0; mi < 4; mi++)
#pragma unroll
                for (int ni = 0; ni < 4; ni++) {
                    MMA16816(acc[mi][ni], Ahf[mi], Bhf[ni]);
                    MMA16816(acc[mi][ni], Ahf[mi], Blf[ni]);
                    MMA16816(acc[mi][ni], Alf[mi], Bhf[ni]);
                }
        }
        __syncthreads();
    }

#pragma unroll
    for (int mi = 0; mi < 4; mi++) {
        int r0 = n0 + wr * 64 + mi * 16 + (lane >> 2);
#pragma unroll
        for (int ni = 0; ni < 4; ni++) {
            int col = j0 + wc * 32 + ni * 8 + (lane & 3) * 2;
            float b0v = bias[col], b1v = bias[col + 1];
            float v0 = acc[mi][ni][0] + b0v;
            float v1 = acc[mi][ni][1] + b1v;
            float v2 = acc[mi][ni][2] + b0v;
            float v3 = acc[mi][ni][3] + b1v;
            if (mode == 2) {
                v0 = 0.5f * v0 * (1.0f + erff(v0 * 0.70710678118654752f));
                v1 = 0.5f * v1 * (1.0f + erff(v1 * 0.70710678118654752f));
                v2 = 0.5f * v2 * (1.0f + erff(v2 * 0.70710678118654752f));
                v3 = 0.5f * v3 * (1.0f + erff(v3 * 0.70710678118654752f));
                __nv_bfloat162 h01, l01, h23, l23;
                split2(v0, v1, h01, l01);
                split2(v2, v3, h23, l23);
                *(__nv_bfloat162*)(Ch + (size_t)r0 * J + col)       = h01;
                *(__nv_bfloat162*)(Cl + (size_t)r0 * J + col)       = l01;
                *(__nv_bfloat162*)(Ch + (size_t)(r0 + 8) * J + col) = h23;
                *(__nv_bfloat162*)(Cl + (size_t)(r0 + 8) * J + col) = l23;
            } else {
                *(float2*)(Cf + (size_t)r0 * J + col)       = make_float2(v0, v1);
                *(float2*)(Cf + (size_t)(r0 + 8) * J + col) = make_float2(v2, v3);
            }
        }
    }
}

// =============== MMA flash attention, block-causal (64-token blocks) ======
// qkv layout: [b, s, 3*D] fp32; q at h*64, k at 512+h*64, v at 1024+h*64.
// CTA = (qb, h, b), 128 threads / 4 warps; warp owns 16 q-rows.
// S = Q*K^T via 3-pass bf16 hi/lo MMA (Q pre-scaled by 0.125).
// P fragments built from S accumulators in registers; O += P*V with
// ldmatrix.trans on V. Output bf16 hi/lo (input of the Wo GEMM).
#define FS 72   // smem stride (bf16 elems) for 64-wide tiles

__global__ __launch_bounds__(128)
void flash_mma(const float* __restrict__ qkv,
               __nv_bfloat16* __restrict__ outh, __nv_bfloat16* __restrict__ outl)
{
    __shared__ __nv_bfloat16 Ksh[64 * FS], Ksl[64 * FS];
    __shared__ __nv_bfloat16 Vsh[64 * FS], Vsl[64 * FS];

    const int qb = blockIdx.x, h = blockIdx.y, b = blockIdx.z;
    const int t = threadIdx.x, lane = t & 31, w = t >> 5;

    // ---- stage Q (x0.125) into Ksh/Ksl, then grab register fragments ----
    {
        int row = t >> 1, half = (t & 1) * 32;
        const float* qrow = qkv + ((size_t)(b * SEQ + qb * 64 + row)) * 1536 + h * 64 + half;
#pragma unroll
        for (int u = 0; u < 8; u++) {
            float4 v = *(const float4*)(qrow + u * 4);
            __nv_bfloat162 h0, l0, h1, l1;
            split2(v.x * 0.125f, v.y * 0.125f, h0, l0);
            split2(v.z * 0.125f, v.w * 0.125f, h1, l1);
            int o = row * FS + half + u * 4;
            *(__nv_bfloat162*)(Ksh + o)     = h0;
            *(__nv_bfloat162*)(Ksh + o + 2) = h1;
            *(__nv_bfloat162*)(Ksl + o)     = l0;
            *(__nv_bfloat162*)(Ksl + o + 2) = l1;
        }
    }
    __syncthreads();

    const uint32_t uKh = smem_u32(Ksh), uKl = smem_u32(Ksl);
    const uint32_t uVh = smem_u32(Vsh), uVl = smem_u32(Vsl);

    uint32_t qh_f[4][4], ql_f[4][4];
    {
        int ro = (w * 16 + (lane & 15)) * FS + ((lane >> 4) << 3);
#pragma unroll
        for (int ks = 0; ks < 4; ks++) {
            LDM_X4(qh_f[ks], uKh + (ro + ks * 16) * 2);
            LDM_X4(ql_f[ks], uKl + (ro + ks * 16) * 2);
        }
    }

    float oacc[8][4];
#pragma unroll
    for (int ni = 0; ni < 8; ni++)
#pragma unroll
        for (int e = 0; e < 4; e++) oacc[ni][e] = 0.0f;
    float m0 = -INFINITY, m1 = -INFINITY, l0s = 0.0f, l1s = 0.0f;

    // ldmatrix lane offsets
    const int krowp = (lane & 7) + ((lane >> 4) << 3);
    const int kcolp = ((lane >> 3) & 1) << 3;
    const int vro = (lane & 15);
    const int vco = ((lane >> 4) << 3);

    for (int kb = 0; kb <= qb; kb++) {
        __syncthreads();   // previous iteration's reads (and Q frag reads) done
        {
            int row = t & 63;
            const float* src = qkv + ((size_t)(b * SEQ + kb * 64 + row)) * 1536
                               + 512 + ((t >> 6) << 9) + h * 64;
            __nv_bfloat16* dh = (t < 64) ? Ksh : Vsh;
            __nv_bfloat16* dl = (t < 64) ? Ksl : Vsl;
#pragma unroll
            for (int u = 0; u < 16; u++) {
                float4 v = *(const float4*)(src + u * 4);
                __nv_bfloat162 h0, e0, h1, e1;
                split2(v.x, v.y, h0, e0);
                split2(v.z, v.w, h1, e1);
                int o = row * FS + u * 4;
                *(__nv_bfloat162*)(dh + o)     = h0;
                *(__nv_bfloat162*)(dh + o + 2) = h1;
                *(__nv_bfloat162*)(dl + o)     = e0;
                *(__nv_bfloat162*)(dl + o + 2) = e1;
            }
        }
        __syncthreads();

        // ---- S = Q K^T ----
        float sacc[8][4];
#pragma unroll
        for (int ni = 0; ni < 8; ni++)
#pragma unroll
            for (int e = 0; e < 4; e++) sacc[ni][e] = 0.0f;

#pragma unroll
        for (int ks = 0; ks < 4; ks++) {
#pragma unroll
            for (int ni2 = 0; ni2 < 4; ni2++) {
                int off = ((ni2 * 16 + krowp) * FS + ks * 16 + kcolp) * 2;
                uint32_t bh[4], bl[4];
                LDM_X4(bh, uKh + off);
                LDM_X4(bl, uKl + off);
                uint32_t b0h[2] = {bh[0], bh[1]}, b1h[2] = {bh[2], bh[3]};
                uint32_t b0l[2] = {bl[0], bl[1]}, b1l[2] = {bl[2], bl[3]};
                MMA16816(sacc[ni2*2],   qh_f[ks], b0h);
                MMA16816(sacc[ni2*2],   qh_f[ks], b0l);
                MMA16816(sacc[ni2*2],   ql_f[ks], b0h);
                MMA16816(sacc[ni2*2+1], qh_f[ks], b1h);
                MMA16816(sacc[ni2*2+1], qh_f[ks], b1l);
                MMA16816(sacc[ni2*2+1], ql_f[ks], b1h);
            }
        }

        // ---- online softmax (rows r0 = w*16 + lane>>2 and r0+8) ----
        float mx0 = -INFINITY, mx1 = -INFINITY;
#pragma unroll
        for (int ni = 0; ni < 8; ni++) {
            mx0 = fmaxf(mx0, fmaxf(sacc[ni][0], sacc[ni][1]));
            mx1 = fmaxf(mx1, fmaxf(sacc[ni][2], sacc[ni][3]));
        }
        mx0 = fmaxf(mx0, __shfl_xor_sync(0xffffffffu, mx0, 1));
        mx0 = fmaxf(mx0, __shfl_xor_sync(0xffffffffu, mx0, 2));
        mx1 = fmaxf(mx1, __shfl_xor_sync(0xffffffffu, mx1, 1));
        mx1 = fmaxf(mx1, __shfl_xor_sync(0xffffffffu, mx1, 2));

        float mn0 = fmaxf(m0, mx0), mn1 = fmaxf(m1, mx1);
        float a0 = __expf(m0 - mn0), a1 = __expf(m1 - mn1);
        float s0 = 0.0f, s1 = 0.0f;
#pragma unroll
        for (int ni = 0; ni < 8; ni++) {
            sacc[ni][0] = __expf(sacc[ni][0] - mn0);
            sacc[ni][1] = __expf(sacc[ni][1] - mn0);
            sacc[ni][2] = __expf(sacc[ni][2] - mn1);
            sacc[ni][3] = __expf(sacc[ni][3] - mn1);
            s0 += sacc[ni][0] + sacc[ni][1];
            s1 += sacc[ni][2] + sacc[ni][3];
        }
        s0 += __shfl_xor_sync(0xffffffffu, s0, 1);
        s0 += __shfl_xor_sync(0xffffffffu, s0, 2);
        s1 += __shfl_xor_sync(0xffffffffu, s1, 1);
        s1 += __shfl_xor_sync(0xffffffffu, s1, 2);
        l0s = l0s * a0 + s0;
        l1s = l1s * a1 + s1;
        m0 = mn0; m1 = mn1;
#pragma unroll
        for (int ni = 0; ni < 8; ni++) {
            oacc[ni][0] *= a0; oacc[ni][1] *= a0;
            oacc[ni][2] *= a1; oacc[ni][3] *= a1;
        }

        // ---- O += P V ----
#pragma unroll
        for (int ksv = 0; ksv < 4; ksv++) {
            uint32_t ph[4], pl[4];
            {
                __nv_bfloat162 hx, lx;
                split2(sacc[2*ksv][0],   sacc[2*ksv][1],   hx, lx);
                ph[0] = *(uint32_t*)&hx; pl[0] = *(uint32_t*)&lx;
                split2(sacc[2*ksv][2],   sacc[2*ksv][3],   hx, lx);
                ph[1] = *(uint32_t*)&hx; pl[1] = *(uint32_t*)&lx;
                split2(sacc[2*ksv+1][0], sacc[2*ksv+1][1], hx, lx);
                ph[2] = *(uint32_t*)&hx; pl[2] = *(uint32_t*)&lx;
                split2(sacc[2*ksv+1][2], sacc[2*ksv+1][3], hx, lx);
                ph[3] = *(uint32_t*)&hx; pl[3] = *(uint32_t*)&lx;
            }
#pragma unroll
            for (int db = 0; db < 4; db++) {
                int off = ((ksv * 16 + vro) * FS + db * 16 + vco) * 2;
                uint32_t vh4[4], vl4[4];
                LDM_X4_T(vh4, uVh + off);
                LDM_X4_T(vl4, uVl + off);
                uint32_t b0h[2] = {vh4[0], vh4[1]}, b1h[2] = {vh4[2], vh4[3]};
                uint32_t b0l[2] = {vl4[0], vl4[1]}, b1l[2] = {vl4[2], vl4[3]};
                MMA16816(oacc[db*2],   ph, b0h);
                MMA16816(oacc[db*2],   ph, b0l);
                MMA16816(oacc[db*2],   pl, b0h);
                MMA16816(oacc[db*2+1], ph, b1h);
                MMA16816(oacc[db*2+1], ph, b1l);
                MMA16816(oacc[db*2+1], pl, b1h);
            }
        }
    }

    // ---- epilogue: divide by l, write bf16 hi/lo ----
    float inv0 = 1.0f / l0s, inv1 = 1.0f / l1s;
    size_t r0g = (size_t)(b * SEQ + qb * 64 + w * 16 + (lane >> 2));
#pragma unroll
    for (int ni = 0; ni < 8; ni++) {
        int col = h * 64 + ni * 8 + (lane & 3) * 2;
        __nv_bfloat162 hx, lx;
        split2(oacc[ni][0] * inv0, oacc[ni][1] * inv0, hx, lx);
        *(__nv_bfloat162*)(outh + r0g * DMODEL + col) = hx;
        *(__nv_bfloat162*)(outl + r0g * DMODEL + col) = lx;
        split2(oacc[ni][2] * inv1, oacc[ni][3] * inv1, hx, lx);
        *(__nv_bfloat162*)(outh + (r0g + 8) * DMODEL + col) = hx;
        *(__nv_bfloat162*)(outl + (r0g + 8) * DMODEL + col) = lx;
    }
}

// -------- residual add + LayerNorm (in place on x; emits hi/lo) ----------
__global__ __launch_bounds__(256)
void add_ln_kernel(float* __restrict__ x, const float* __restrict__ o,
                   const float* __restrict__ sc, const float* __restrict__ bi,
                   __nv_bfloat16* __restrict__ xh, __nv_bfloat16* __restrict__ xl)
{
    int tok = blockIdx.x;
    int t = threadIdx.x;
    size_t base = (size_t)tok * DMODEL;
    float v0 = x[base + t]       + o[base + t];
    float v1 = x[base + t + 256] + o[base + t + 256];

    __shared__ float red[8];
    int warp = t >> 5, lane = t & 31;

    float s = v0 + v1;
#pragma unroll
    for (int off = 16; off; off >>= 1) s += __shfl_xor_sync(0xffffffffu, s, off);
    if (lane == 0) red[warp] = s;
    __syncthreads();
    float tot = 0.0f;
#pragma unroll
    for (int w = 0; w < 8; w++) tot += red[w];
    float mean = tot * (1.0f / 512.0f);

    float d0 = v0 - mean, d1 = v1 - mean;
    float q = d0 * d0 + d1 * d1;
#pragma unroll
    for (int off = 16; off; off >>= 1) q += __shfl_xor_sync(0xffffffffu, q, off);
    __syncthreads();
    if (lane == 0) red[warp] = q;
    __syncthreads();
    float tq = 0.0f;
#pragma unroll
    for (int w = 0; w < 8; w++) tq += red[w];
    float inv = rsqrtf(tq * (1.0f / 512.0f) + 1e-5f);

    float y0 = d0 * inv * sc[t]       + bi[t];
    float y1 = d1 * inv * sc[t + 256] + bi[t + 256];
    x[base + t]       = y0;
    x[base + t + 256] = y1;
    __nv_bfloat16 h0 = __float2bfloat16_rn(y0);
    __nv_bfloat16 h1 = __float2bfloat16_rn(y1);
    xh[base + t]       = h0;
    xh[base + t + 256] = h1;
    xl[base + t]       = __float2bfloat16_rn(y0 - __bfloat162float(h0));
    xl[base + t + 256] = __float2bfloat16_rn(y1 - __bfloat162float(h1));
}

// ------- gather init slots -> hi/lo bf16 [2560, 512] ----------------------
__global__ void gather_kernel(const float* __restrict__ x,
                              __nv_bfloat16* __restrict__ yh,
                              __nv_bfloat16* __restrict__ yl)
{
    int idx = blockIdx.x * blockDim.x + threadIdx.x;
    int d = idx & 511;
    int row = idx >> 9;
    int b = row / (PAIRS * 64);
    int r2 = row - b * (PAIRS * 64);
    int pair = r2 >> 6;
    int patch = r2 & 63;
    int s = pair * 128 + patch;
    float v = x[((size_t)(b * SEQ + s)) * DMODEL + d];
    __nv_bfloat16 hb = __float2bfloat16_rn(v);
    yh[idx] = hb;
    yl[idx] = __float2bfloat16_rn(v - __bfloat162float(hb));
}

// ---------------- depatchify to output --------------------------------
__global__ void depatch_kernel(const float* __restrict__ y, float* __restrict__ out)
{
    int idx = blockIdx.x * blockDim.x + threadIdx.x;
    int w = idx & 127;
    int h = (idx >> 7) & 127;
    int ch = (idx >> 14) & 1;
    int rest = idx >> 15;
    int pr = h >> 4, i = h & 15;
    int pc = w >> 4, j = w & 15;
    int row = rest * 64 + pr * 8 + pc;
    int fi = ch * 256 + i * 16 + j;
    out[idx] = y[(size_t)row * DMODEL + fi];
}

// ---------------- host launcher ----------------------------------------
extern "C" void kernel_launch(void* const* d_in, const int* in_sizes, int n_in,
                              void* d_out, int out_size)
{
    const float* initp     = (const float*)d_in[0];
    const float* endp      = (const float*)d_in[1];
    // d_in[2] = c_mask (bool) — unused by the reference forward
    const float* pre_W     = (const float*)d_in[3];
    const float* pre_b     = (const float*)d_in[4];
    const float* post_W    = (const float*)d_in[5];
    const float* post_b    = (const float*)d_in[6];
    const float* patch_pos = (const float*)d_in[7];
    const float* func_pos  = (const float*)d_in[8];
    const float* Wqkv      = (const float*)d_in[9];
    const float* bqkv      = (const float*)d_in[10];
    const float* Wo        = (const float*)d_in[11];
    const float* bo        = (const float*)d_in[12];
    const float* ln1s      = (const float*)d_in[13];
    const float* ln1b      = (const float*)d_in[14];
    const float* ln2s      = (const float*)d_in[15];
    const float* ln2b      = (const float*)d_in[16];
    const float* W1        = (const float*)d_in[17];
    const float* b1        = (const float*)d_in[18];
    const float* W2        = (const float*)d_in[19];
    const float* b2        = (const float*)d_in[20];
    float* out = (float*)d_out;

    float *px, *pqkv, *po;
    __nv_bfloat16 *wh, *wl, *inh, *inl, *xh, *xl, *ah, *al, *hh, *hl;
    cudaGetSymbolAddress((void**)&px,   g_x);
    cudaGetSymbolAddress((void**)&pqkv, g_qkv);
    cudaGetSymbolAddress((void**)&po,   g_o);
    cudaGetSymbolAddress((void**)&wh,   g_wh);
    cudaGetSymbolAddress((void**)&wl,   g_wl);
    cudaGetSymbolAddress((void**)&inh,  g_inh);
    cudaGetSymbolAddress((void**)&inl,  g_inl);
    cudaGetSymbolAddress((void**)&xh,   g_xh);
    cudaGetSymbolAddress((void**)&xl,   g_xl);
    cudaGetSymbolAddress((void**)&ah,   g_ah);
    cudaGetSymbolAddress((void**)&al,   g_al);
    cudaGetSymbolAddress((void**)&hh,   g_hh);
    cudaGetSymbolAddress((void**)&hl,   g_hl);

    static bool attr_set = false;
    if (!attr_set) {
        cudaFuncSetAttribute(gemm_bf, cudaFuncAttributeMaxDynamicSharedMemorySize, GB_SMEM);
        attr_set = true;
    }

    const int TOKELEM = NTOK * DMODEL;

    // ---- weight hi/lo conversion ----
    {
        struct { const float* s; int off; int n; } wjobs[6] = {
            {pre_W,  W_PRE,  512*512},
            {Wqkv,   W_QKV,  6*1536*512},
            {Wo,     W_WO,   6*512*512},
            {W1,     W_W1,   6*2048*512},
            {W2,     W_W2,   6*512*2048},
            {post_W, W_POST, 512*512},
        };
        for (int i = 0; i < 6; i++) {
            int n4 = wjobs[i].n >> 2;
            cvt_w<<<(n4 + 255) / 256, 256>>>(wjobs[i].s, wh + wjobs[i].off, wl + wjobs[i].off, n4);
        }
    }

    // embed
    patchify_kernel<<<TOKELEM / 256, 256>>>(initp, endp, inh, inl);
    gemm_bf<<<dim3(DMODEL / 128, NTOK / 128), 256, GB_SMEM>>>(
        inh, inl, wh + W_PRE, wl + W_PRE, pre_b, px, nullptr, nullptr, 512, DMODEL, 0);
    add_pos_kernel<<<TOKELEM / 256, 256>>>(px, patch_pos, func_pos, xh, xl);

    for (int l = 0; l < NLAYER; l++) {
        const __nv_bfloat16* qh = wh + W_QKV + (size_t)l * 1536 * 512;
        const __nv_bfloat16* ql = wl + W_QKV + (size_t)l * 1536 * 512;
        const __nv_bfloat16* oh = wh + W_WO  + (size_t)l * 512 * 512;
        const __nv_bfloat16* ol = wl + W_WO  + (size_t)l * 512 * 512;
        const __nv_bfloat16* f1h = wh + W_W1 + (size_t)l * 2048 * 512;
        const __nv_bfloat16* f1l = wl + W_W1 + (size_t)l * 2048 * 512;
        const __nv_bfloat16* f2h = wh + W_W2 + (size_t)l * 512 * 2048;
        const __nv_bfloat16* f2l = wl + W_W2 + (size_t)l * 512 * 2048;
        const float* bqkv_l = bqkv + (size_t)l * 1536;
        const float* bo_l   = bo   + (size_t)l * DMODEL;
        const float* b1_l   = b1   + (size_t)l * DFFN;
        const float* b2_l   = b2   + (size_t)l * DMODEL;

        gemm_bf<<<dim3(1536 / 128, NTOK / 128), 256, GB_SMEM>>>(
            xh, xl, qh, ql, bqkv_l, pqkv, nullptr, nullptr, 512, 1536, 0);
        flash_mma<<<dim3(SEQ / 64, NHEAD, BSZ), 128>>>(pqkv, ah, al);
        gemm_bf<<<dim3(DMODEL / 128, NTOK / 128), 256, GB_SMEM>>>(
            ah, al, oh, ol, bo_l, po, nullptr, nullptr, 512, DMODEL, 0);
        add_ln_kernel<<<NTOK, 256>>>(px, po, ln1s + (size_t)l * DMODEL,
                                     ln1b + (size_t)l * DMODEL, xh, xl);
        gemm_bf<<<dim3(DFFN / 128, NTOK / 128), 256, GB_SMEM>>>(
            xh, xl, f1h, f1l, b1_l, nullptr, hh, hl, 512, DFFN, 2);
        gemm_bf<<<dim3(DMODEL / 128, NTOK / 128), 256, GB_SMEM>>>(
            hh, hl, f2h, f2l, b2_l, po, nullptr, nullptr, 2048, DMODEL, 0);
        add_ln_kernel<<<NTOK, 256>>>(px, po, ln2s + (size_t)l * DMODEL,
                                     ln2b + (size_t)l * DMODEL, xh, xl);
    }

    // output head
    gather_kernel<<<(NSEL * DMODEL) / 256, 256>>>(px, inh, inl);
    gemm_bf<<<dim3(DMODEL / 128, NSEL / 128), 256, GB_SMEM>>>(
        inh, inl, wh + W_POST, wl + W_POST, post_b, po, nullptr, nullptr, 512, DMODEL, 0);
    depatch_kernel<<<(BSZ * PAIRS * CCH * HWDIM * HWDIM) / 256, 256>>>(po, out);
}

// round 14
// speedup vs baseline: 2.8584x; 1.3680x over previous
#include <cuda_runtime.h>
#include <cuda_bf16.h>
#include <math.h>
#include <stdint.h>

// ---------------- problem constants ----------------
#define BSZ     8
#define PAIRS   5
#define CCH     2
#define PGRID   8          // P
#define RRES    16         // R
#define HWDIM   128        // P*R
#define SEQ     640        // PAIRS*2*P*P
#define DMODEL  512
#define NHEAD   8
#define DHEAD   64
#define DFFN    2048
#define NLAYER  6
#define NTOK    (BSZ*SEQ)  // 5120
#define NSEL    (BSZ*PAIRS*PGRID*PGRID)  // 2560

// ---------------- weight hi/lo buffer offsets ----------------
#define W_PRE   0
#define W_QKV   (W_PRE  + 512*512)
#define W_WO    (W_QKV  + 6*1536*512)
#define W_W1    (W_WO   + 6*512*512)
#define W_W2    (W_W1   + 6*2048*512)
#define W_POST  (W_W2   + 6*512*2048)
#define W_TOT   (W_POST + 512*512)

// ---------------- scratch (device globals; no allocation allowed) ----------
__device__ float g_x  [NTOK*DMODEL];          // token stream f (fp32, residual)
__device__ float g_qkv[NTOK*3*DMODEL];        // qkv fp32 (flash input)
__device__ float g_o  [NTOK*DMODEL];          // gemm fp32 output (Wo / W2 / post)
__device__ __nv_bfloat16 g_wh[W_TOT], g_wl[W_TOT];            // weights hi/lo
__device__ __nv_bfloat16 g_inh[NTOK*DMODEL], g_inl[NTOK*DMODEL];  // patchify / gather out
__device__ __nv_bfloat16 g_xh [NTOK*DMODEL], g_xl [NTOK*DMODEL];  // x hi/lo
__device__ __nv_bfloat16 g_ah [NTOK*DMODEL], g_al [NTOK*DMODEL];  // attention out hi/lo
__device__ __nv_bfloat16 g_hh [NTOK*DFFN],   g_hl [NTOK*DFFN];    // FF hidden hi/lo

// ================= helpers =================
__device__ __forceinline__ uint32_t smem_u32(const void* p) {
    uint32_t a;
    asm("{ .reg .u64 t; cvta.to.shared.u64 t, %1; cvt.u32.u64 %0, t; }" : "=r"(a) : "l"(p));
    return a;
}

__device__ __forceinline__ void split2(float a, float b,
                                       __nv_bfloat162& h, __nv_bfloat162& l)
{
    h = __floats2bfloat162_rn(a, b);
    l = __floats2bfloat162_rn(a - __bfloat162float(h.x), b - __bfloat162float(h.y));
}

#define LDM_X4(r, addr) \
    asm volatile("ldmatrix.sync.aligned.m8n8.x4.shared.b16 {%0,%1,%2,%3}, [%4];" \
        : "=r"((r)[0]), "=r"((r)[1]), "=r"((r)[2]), "=r"((r)[3]) : "r"(addr))

#define LDM_X4_T(r, addr) \
    asm volatile("ldmatrix.sync.aligned.m8n8.x4.trans.shared.b16 {%0,%1,%2,%3}, [%4];" \
        : "=r"((r)[0]), "=r"((r)[1]), "=r"((r)[2]), "=r"((r)[3]) : "r"(addr))

#define MMA16816(c, a, b) \
    asm volatile("mma.sync.aligned.m16n8k16.row.col.f32.bf16.bf16.f32 " \
        "{%0,%1,%2,%3}, {%4,%5,%6,%7}, {%8,%9}, {%0,%1,%2,%3};" \
        : "+f"((c)[0]), "+f"((c)[1]), "+f"((c)[2]), "+f"((c)[3]) \
        : "r"((a)[0]), "r"((a)[1]), "r"((a)[2]), "r"((a)[3]), "r"((b)[0]), "r"((b)[1]))

#define CP16(saddr, gptr) \
    asm volatile("cp.async.cg.shared.global [%0], [%1], 16;" :: "r"(saddr), "l"(gptr) : "memory")
#define CP_COMMIT() asm volatile("cp.async.commit_group;" ::: "memory")

// ---------------- weight fp32 -> bf16 hi/lo converter ----------------
__global__ void cvt_w(const float* __restrict__ src, __nv_bfloat16* __restrict__ dh,
                      __nv_bfloat16* __restrict__ dl, int n4)
{
    int i = blockIdx.x * 256 + threadIdx.x;
    if (i >= n4) return;
    float4 v = ((const float4*)src)[i];
    __nv_bfloat162 h0, l0, h1, l1;
    split2(v.x, v.y, h0, l0);
    split2(v.z, v.w, h1, l1);
    *(__nv_bfloat162*)(dh + 4 * (size_t)i)     = h0;
    *(__nv_bfloat162*)(dh + 4 * (size_t)i + 2) = h1;
    *(__nv_bfloat162*)(dl + 4 * (size_t)i)     = l0;
    *(__nv_bfloat162*)(dl + 4 * (size_t)i + 2) = l1;
}

// ---------------- patchify: (init,end) -> hi/lo bf16 [5120, 512] -----------
__global__ void patchify_kernel(const float* __restrict__ initp,
                                const float* __restrict__ endp,
                                __nv_bfloat16* __restrict__ Xh,
                                __nv_bfloat16* __restrict__ Xl)
{
    int idx = blockIdx.x * blockDim.x + threadIdx.x;
    int fi = idx & 511;
    int n  = idx >> 9;
    int b  = n / SEQ;
    int s  = n - b * SEQ;
    int fn = s >> 6;
    int patch = s & 63;
    int pair = fn >> 1, io = fn & 1;
    int pr = patch >> 3, pc = patch & 7;
    int ch = fi >> 8;
    int rem = fi & 255;
    int i = rem >> 4, j = rem & 15;
    const float* src = io ? endp : initp;
    int h = pr * RRES + i, w = pc * RRES + j;
    float v = src[((((size_t)b * PAIRS + pair) * CCH + ch) * HWDIM + h) * HWDIM + w];
    __nv_bfloat16 hb = __float2bfloat16_rn(v);
    Xh[idx] = hb;
    Xl[idx] = __float2bfloat16_rn(v - __bfloat162float(hb));
}

// ---------------- positional add (updates fp32 x, emits hi/lo) -------------
__global__ void add_pos_kernel(float* __restrict__ x,
                               const float* __restrict__ patch_pos,
                               const float* __restrict__ func_pos,
                               __nv_bfloat16* __restrict__ xh,
                               __nv_bfloat16* __restrict__ xl)
{
    int idx = blockIdx.x * blockDim.x + threadIdx.x;
    int d = idx & 511;
    int n = idx >> 9;
    int s = n % SEQ;
    int fn = s >> 6;
    int patch = s & 63;
    float v = x[idx] + patch_pos[patch * DMODEL + d] + func_pos[fn * DMODEL + d];
    x[idx] = v;
    __nv_bfloat16 hb = __float2bfloat16_rn(v);
    xh[idx] = hb;
    xl[idx] = __float2bfloat16_rn(v - __bfloat162float(hb));
}

// =============== bf16 hi/lo MMA GEMM: C = A[N,K] @ W[J,K]^T + bias ========
// Block tile 128x64, 128 threads / 4 warps (2x2), warp tile 64x32, K-chunk 32.
// 3 MMA passes: AhWh + AhWl + AlWh. cp.async 2-stage double buffer.
// 60KB smem + ~160 regs -> 3 CTAs/SM (occupancy to hide syncs).
#define GS     40                       // padded smem stride (bf16)
#define ATB    (128 * GS * 2)           // 10240 B per A tile
#define WTB    (64 * GS * 2)            // 5120 B per W tile
#define STAGE  (2 * ATB + 2 * WTB)      // 30720 B
#define GB_SMEM (2 * STAGE)             // 61440 B

__global__ __launch_bounds__(128, 1)
void gemm_bf(const __nv_bfloat16* __restrict__ Ah, const __nv_bfloat16* __restrict__ Al,
             const __nv_bfloat16* __restrict__ Wh, const __nv_bfloat16* __restrict__ Wl,
             const float* __restrict__ bias,
             float* __restrict__ Cf,
             __nv_bfloat16* __restrict__ Ch, __nv_bfloat16* __restrict__ Cl,
             int K, int J, int mode)
{
    extern __shared__ char smem[];
    const uint32_t sbase = smem_u32(smem);
    const int t = threadIdx.x;
    const int lane = t & 31, wid = t >> 5;
    const int wr = wid >> 1, wc = wid & 1;          // warp grid 2 x 2
    const int n0 = blockIdx.y * 128, j0 = blockIdx.x * 64;

    float acc[4][4][4];
#pragma unroll
    for (int mi = 0; mi < 4; mi++)
#pragma unroll
        for (int ni = 0; ni < 4; ni++)
#pragma unroll
            for (int e = 0; e < 4; e++) acc[mi][ni][e] = 0.0f;

    // ldmatrix lane offsets (bytes)
    const int aoff = ((wr * 64 + (lane & 15)) * GS + ((lane >> 4) << 3)) * 2;
    const int boff = ((wc * 32 + (lane & 7) + ((lane >> 4) << 3)) * GS
                      + (((lane >> 3) & 1) << 3)) * 2;

    const int NC = K >> 5;

    auto issue = [&](int c) {
        uint32_t st = sbase + (uint32_t)(c & 1) * STAGE;
        int kc = c << 5;
#pragma unroll
        for (int u = 0; u < 4; u++) {               // A: 512 segs of 16B
            int s = u * 128 + t;
            int row = s >> 2, seg = s & 3;
            size_t g = (size_t)(n0 + row) * K + kc + seg * 8;
            uint32_t sa = st + (uint32_t)(row * 80 + seg * 16);
            CP16(sa,       Ah + g);
            CP16(sa + ATB, Al + g);
        }
#pragma unroll
        for (int u = 0; u < 2; u++) {               // W: 256 segs of 16B
            int s = u * 128 + t;
            int row = s >> 2, seg = s & 3;
            size_t g = (size_t)(j0 + row) * K + kc + seg * 8;
            uint32_t sw = st + 2 * ATB + (uint32_t)(row * 80 + seg * 16);
            CP16(sw,       Wh + g);
            CP16(sw + WTB, Wl + g);
        }
        CP_COMMIT();
    };

    issue(0);
    for (int c = 0; c < NC; c++) {
        if (c + 1 < NC) {
            issue(c + 1);
            asm volatile("cp.async.wait_group 1;" ::: "memory");
        } else {
            asm volatile("cp.async.wait_group 0;" ::: "memory");
        }
        __syncthreads();

        const uint32_t sb = sbase + (uint32_t)(c & 1) * STAGE;
        const uint32_t uAh = sb, uAl = sb + ATB;
        const uint32_t uWh = sb + 2 * ATB, uWl = sb + 2 * ATB + WTB;

#pragma unroll
        for (int ks = 0; ks < 32; ks += 16) {
            uint32_t Ahf[4][4], Alf[4][4], Bhf[4][2], Blf[4][2];
#pragma unroll
            for (int mi = 0; mi < 4; mi++) {
                int d = (mi * 16 * GS + ks) * 2;
                LDM_X4(Ahf[mi], uAh + aoff + d);
                LDM_X4(Alf[mi], uAl + aoff + d);
            }
#pragma unroll
            for (int pi = 0; pi < 2; pi++) {
                int d = (pi * 16 * GS + ks) * 2;
                uint32_t r[4];
                LDM_X4(r, uWh + boff + d);
                Bhf[2*pi][0] = r[0]; Bhf[2*pi][1] = r[1];
                Bhf[2*pi+1][0] = r[2]; Bhf[2*pi+1][1] = r[3];
                LDM_X4(r, uWl + boff + d);
                Blf[2*pi][0] = r[0]; Blf[2*pi][1] = r[1];
                Blf[2*pi+1][0] = r[2]; Blf[2*pi+1][1] = r[3];
            }
#pragma unroll
            for (int mi = 0; mi < 4; mi++)
#pragma unroll
                for (int ni = 0; ni < 4; ni++) {
                    MMA16816(acc[mi][ni], Ahf[mi], Bhf[ni]);
                    MMA16816(acc[mi][ni], Ahf[mi], Blf[ni]);
                    MMA16816(acc[mi][ni], Alf[mi], Bhf[ni]);
                }
        }
        __syncthreads();
    }

#pragma unroll
    for (int mi = 0; mi < 4; mi++) {
        int r0 = n0 + wr * 64 + mi * 16 + (lane >> 2);
#pragma unroll
        for (int ni = 0; ni < 4; ni++) {
            int col = j0 + wc * 32 + ni * 8 + (lane & 3) * 2;
            float b0v = bias[col], b1v = bias[col + 1];
            float v0 = acc[mi][ni][0] + b0v;
            float v1 = acc[mi][ni][1] + b1v;
            float v2 = acc[mi][ni][2] + b0v;
            float v3 = acc[mi][ni][3] + b1v;
            if (mode == 2) {
                v0 = 0.5f * v0 * (1.0f + erff(v0 * 0.70710678118654752f));
                v1 = 0.5f * v1 * (1.0f + erff(v1 * 0.70710678118654752f));
                v2 = 0.5f * v2 * (1.0f + erff(v2 * 0.70710678118654752f));
                v3 = 0.5f * v3 * (1.0f + erff(v3 * 0.70710678118654752f));
                __nv_bfloat162 h01, l01, h23, l23;
                split2(v0, v1, h01, l01);
                split2(v2, v3, h23, l23);
                *(__nv_bfloat162*)(Ch + (size_t)r0 * J + col)       = h01;
                *(__nv_bfloat162*)(Cl + (size_t)r0 * J + col)       = l01;
                *(__nv_bfloat162*)(Ch + (size_t)(r0 + 8) * J + col) = h23;
                *(__nv_bfloat162*)(Cl + (size_t)(r0 + 8) * J + col) = l23;
            } else {
                *(float2*)(Cf + (size_t)r0 * J + col)       = make_float2(v0, v1);
                *(float2*)(Cf + (size_t)(r0 + 8) * J + col) = make_float2(v2, v3);
            }
        }
    }
}

// =============== MMA flash attention, block-causal (64-token blocks) ======
#define FS 72   // smem stride (bf16 elems) for 64-wide tiles

__global__ __launch_bounds__(128)
void flash_mma(const float* __restrict__ qkv,
               __nv_bfloat16* __restrict__ outh, __nv_bfloat16* __restrict__ outl)
{
    __shared__ __nv_bfloat16 Ksh[64 * FS], Ksl[64 * FS];
    __shared__ __nv_bfloat16 Vsh[64 * FS], Vsl[64 * FS];

    const int qb = blockIdx.x, h = blockIdx.y, b = blockIdx.z;
    const int t = threadIdx.x, lane = t & 31, w = t >> 5;

    // ---- stage Q (x0.125) into Ksh/Ksl, then grab register fragments ----
    {
        int row = t >> 1, half = (t & 1) * 32;
        const float* qrow = qkv + ((size_t)(b * SEQ + qb * 64 + row)) * 1536 + h * 64 + half;
#pragma unroll
        for (int u = 0; u < 8; u++) {
            float4 v = *(const float4*)(qrow + u * 4);
            __nv_bfloat162 h0, l0, h1, l1;
            split2(v.x * 0.125f, v.y * 0.125f, h0, l0);
            split2(v.z * 0.125f, v.w * 0.125f, h1, l1);
            int o = row * FS + half + u * 4;
            *(__nv_bfloat162*)(Ksh + o)     = h0;
            *(__nv_bfloat162*)(Ksh + o + 2) = h1;
            *(__nv_bfloat162*)(Ksl + o)     = l0;
            *(__nv_bfloat162*)(Ksl + o + 2) = l1;
        }
    }
    __syncthreads();

    const uint32_t uKh = smem_u32(Ksh), uKl = smem_u32(Ksl);
    const uint32_t uVh = smem_u32(Vsh), uVl = smem_u32(Vsl);

    uint32_t qh_f[4][4], ql_f[4][4];
    {
        int ro = (w * 16 + (lane & 15)) * FS + ((lane >> 4) << 3);
#pragma unroll
        for (int ks = 0; ks < 4; ks++) {
            LDM_X4(qh_f[ks], uKh + (ro + ks * 16) * 2);
            LDM_X4(ql_f[ks], uKl + (ro + ks * 16) * 2);
        }
    }

    float oacc[8][4];
#pragma unroll
    for (int ni = 0; ni < 8; ni++)
#pragma unroll
        for (int e = 0; e < 4; e++) oacc[ni][e] = 0.0f;
    float m0 = -INFINITY, m1 = -INFINITY, l0s = 0.0f, l1s = 0.0f;

    const int krowp = (lane & 7) + ((lane >> 4) << 3);
    const int kcolp = ((lane >> 3) & 1) << 3;
    const int vro = (lane & 15);
    const int vco = ((lane >> 4) << 3);

    for (int kb = 0; kb <= qb; kb++) {
        __syncthreads();
        {
            int row = t & 63;
            const float* src = qkv + ((size_t)(b * SEQ + kb * 64 + row)) * 1536
                               + 512 + ((t >> 6) << 9) + h * 64;
            __nv_bfloat16* dh = (t < 64) ? Ksh : Vsh;
            __nv_bfloat16* dl = (t < 64) ? Ksl : Vsl;
#pragma unroll
            for (int u = 0; u < 16; u++) {
                float4 v = *(const float4*)(src + u * 4);
                __nv_bfloat162 h0, e0, h1, e1;
                split2(v.x, v.y, h0, e0);
                split2(v.z, v.w, h1, e1);
                int o = row * FS + u * 4;
                *(__nv_bfloat162*)(dh + o)     = h0;
                *(__nv_bfloat162*)(dh + o + 2) = h1;
                *(__nv_bfloat162*)(dl + o)     = e0;
                *(__nv_bfloat162*)(dl + o + 2) = e1;
            }
        }
        __syncthreads();

        // ---- S = Q K^T ----
        float sacc[8][4];
#pragma unroll
        for (int ni = 0; ni < 8; ni++)
#pragma unroll
            for (int e = 0; e < 4; e++) sacc[ni][e] = 0.0f;

#pragma unroll
        for (int ks = 0; ks < 4; ks++) {
#pragma unroll
            for (int ni2 = 0; ni2 < 4; ni2++) {
                int off = ((ni2 * 16 + krowp) * FS + ks * 16 + kcolp) * 2;
                uint32_t bh[4], bl[4];
                LDM_X4(bh, uKh + off);
                LDM_X4(bl, uKl + off);
                uint32_t b0h[2] = {bh[0], bh[1]}, b1h[2] = {bh[2], bh[3]};
                uint32_t b0l[2] = {bl[0], bl[1]}, b1l[2] = {bl[2], bl[3]};
                MMA16816(sacc[ni2*2],   qh_f[ks], b0h);
                MMA16816(sacc[ni2*2],   qh_f[ks], b0l);
                MMA16816(sacc[ni2*2],   ql_f[ks], b0h);
                MMA16816(sacc[ni2*2+1], qh_f[ks], b1h);
                MMA16816(sacc[ni2*2+1], qh_f[ks], b1l);
                MMA16816(sacc[ni2*2+1], ql_f[ks], b1h);
            }
        }

        // ---- online softmax ----
        float mx0 = -INFINITY, mx1 = -INFINITY;
#pragma unroll
        for (int ni = 0; ni < 8; ni++) {
            mx0 = fmaxf(mx0, fmaxf(sacc[ni][0], sacc[ni][1]));
            mx1 = fmaxf(mx1, fmaxf(sacc[ni][2], sacc[ni][3]));
        }
        mx0 = fmaxf(mx0, __shfl_xor_sync(0xffffffffu, mx0, 1));
        mx0 = fmaxf(mx0, __shfl_xor_sync(0xffffffffu, mx0, 2));
        mx1 = fmaxf(mx1, __shfl_xor_sync(0xffffffffu, mx1, 1));
        mx1 = fmaxf(mx1, __shfl_xor_sync(0xffffffffu, mx1, 2));

        float mn0 = fmaxf(m0, mx0), mn1 = fmaxf(m1, mx1);
        float a0 = __expf(m0 - mn0), a1 = __expf(m1 - mn1);
        float s0 = 0.0f, s1 = 0.0f;
#pragma unroll
        for (int ni = 0; ni < 8; ni++) {
            sacc[ni][0] = __expf(sacc[ni][0] - mn0);
            sacc[ni][1] = __expf(sacc[ni][1] - mn0);
            sacc[ni][2] = __expf(sacc[ni][2] - mn1);
            sacc[ni][3] = __expf(sacc[ni][3] - mn1);
            s0 += sacc[ni][0] + sacc[ni][1];
            s1 += sacc[ni][2] + sacc[ni][3];
        }
        s0 += __shfl_xor_sync(0xffffffffu, s0, 1);
        s0 += __shfl_xor_sync(0xffffffffu, s0, 2);
        s1 += __shfl_xor_sync(0xffffffffu, s1, 1);
        s1 += __shfl_xor_sync(0xffffffffu, s1, 2);
        l0s = l0s * a0 + s0;
        l1s = l1s * a1 + s1;
        m0 = mn0; m1 = mn1;
#pragma unroll
        for (int ni = 0; ni < 8; ni++) {
            oacc[ni][0] *= a0; oacc[ni][1] *= a0;
            oacc[ni][2] *= a1; oacc[ni][3] *= a1;
        }

        // ---- O += P V ----
#pragma unroll
        for (int ksv = 0; ksv < 4; ksv++) {
            uint32_t ph[4], pl[4];
            {
                __nv_bfloat162 hx, lx;
                split2(sacc[2*ksv][0],   sacc[2*ksv][1],   hx, lx);
                ph[0] = *(uint32_t*)&hx; pl[0] = *(uint32_t*)&lx;
                split2(sacc[2*ksv][2],   sacc[2*ksv][3],   hx, lx);
                ph[1] = *(uint32_t*)&hx; pl[1] = *(uint32_t*)&lx;
                split2(sacc[2*ksv+1][0], sacc[2*ksv+1][1], hx, lx);
                ph[2] = *(uint32_t*)&hx; pl[2] = *(uint32_t*)&lx;
                split2(sacc[2*ksv+1][2], sacc[2*ksv+1][3], hx, lx);
                ph[3] = *(uint32_t*)&hx; pl[3] = *(uint32_t*)&lx;
            }
#pragma unroll
            for (int db = 0; db < 4; db++) {
                int off = ((ksv * 16 + vro) * FS + db * 16 + vco) * 2;
                uint32_t vh4[4], vl4[4];
                LDM_X4_T(vh4, uVh + off);
                LDM_X4_T(vl4, uVl + off);
                uint32_t b0h[2] = {vh4[0], vh4[1]}, b1h[2] = {vh4[2], vh4[3]};
                uint32_t b0l[2] = {vl4[0], vl4[1]}, b1l[2] = {vl4[2], vl4[3]};
                MMA16816(oacc[db*2],   ph, b0h);
                MMA16816(oacc[db*2],   ph, b0l);
                MMA16816(oacc[db*2],   pl, b0h);
                MMA16816(oacc[db*2+1], ph, b1h);
                MMA16816(oacc[db*2+1], ph, b1l);
                MMA16816(oacc[db*2+1], pl, b1h);
            }
        }
    }

    // ---- epilogue ----
    float inv0 = 1.0f / l0s, inv1 = 1.0f / l1s;
    size_t r0g = (size_t)(b * SEQ + qb * 64 + w * 16 + (lane >> 2));
#pragma unroll
    for (int ni = 0; ni < 8; ni++) {
        int col = h * 64 + ni * 8 + (lane & 3) * 2;
        __nv_bfloat162 hx, lx;
        split2(oacc[ni][0] * inv0, oacc[ni][1] * inv0, hx, lx);
        *(__nv_bfloat162*)(outh + r0g * DMODEL + col) = hx;
        *(__nv_bfloat162*)(outl + r0g * DMODEL + col) = lx;
        split2(oacc[ni][2] * inv1, oacc[ni][3] * inv1, hx, lx);
        *(__nv_bfloat162*)(outh + (r0g + 8) * DMODEL + col) = hx;
        *(__nv_bfloat162*)(outl + (r0g + 8) * DMODEL + col) = lx;
    }
}

// -------- residual add + LayerNorm (in place on x; emits hi/lo) ----------
__global__ __launch_bounds__(256)
void add_ln_kernel(float* __restrict__ x, const float* __restrict__ o,
                   const float* __restrict__ sc, const float* __restrict__ bi,
                   __nv_bfloat16* __restrict__ xh, __nv_bfloat16* __restrict__ xl)
{
    int tok = blockIdx.x;
    int t = threadIdx.x;
    size_t base = (size_t)tok * DMODEL;
    float v0 = x[base + t]       + o[base + t];
    float v1 = x[base + t + 256] + o[base + t + 256];

    __shared__ float red[8];
    int warp = t >> 5, lane = t & 31;

    float s = v0 + v1;
#pragma unroll
    for (int off = 16; off; off >>= 1) s += __shfl_xor_sync(0xffffffffu, s, off);
    if (lane == 0) red[warp] = s;
    __syncthreads();
    float tot = 0.0f;
#pragma unroll
    for (int w = 0; w < 8; w++) tot += red[w];
    float mean = tot * (1.0f / 512.0f);

    float d0 = v0 - mean, d1 = v1 - mean;
    float q = d0 * d0 + d1 * d1;
#pragma unroll
    for (int off = 16; off; off >>= 1) q += __shfl_xor_sync(0xffffffffu, q, off);
    __syncthreads();
    if (lane == 0) red[warp] = q;
    __syncthreads();
    float tq = 0.0f;
#pragma unroll
    for (int w = 0; w < 8; w++) tq += red[w];
    float inv = rsqrtf(tq * (1.0f / 512.0f) + 1e-5f);

    float y0 = d0 * inv * sc[t]       + bi[t];
    float y1 = d1 * inv * sc[t + 256] + bi[t + 256];
    x[base + t]       = y0;
    x[base + t + 256] = y1;
    __nv_bfloat16 h0 = __float2bfloat16_rn(y0);
    __nv_bfloat16 h1 = __float2bfloat16_rn(y1);
    xh[base + t]       = h0;
    xh[base + t + 256] = h1;
    xl[base + t]       = __float2bfloat16_rn(y0 - __bfloat162float(h0));
    xl[base + t + 256] = __float2bfloat16_rn(y1 - __bfloat162float(h1));
}

// ------- gather init slots -> hi/lo bf16 [2560, 512] ----------------------
__global__ void gather_kernel(const float* __restrict__ x,
                              __nv_bfloat16* __restrict__ yh,
                              __nv_bfloat16* __restrict__ yl)
{
    int idx = blockIdx.x * blockDim.x + threadIdx.x;
    int d = idx & 511;
    int row = idx >> 9;
    int b = row / (PAIRS * 64);
    int r2 = row - b * (PAIRS * 64);
    int pair = r2 >> 6;
    int patch = r2 & 63;
    int s = pair * 128 + patch;
    float v = x[((size_t)(b * SEQ + s)) * DMODEL + d];
    __nv_bfloat16 hb = __float2bfloat16_rn(v);
    yh[idx] = hb;
    yl[idx] = __float2bfloat16_rn(v - __bfloat162float(hb));
}

// ---------------- depatchify to output --------------------------------
__global__ void depatch_kernel(const float* __restrict__ y, float* __restrict__ out)
{
    int idx = blockIdx.x * blockDim.x + threadIdx.x;
    int w = idx & 127;
    int h = (idx >> 7) & 127;
    int ch = (idx >> 14) & 1;
    int rest = idx >> 15;
    int pr = h >> 4, i = h & 15;
    int pc = w >> 4, j = w & 15;
    int row = rest * 64 + pr * 8 + pc;
    int fi = ch * 256 + i * 16 + j;
    out[idx] = y[(size_t)row * DMODEL + fi];
}

// ---------------- host launcher ----------------------------------------
extern "C" void kernel_launch(void* const* d_in, const int* in_sizes, int n_in,
                              void* d_out, int out_size)
{
    const float* initp     = (const float*)d_in[0];
    const float* endp      = (const float*)d_in[1];
    // d_in[2] = c_mask (bool) — unused by the reference forward
    const float* pre_W     = (const float*)d_in[3];
    const float* pre_b     = (const float*)d_in[4];
    const float* post_W    = (const float*)d_in[5];
    const float* post_b    = (const float*)d_in[6];
    const float* patch_pos = (const float*)d_in[7];
    const float* func_pos  = (const float*)d_in[8];
    const float* Wqkv      = (const float*)d_in[9];
    const float* bqkv      = (const float*)d_in[10];
    const float* Wo        = (const float*)d_in[11];
    const float* bo        = (const float*)d_in[12];
    const float* ln1s      = (const float*)d_in[13];
    const float* ln1b      = (const float*)d_in[14];
    const float* ln2s      = (const float*)d_in[15];
    const float* ln2b      = (const float*)d_in[16];
    const float* W1        = (const float*)d_in[17];
    const float* b1        = (const float*)d_in[18];
    const float* W2        = (const float*)d_in[19];
    const float* b2        = (const float*)d_in[20];
    float* out = (float*)d_out;

    float *px, *pqkv, *po;
    __nv_bfloat16 *wh, *wl, *inh, *inl, *xh, *xl, *ah, *al, *hh, *hl;
    cudaGetSymbolAddress((void**)&px,   g_x);
    cudaGetSymbolAddress((void**)&pqkv, g_qkv);
    cudaGetSymbolAddress((void**)&po,   g_o);
    cudaGetSymbolAddress((void**)&wh,   g_wh);
    cudaGetSymbolAddress((void**)&wl,   g_wl);
    cudaGetSymbolAddress((void**)&inh,  g_inh);
    cudaGetSymbolAddress((void**)&inl,  g_inl);
    cudaGetSymbolAddress((void**)&xh,   g_xh);
    cudaGetSymbolAddress((void**)&xl,   g_xl);
    cudaGetSymbolAddress((void**)&ah,   g_ah);
    cudaGetSymbolAddress((void**)&al,   g_al);
    cudaGetSymbolAddress((void**)&hh,   g_hh);
    cudaGetSymbolAddress((void**)&hl,   g_hl);

    static bool attr_set = false;
    if (!attr_set) {
        cudaFuncSetAttribute(gemm_bf, cudaFuncAttributeMaxDynamicSharedMemorySize, GB_SMEM);
        attr_set = true;
    }

    const int TOKELEM = NTOK * DMODEL;

    // ---- weight hi/lo conversion ----
    {
        struct { const float* s; int off; int n; } wjobs[6] = {
            {pre_W,  W_PRE,  512*512},
            {Wqkv,   W_QKV,  6*1536*512},
            {Wo,     W_WO,   6*512*512},
            {W1,     W_W1,   6*2048*512},
            {W2,     W_W2,   6*512*2048},
            {post_W, W_POST, 512*512},
        };
        for (int i = 0; i < 6; i++) {
            int n4 = wjobs[i].n >> 2;
            cvt_w<<<(n4 + 255) / 256, 256>>>(wjobs[i].s, wh + wjobs[i].off, wl + wjobs[i].off, n4);
        }
    }

    // embed
    patchify_kernel<<<TOKELEM / 256, 256>>>(initp, endp, inh, inl);
    gemm_bf<<<dim3(DMODEL / 64, NTOK / 128), 128, GB_SMEM>>>(
        inh, inl, wh + W_PRE, wl + W_PRE, pre_b, px, nullptr, nullptr, 512, DMODEL, 0);
    add_pos_kernel<<<TOKELEM / 256, 256>>>(px, patch_pos, func_pos, xh, xl);

    for (int l = 0; l < NLAYER; l++) {
        const __nv_bfloat16* qh = wh + W_QKV + (size_t)l * 1536 * 512;
        const __nv_bfloat16* ql = wl + W_QKV + (size_t)l * 1536 * 512;
        const __nv_bfloat16* oh = wh + W_WO  + (size_t)l * 512 * 512;
        const __nv_bfloat16* ol = wl + W_WO  + (size_t)l * 512 * 512;
        const __nv_bfloat16* f1h = wh + W_W1 + (size_t)l * 2048 * 512;
        const __nv_bfloat16* f1l = wl + W_W1 + (size_t)l * 2048 * 512;
        const __nv_bfloat16* f2h = wh + W_W2 + (size_t)l * 512 * 2048;
        const __nv_bfloat16* f2l = wl + W_W2 + (size_t)l * 512 * 2048;
        const float* bqkv_l = bqkv + (size_t)l * 1536;
        const float* bo_l   = bo   + (size_t)l * DMODEL;
        const float* b1_l   = b1   + (size_t)l * DFFN;
        const float* b2_l   = b2   + (size_t)l * DMODEL;

        gemm_bf<<<dim3(1536 / 64, NTOK / 128), 128, GB_SMEM>>>(
            xh, xl, qh, ql, bqkv_l, pqkv, nullptr, nullptr, 512, 1536, 0);
        flash_mma<<<dim3(SEQ / 64, NHEAD, BSZ), 128>>>(pqkv, ah, al);
        gemm_bf<<<dim3(DMODEL / 64, NTOK / 128), 128, GB_SMEM>>>(
            ah, al, oh, ol, bo_l, po, nullptr, nullptr, 512, DMODEL, 0);
        add_ln_kernel<<<NTOK, 256>>>(px, po, ln1s + (size_t)l * DMODEL,
                                     ln1b + (size_t)l * DMODEL, xh, xl);
        gemm_bf<<<dim3(DFFN / 64, NTOK / 128), 128, GB_SMEM>>>(
            xh, xl, f1h, f1l, b1_l, nullptr, hh, hl, 512, DFFN, 2);
        gemm_bf<<<dim3(DMODEL / 64, NTOK / 128), 128, GB_SMEM>>>(
            hh, hl, f2h, f2l, b2_l, po, nullptr, nullptr, 2048, DMODEL, 0);
        add_ln_kernel<<<NTOK, 256>>>(px, po, ln2s + (size_t)l * DMODEL,
                                     ln2b + (size_t)l * DMODEL, xh, xl);
    }

    // output head
    gather_kernel<<<(NSEL * DMODEL) / 256, 256>>>(px, inh, inl);
    gemm_bf<<<dim3(DMODEL / 64, NSEL / 128), 128, GB_SMEM>>>(
        inh, inl, wh + W_POST, wl + W_POST, post_b, po, nullptr, nullptr, 512, DMODEL, 0);
    depatch_kernel<<<(BSZ * PAIRS * CCH * HWDIM * HWDIM) / 256, 256>>>(po, out);
}

// round 16
// speedup vs baseline: 3.0778x; 1.0767x over previous
#include <cuda_runtime.h>
#include <cuda_bf16.h>
#include <math.h>
#include <stdint.h>

// ---------------- problem constants ----------------
#define BSZ     8
#define PAIRS   5
#define CCH     2
#define PGRID   8          // P
#define RRES    16         // R
#define HWDIM   128        // P*R
#define SEQ     640        // PAIRS*2*P*P
#define DMODEL  512
#define NHEAD   8
#define DHEAD   64
#define DFFN    2048
#define NLAYER  6
#define NTOK    (BSZ*SEQ)  // 5120
#define NSEL    (BSZ*PAIRS*PGRID*PGRID)  // 2560

// ---------------- weight hi/lo buffer offsets ----------------
#define W_PRE   0
#define W_QKV   (W_PRE  + 512*512)
#define W_WO    (W_QKV  + 6*1536*512)
#define W_W1    (W_WO   + 6*512*512)
#define W_W2    (W_W1   + 6*2048*512)
#define W_POST  (W_W2   + 6*512*2048)
#define W_TOT   (W_POST + 512*512)

// ---------------- scratch (device globals; no allocation allowed) ----------
__device__ float g_x  [NTOK*DMODEL];          // token stream f (fp32, residual)
__device__ float g_o  [NTOK*DMODEL];          // gemm fp32 output (Wo / W2 / post)
__device__ __nv_bfloat16 g_wh[W_TOT], g_wl[W_TOT];            // weights hi/lo
__device__ __nv_bfloat16 g_qh[NTOK*3*DMODEL], g_ql[NTOK*3*DMODEL]; // qkv hi/lo (Q pre-scaled)
__device__ __nv_bfloat16 g_inh[NTOK*DMODEL], g_inl[NTOK*DMODEL];  // patchify / gather out
__device__ __nv_bfloat16 g_xh [NTOK*DMODEL], g_xl [NTOK*DMODEL];  // x hi/lo
__device__ __nv_bfloat16 g_ah [NTOK*DMODEL], g_al [NTOK*DMODEL];  // attention out hi/lo
__device__ __nv_bfloat16 g_hh [NTOK*DFFN],   g_hl [NTOK*DFFN];    // FF hidden hi/lo

// ================= helpers =================
__device__ __forceinline__ uint32_t smem_u32(const void* p) {
    uint32_t a;
    asm("{ .reg .u64 t; cvta.to.shared.u64 t, %1; cvt.u32.u64 %0, t; }" : "=r"(a) : "l"(p));
    return a;
}

__device__ __forceinline__ void split2(float a, float b,
                                       __nv_bfloat162& h, __nv_bfloat162& l)
{
    h = __floats2bfloat162_rn(a, b);
    l = __floats2bfloat162_rn(a - __bfloat162float(h.x), b - __bfloat162float(h.y));
}

#define LDM_X4(r, addr) \
    asm volatile("ldmatrix.sync.aligned.m8n8.x4.shared.b16 {%0,%1,%2,%3}, [%4];" \
        : "=r"((r)[0]), "=r"((r)[1]), "=r"((r)[2]), "=r"((r)[3]) : "r"(addr))

#define LDM_X4_T(r, addr) \
    asm volatile("ldmatrix.sync.aligned.m8n8.x4.trans.shared.b16 {%0,%1,%2,%3}, [%4];" \
        : "=r"((r)[0]), "=r"((r)[1]), "=r"((r)[2]), "=r"((r)[3]) : "r"(addr))

#define MMA16816(c, a, b) \
    asm volatile("mma.sync.aligned.m16n8k16.row.col.f32.bf16.bf16.f32 " \
        "{%0,%1,%2,%3}, {%4,%5,%6,%7}, {%8,%9}, {%0,%1,%2,%3};" \
        : "+f"((c)[0]), "+f"((c)[1]), "+f"((c)[2]), "+f"((c)[3]) \
        : "r"((a)[0]), "r"((a)[1]), "r"((a)[2]), "r"((a)[3]), "r"((b)[0]), "r"((b)[1]))

#define CP16(saddr, gptr) \
    asm volatile("cp.async.cg.shared.global [%0], [%1], 16;" :: "r"(saddr), "l"(gptr) : "memory")
#define CP_COMMIT() asm volatile("cp.async.commit_group;" ::: "memory")

// ---------------- weight fp32 -> bf16 hi/lo converter ----------------
__global__ void cvt_w(const float* __restrict__ src, __nv_bfloat16* __restrict__ dh,
                      __nv_bfloat16* __restrict__ dl, int n4)
{
    int i = blockIdx.x * 256 + threadIdx.x;
    if (i >= n4) return;
    float4 v = ((const float4*)src)[i];
    __nv_bfloat162 h0, l0, h1, l1;
    split2(v.x, v.y, h0, l0);
    split2(v.z, v.w, h1, l1);
    *(__nv_bfloat162*)(dh + 4 * (size_t)i)     = h0;
    *(__nv_bfloat162*)(dh + 4 * (size_t)i + 2) = h1;
    *(__nv_bfloat162*)(dl + 4 * (size_t)i)     = l0;
    *(__nv_bfloat162*)(dl + 4 * (size_t)i + 2) = l1;
}

// ---------------- patchify: (init,end) -> hi/lo bf16 [5120, 512] -----------
__global__ void patchify_kernel(const float* __restrict__ initp,
                                const float* __restrict__ endp,
                                __nv_bfloat16* __restrict__ Xh,
                                __nv_bfloat16* __restrict__ Xl)
{
    int idx = blockIdx.x * blockDim.x + threadIdx.x;
    int fi = idx & 511;
    int n  = idx >> 9;
    int b  = n / SEQ;
    int s  = n - b * SEQ;
    int fn = s >> 6;
    int patch = s & 63;
    int pair = fn >> 1, io = fn & 1;
    int pr = patch >> 3, pc = patch & 7;
    int ch = fi >> 8;
    int rem = fi & 255;
    int i = rem >> 4, j = rem & 15;
    const float* src = io ? endp : initp;
    int h = pr * RRES + i, w = pc * RRES + j;
    float v = src[((((size_t)b * PAIRS + pair) * CCH + ch) * HWDIM + h) * HWDIM + w];
    __nv_bfloat16 hb = __float2bfloat16_rn(v);
    Xh[idx] = hb;
    Xl[idx] = __float2bfloat16_rn(v - __bfloat162float(hb));
}

// ---------------- positional add (updates fp32 x, emits hi/lo) -------------
__global__ void add_pos_kernel(float* __restrict__ x,
                               const float* __restrict__ patch_pos,
                               const float* __restrict__ func_pos,
                               __nv_bfloat16* __restrict__ xh,
                               __nv_bfloat16* __restrict__ xl)
{
    int idx = blockIdx.x * blockDim.x + threadIdx.x;
    int d = idx & 511;
    int n = idx >> 9;
    int s = n % SEQ;
    int fn = s >> 6;
    int patch = s & 63;
    float v = x[idx] + patch_pos[patch * DMODEL + d] + func_pos[fn * DMODEL + d];
    x[idx] = v;
    __nv_bfloat16 hb = __float2bfloat16_rn(v);
    xh[idx] = hb;
    xl[idx] = __float2bfloat16_rn(v - __bfloat162float(hb));
}

// =============== bf16 hi/lo MMA GEMM: C = A[N,K] @ W[J,K]^T + bias ========
// Block tile 128x64, 128 threads / 4 warps (2x2), warp tile 64x32, K-chunk 32.
// 3 MMA passes: AhWh + AhWl + AlWh. cp.async 2-stage, ONE sync per chunk
// (wait -> sync -> issue(c+1) -> compute).
// mode 0: fp32 out. mode 2: GELU + bf16 hi/lo out. mode 3: qkv bf16 hi/lo out
// (cols < 512 scaled by 0.125 = attention 1/sqrt(dh)).
#define GS     40                       // padded smem stride (bf16)
#define ATB    (128 * GS * 2)           // 10240 B per A tile
#define WTB    (64 * GS * 2)            // 5120 B per W tile
#define STAGE  (2 * ATB + 2 * WTB)      // 30720 B
#define GB_SMEM (2 * STAGE)             // 61440 B

__global__ __launch_bounds__(128, 1)
void gemm_bf(const __nv_bfloat16* __restrict__ Ah, const __nv_bfloat16* __restrict__ Al,
             const __nv_bfloat16* __restrict__ Wh, const __nv_bfloat16* __restrict__ Wl,
             const float* __restrict__ bias,
             float* __restrict__ Cf,
             __nv_bfloat16* __restrict__ Ch, __nv_bfloat16* __restrict__ Cl,
             int K, int J, int mode)
{
    extern __shared__ char smem[];
    const uint32_t sbase = smem_u32(smem);
    const int t = threadIdx.x;
    const int lane = t & 31, wid = t >> 5;
    const int wr = wid >> 1, wc = wid & 1;          // warp grid 2 x 2
    const int n0 = blockIdx.y * 128, j0 = blockIdx.x * 64;

    float acc[4][4][4];
#pragma unroll
    for (int mi = 0; mi < 4; mi++)
#pragma unroll
        for (int ni = 0; ni < 4; ni++)
#pragma unroll
            for (int e = 0; e < 4; e++) acc[mi][ni][e] = 0.0f;

    // ldmatrix lane offsets (bytes)
    const int aoff = ((wr * 64 + (lane & 15)) * GS + ((lane >> 4) << 3)) * 2;
    const int boff = ((wc * 32 + (lane & 7) + ((lane >> 4) << 3)) * GS
                      + (((lane >> 3) & 1) << 3)) * 2;

    const int NC = K >> 5;

    auto issue = [&](int c) {
        uint32_t st = sbase + (uint32_t)(c & 1) * STAGE;
        int kc = c << 5;
#pragma unroll
        for (int u = 0; u < 4; u++) {               // A: 512 segs of 16B
            int s = u * 128 + t;
            int row = s >> 2, seg = s & 3;
            size_t g = (size_t)(n0 + row) * K + kc + seg * 8;
            uint32_t sa = st + (uint32_t)(row * 80 + seg * 16);
            CP16(sa,       Ah + g);
            CP16(sa + ATB, Al + g);
        }
#pragma unroll
        for (int u = 0; u < 2; u++) {               // W: 256 segs of 16B
            int s = u * 128 + t;
            int row = s >> 2, seg = s & 3;
            size_t g = (size_t)(j0 + row) * K + kc + seg * 8;
            uint32_t sw = st + 2 * ATB + (uint32_t)(row * 80 + seg * 16);
            CP16(sw,       Wh + g);
            CP16(sw + WTB, Wl + g);
        }
        CP_COMMIT();
    };

    issue(0);
    for (int c = 0; c < NC; c++) {
        asm volatile("cp.async.wait_group 0;" ::: "memory");
        __syncthreads();           // buf c visible AND everyone done with buf c-1
        if (c + 1 < NC) issue(c + 1);

        const uint32_t sb = sbase + (uint32_t)(c & 1) * STAGE;
        const uint32_t uAh = sb, uAl = sb + ATB;
        const uint32_t uWh = sb + 2 * ATB, uWl = sb + 2 * ATB + WTB;

#pragma unroll
        for (int ks = 0; ks < 32; ks += 16) {
            uint32_t Ahf[4][4], Alf[4][4], Bhf[4][2], Blf[4][2];
#pragma unroll
            for (int mi = 0; mi < 4; mi++) {
                int d = (mi * 16 * GS + ks) * 2;
                LDM_X4(Ahf[mi], uAh + aoff + d);
                LDM_X4(Alf[mi], uAl + aoff + d);
            }
#pragma unroll
            for (int pi = 0; pi < 2; pi++) {
                int d = (pi * 16 * GS + ks) * 2;
                uint32_t r[4];
                LDM_X4(r, uWh + boff + d);
                Bhf[2*pi][0] = r[0]; Bhf[2*pi][1] = r[1];
                Bhf[2*pi+1][0] = r[2]; Bhf[2*pi+1][1] = r[3];
                LDM_X4(r, uWl + boff + d);
                Blf[2*pi][0] = r[0]; Blf[2*pi][1] = r[1];
                Blf[2*pi+1][0] = r[2]; Blf[2*pi+1][1] = r[3];
            }
#pragma unroll
            for (int mi = 0; mi < 4; mi++)
#pragma unroll
                for (int ni = 0; ni < 4; ni++) {
                    MMA16816(acc[mi][ni], Ahf[mi], Bhf[ni]);
                    MMA16816(acc[mi][ni], Ahf[mi], Blf[ni]);
                    MMA16816(acc[mi][ni], Alf[mi], Bhf[ni]);
                }
        }
    }

#pragma unroll
    for (int mi = 0; mi < 4; mi++) {
        int r0 = n0 + wr * 64 + mi * 16 + (lane >> 2);
#pragma unroll
        for (int ni = 0; ni < 4; ni++) {
            int col = j0 + wc * 32 + ni * 8 + (lane & 3) * 2;
            float b0v = bias[col], b1v = bias[col + 1];
            float v0 = acc[mi][ni][0] + b0v;
            float v1 = acc[mi][ni][1] + b1v;
            float v2 = acc[mi][ni][2] + b0v;
            float v3 = acc[mi][ni][3] + b1v;
            if (mode == 0) {
                *(float2*)(Cf + (size_t)r0 * J + col)       = make_float2(v0, v1);
                *(float2*)(Cf + (size_t)(r0 + 8) * J + col) = make_float2(v2, v3);
            } else {
                if (mode == 2) {
                    v0 = 0.5f * v0 * (1.0f + erff(v0 * 0.70710678118654752f));
                    v1 = 0.5f * v1 * (1.0f + erff(v1 * 0.70710678118654752f));
                    v2 = 0.5f * v2 * (1.0f + erff(v2 * 0.70710678118654752f));
                    v3 = 0.5f * v3 * (1.0f + erff(v3 * 0.70710678118654752f));
                } else {                       // mode 3: qkv, scale Q columns
                    float sc = (col < 512) ? 0.125f : 1.0f;
                    v0 *= sc; v1 *= sc; v2 *= sc; v3 *= sc;
                }
                __nv_bfloat162 h01, l01, h23, l23;
                split2(v0, v1, h01, l01);
                split2(v2, v3, h23, l23);
                *(__nv_bfloat162*)(Ch + (size_t)r0 * J + col)       = h01;
                *(__nv_bfloat162*)(Cl + (size_t)r0 * J + col)       = l01;
                *(__nv_bfloat162*)(Ch + (size_t)(r0 + 8) * J + col) = h23;
                *(__nv_bfloat162*)(Cl + (size_t)(r0 + 8) * J + col) = l23;
            }
        }
    }
}

// =============== MMA flash attention, block-causal (64-token blocks) ======
// Inputs: qkv bf16 hi/lo [b, s, 1536] (Q already scaled by 0.125).
// cp.async fills, double-buffered K/V stages, ONE sync per KV iteration.
#define FS   72                    // smem stride (bf16 elems)
#define FTB  (64 * FS * 2)         // 9216 B per tile
#define FKV_OFF (2 * FTB)          // after Q hi/lo
#define FSTG (4 * FTB)             // Khi,Klo,Vhi,Vlo per stage = 36864 B
#define FL_SMEM (2 * FTB + 2 * FSTG)   // 92160 B

__global__ __launch_bounds__(128)
void flash_mma(const __nv_bfloat16* __restrict__ qh, const __nv_bfloat16* __restrict__ ql,
               __nv_bfloat16* __restrict__ outh, __nv_bfloat16* __restrict__ outl)
{
    extern __shared__ char fsm[];
    const uint32_t sb = smem_u32(fsm);
    const int qb = blockIdx.x, h = blockIdx.y, b = blockIdx.z;
    const int t = threadIdx.x, lane = t & 31, w = t >> 5;

    const uint32_t uQh = sb, uQl = sb + FTB;

    // ---- Q tile cp.async (group 0) ----
    {
        size_t qbase = (size_t)(b * SEQ + qb * 64) * 1536 + h * 64;
#pragma unroll
        for (int u = 0; u < 4; u++) {
            int s = u * 128 + t;
            int row = s >> 3, seg = s & 7;
            uint32_t d = (uint32_t)(row * 144 + seg * 16);
            size_t g = qbase + (size_t)row * 1536 + seg * 8;
            CP16(uQh + d, qh + g);
            CP16(uQl + d, ql + g);
        }
        CP_COMMIT();
    }

    auto issue_kv = [&](int kb) {
        uint32_t st = sb + FKV_OFF + (uint32_t)(kb & 1) * FSTG;
        size_t kbase = (size_t)(b * SEQ + kb * 64) * 1536 + 512 + h * 64;
#pragma unroll
        for (int u = 0; u < 4; u++) {
            int s = u * 128 + t;
            int row = s >> 3, seg = s & 7;
            uint32_t d = (uint32_t)(row * 144 + seg * 16);
            size_t gk = kbase + (size_t)row * 1536 + seg * 8;
            CP16(st + d,           qh + gk);         // Khi
            CP16(st + FTB + d,     ql + gk);         // Klo
            CP16(st + 2*FTB + d,   qh + gk + 512);   // Vhi
            CP16(st + 3*FTB + d,   ql + gk + 512);   // Vlo
        }
        CP_COMMIT();
    };
    issue_kv(0);

    asm volatile("cp.async.wait_group 1;" ::: "memory");   // Q arrived
    __syncthreads();

    // ---- Q register fragments ----
    uint32_t qh_f[4][4], ql_f[4][4];
    {
        int ro = (w * 16 + (lane & 15)) * FS + ((lane >> 4) << 3);
#pragma unroll
        for (int ks = 0; ks < 4; ks++) {
            LDM_X4(qh_f[ks], uQh + (ro + ks * 16) * 2);
            LDM_X4(ql_f[ks], uQl + (ro + ks * 16) * 2);
        }
    }

    float oacc[8][4];
#pragma unroll
    for (int ni = 0; ni < 8; ni++)
#pragma unroll
        for (int e = 0; e < 4; e++) oacc[ni][e] = 0.0f;
    float m0 = -INFINITY, m1 = -INFINITY, l0s = 0.0f, l1s = 0.0f;

    const int krowp = (lane & 7) + ((lane >> 4) << 3);
    const int kcolp = ((lane >> 3) & 1) << 3;
    const int vro = (lane & 15);
    const int vco = ((lane >> 4) << 3);

    for (int kb = 0; kb <= qb; kb++) {
        asm volatile("cp.async.wait_group 0;" ::: "memory");
        __syncthreads();          // KV kb visible AND everyone done with kb-1
        if (kb < qb) issue_kv(kb + 1);

        const uint32_t uKh = sb + FKV_OFF + (uint32_t)(kb & 1) * FSTG;
        const uint32_t uKl = uKh + FTB, uVh = uKh + 2 * FTB, uVl = uKh + 3 * FTB;

        // ---- S = Q K^T ----
        float sacc[8][4];
#pragma unroll
        for (int ni = 0; ni < 8; ni++)
#pragma unroll
            for (int e = 0; e < 4; e++) sacc[ni][e] = 0.0f;

#pragma unroll
        for (int ks = 0; ks < 4; ks++) {
#pragma unroll
            for (int ni2 = 0; ni2 < 4; ni2++) {
                int off = ((ni2 * 16 + krowp) * FS + ks * 16 + kcolp) * 2;
                uint32_t bh[4], bl[4];
                LDM_X4(bh, uKh + off);
                LDM_X4(bl, uKl + off);
                uint32_t b0h[2] = {bh[0], bh[1]}, b1h[2] = {bh[2], bh[3]};
                uint32_t b0l[2] = {bl[0], bl[1]}, b1l[2] = {bl[2], bl[3]};
                MMA16816(sacc[ni2*2],   qh_f[ks], b0h);
                MMA16816(sacc[ni2*2],   qh_f[ks], b0l);
                MMA16816(sacc[ni2*2],   ql_f[ks], b0h);
                MMA16816(sacc[ni2*2+1], qh_f[ks], b1h);
                MMA16816(sacc[ni2*2+1], qh_f[ks], b1l);
                MMA16816(sacc[ni2*2+1], ql_f[ks], b1h);
            }
        }

        // ---- online softmax ----
        float mx0 = -INFINITY, mx1 = -INFINITY;
#pragma unroll
        for (int ni = 0; ni < 8; ni++) {
            mx0 = fmaxf(mx0, fmaxf(sacc[ni][0], sacc[ni][1]));
            mx1 = fmaxf(mx1, fmaxf(sacc[ni][2], sacc[ni][3]));
        }
        mx0 = fmaxf(mx0, __shfl_xor_sync(0xffffffffu, mx0, 1));
        mx0 = fmaxf(mx0, __shfl_xor_sync(0xffffffffu, mx0, 2));
        mx1 = fmaxf(mx1, __shfl_xor_sync(0xffffffffu, mx1, 1));
        mx1 = fmaxf(mx1, __shfl_xor_sync(0xffffffffu, mx1, 2));

        float mn0 = fmaxf(m0, mx0), mn1 = fmaxf(m1, mx1);
        float a0 = __expf(m0 - mn0), a1 = __expf(m1 - mn1);
        float s0 = 0.0f, s1 = 0.0f;
#pragma unroll
        for (int ni = 0; ni < 8; ni++) {
            sacc[ni][0] = __expf(sacc[ni][0] - mn0);
            sacc[ni][1] = __expf(sacc[ni][1] - mn0);
            sacc[ni][2] = __expf(sacc[ni][2] - mn1);
            sacc[ni][3] = __expf(sacc[ni][3] - mn1);
            s0 += sacc[ni][0] + sacc[ni][1];
            s1 += sacc[ni][2] + sacc[ni][3];
        }
        s0 += __shfl_xor_sync(0xffffffffu, s0, 1);
        s0 += __shfl_xor_sync(0xffffffffu, s0, 2);
        s1 += __shfl_xor_sync(0xffffffffu, s1, 1);
        s1 += __shfl_xor_sync(0xffffffffu, s1, 2);
        l0s = l0s * a0 + s0;
        l1s = l1s * a1 + s1;
        m0 = mn0; m1 = mn1;
#pragma unroll
        for (int ni = 0; ni < 8; ni++) {
            oacc[ni][0] *= a0; oacc[ni][1] *= a0;
            oacc[ni][2] *= a1; oacc[ni][3] *= a1;
        }

        // ---- O += P V ----
#pragma unroll
        for (int ksv = 0; ksv < 4; ksv++) {
            uint32_t ph[4], pl[4];
            {
                __nv_bfloat162 hx, lx;
                split2(sacc[2*ksv][0],   sacc[2*ksv][1],   hx, lx);
                ph[0] = *(uint32_t*)&hx; pl[0] = *(uint32_t*)&lx;
                split2(sacc[2*ksv][2],   sacc[2*ksv][3],   hx, lx);
                ph[1] = *(uint32_t*)&hx; pl[1] = *(uint32_t*)&lx;
                split2(sacc[2*ksv+1][0], sacc[2*ksv+1][1], hx, lx);
                ph[2] = *(uint32_t*)&hx; pl[2] = *(uint32_t*)&lx;
                split2(sacc[2*ksv+1][2], sacc[2*ksv+1][3], hx, lx);
                ph[3] = *(uint32_t*)&hx; pl[3] = *(uint32_t*)&lx;
            }
#pragma unroll
            for (int db = 0; db < 4; db++) {
                int off = ((ksv * 16 + vro) * FS + db * 16 + vco) * 2;
                uint32_t vh4[4], vl4[4];
                LDM_X4_T(vh4, uVh + off);
                LDM_X4_T(vl4, uVl + off);
                uint32_t b0h[2] = {vh4[0], vh4[1]}, b1h[2] = {vh4[2], vh4[3]};
                uint32_t b0l[2] = {vl4[0], vl4[1]}, b1l[2] = {vl4[2], vl4[3]};
                MMA16816(oacc[db*2],   ph, b0h);
                MMA16816(oacc[db*2],   ph, b0l);
                MMA16816(oacc[db*2],   pl, b0h);
                MMA16816(oacc[db*2+1], ph, b1h);
                MMA16816(oacc[db*2+1], ph, b1l);
                MMA16816(oacc[db*2+1], pl, b1h);
            }
        }
    }

    // ---- epilogue ----
    float inv0 = 1.0f / l0s, inv1 = 1.0f / l1s;
    size_t r0g = (size_t)(b * SEQ + qb * 64 + w * 16 + (lane >> 2));
#pragma unroll
    for (int ni = 0; ni < 8; ni++) {
        int col = h * 64 + ni * 8 + (lane & 3) * 2;
        __nv_bfloat162 hx, lx;
        split2(oacc[ni][0] * inv0, oacc[ni][1] * inv0, hx, lx);
        *(__nv_bfloat162*)(outh + r0g * DMODEL + col) = hx;
        *(__nv_bfloat162*)(outl + r0g * DMODEL + col) = lx;
        split2(oacc[ni][2] * inv1, oacc[ni][3] * inv1, hx, lx);
        *(__nv_bfloat162*)(outh + (r0g + 8) * DMODEL + col) = hx;
        *(__nv_bfloat162*)(outl + (r0g + 8) * DMODEL + col) = lx;
    }
}

// -------- residual add + LayerNorm (in place on x; emits hi/lo) ----------
__global__ __launch_bounds__(256)
void add_ln_kernel(float* __restrict__ x, const float* __restrict__ o,
                   const float* __restrict__ sc, const float* __restrict__ bi,
                   __nv_bfloat16* __restrict__ xh, __nv_bfloat16* __restrict__ xl)
{
    int tok = blockIdx.x;
    int t = threadIdx.x;
    size_t base = (size_t)tok * DMODEL;
    float v0 = x[base + t]       + o[base + t];
    float v1 = x[base + t + 256] + o[base + t + 256];

    __shared__ float red[8];
    int warp = t >> 5, lane = t & 31;

    float s = v0 + v1;
#pragma unroll
    for (int off = 16; off; off >>= 1) s += __shfl_xor_sync(0xffffffffu, s, off);
    if (lane == 0) red[warp] = s;
    __syncthreads();
    float tot = 0.0f;
#pragma unroll
    for (int w = 0; w < 8; w++) tot += red[w];
    float mean = tot * (1.0f / 512.0f);

    float d0 = v0 - mean, d1 = v1 - mean;
    float q = d0 * d0 + d1 * d1;
#pragma unroll
    for (int off = 16; off; off >>= 1) q += __shfl_xor_sync(0xffffffffu, q, off);
    __syncthreads();
    if (lane == 0) red[warp] = q;
    __syncthreads();
    float tq = 0.0f;
#pragma unroll
    for (int w = 0; w < 8; w++) tq += red[w];
    float inv = rsqrtf(tq * (1.0f / 512.0f) + 1e-5f);

    float y0 = d0 * inv * sc[t]       + bi[t];
    float y1 = d1 * inv * sc[t + 256] + bi[t + 256];
    x[base + t]       = y0;
    x[base + t + 256] = y1;
    __nv_bfloat16 h0 = __float2bfloat16_rn(y0);
    __nv_bfloat16 h1 = __float2bfloat16_rn(y1);
    xh[base + t]       = h0;
    xh[base + t + 256] = h1;
    xl[base + t]       = __float2bfloat16_rn(y0 - __bfloat162float(h0));
    xl[base + t + 256] = __float2bfloat16_rn(y1 - __bfloat162float(h1));
}

// ------- gather init slots -> hi/lo bf16 [2560, 512] ----------------------
__global__ void gather_kernel(const float* __restrict__ x,
                              __nv_bfloat16* __restrict__ yh,
                              __nv_bfloat16* __restrict__ yl)
{
    int idx = blockIdx.x * blockDim.x + threadIdx.x;
    int d = idx & 511;
    int row = idx >> 9;
    int b = row / (PAIRS * 64);
    int r2 = row - b * (PAIRS * 64);
    int pair = r2 >> 6;
    int patch = r2 & 63;
    int s = pair * 128 + patch;
    float v = x[((size_t)(b * SEQ + s)) * DMODEL + d];
    __nv_bfloat16 hb = __float2bfloat16_rn(v);
    yh[idx] = hb;
    yl[idx] = __float2bfloat16_rn(v - __bfloat162float(hb));
}

// ---------------- depatchify to output --------------------------------
__global__ void depatch_kernel(const float* __restrict__ y, float* __restrict__ out)
{
    int idx = blockIdx.x * blockDim.x + threadIdx.x;
    int w = idx & 127;
    int h = (idx >> 7) & 127;
    int ch = (idx >> 14) & 1;
    int rest = idx >> 15;
    int pr = h >> 4, i = h & 15;
    int pc = w >> 4, j = w & 15;
    int row = rest * 64 + pr * 8 + pc;
    int fi = ch * 256 + i * 16 + j;
    out[idx] = y[(size_t)row * DMODEL + fi];
}

// ---------------- host launcher ----------------------------------------
extern "C" void kernel_launch(void* const* d_in, const int* in_sizes, int n_in,
                              void* d_out, int out_size)
{
    const float* initp     = (const float*)d_in[0];
    const float* endp      = (const float*)d_in[1];
    // d_in[2] = c_mask (bool) — unused by the reference forward
    const float* pre_W     = (const float*)d_in[3];
    const float* pre_b     = (const float*)d_in[4];
    const float* post_W    = (const float*)d_in[5];
    const float* post_b    = (const float*)d_in[6];
    const float* patch_pos = (const float*)d_in[7];
    const float* func_pos  = (const float*)d_in[8];
    const float* Wqkv      = (const float*)d_in[9];
    const float* bqkv      = (const float*)d_in[10];
    const float* Wo        = (const float*)d_in[11];
    const float* bo        = (const float*)d_in[12];
    const float* ln1s      = (const float*)d_in[13];
    const float* ln1b      = (const float*)d_in[14];
    const float* ln2s      = (const float*)d_in[15];
    const float* ln2b      = (const float*)d_in[16];
    const float* W1        = (const float*)d_in[17];
    const float* b1        = (const float*)d_in[18];
    const float* W2        = (const float*)d_in[19];
    const float* b2        = (const float*)d_in[20];
    float* out = (float*)d_out;

    float *px, *po;
    __nv_bfloat16 *wh, *wl, *qhb, *qlb, *inh, *inl, *xh, *xl, *ah, *al, *hh, *hl;
    cudaGetSymbolAddress((void**)&px,   g_x);
    cudaGetSymbolAddress((void**)&po,   g_o);
    cudaGetSymbolAddress((void**)&wh,   g_wh);
    cudaGetSymbolAddress((void**)&wl,   g_wl);
    cudaGetSymbolAddress((void**)&qhb,  g_qh);
    cudaGetSymbolAddress((void**)&qlb,  g_ql);
    cudaGetSymbolAddress((void**)&inh,  g_inh);
    cudaGetSymbolAddress((void**)&inl,  g_inl);
    cudaGetSymbolAddress((void**)&xh,   g_xh);
    cudaGetSymbolAddress((void**)&xl,   g_xl);
    cudaGetSymbolAddress((void**)&ah,   g_ah);
    cudaGetSymbolAddress((void**)&al,   g_al);
    cudaGetSymbolAddress((void**)&hh,   g_hh);
    cudaGetSymbolAddress((void**)&hl,   g_hl);

    static bool attr_set = false;
    if (!attr_set) {
        cudaFuncSetAttribute(gemm_bf, cudaFuncAttributeMaxDynamicSharedMemorySize, GB_SMEM);
        cudaFuncSetAttribute(flash_mma, cudaFuncAttributeMaxDynamicSharedMemorySize, FL_SMEM);
        attr_set = true;
    }

    const int TOKELEM = NTOK * DMODEL;

    // ---- weight hi/lo conversion ----
    {
        struct { const float* s; int off; int n; } wjobs[6] = {
            {pre_W,  W_PRE,  512*512},
            {Wqkv,   W_QKV,  6*1536*512},
            {Wo,     W_WO,   6*512*512},
            {W1,     W_W1,   6*2048*512},
            {W2,     W_W2,   6*512*2048},
            {post_W, W_POST, 512*512},
        };
        for (int i = 0; i < 6; i++) {
            int n4 = wjobs[i].n >> 2;
            cvt_w<<<(n4 + 255) / 256, 256>>>(wjobs[i].s, wh + wjobs[i].off, wl + wjobs[i].off, n4);
        }
    }

    // embed
    patchify_kernel<<<TOKELEM / 256, 256>>>(initp, endp, inh, inl);
    gemm_bf<<<dim3(DMODEL / 64, NTOK / 128), 128, GB_SMEM>>>(
        inh, inl, wh + W_PRE, wl + W_PRE, pre_b, px, nullptr, nullptr, 512, DMODEL, 0);
    add_pos_kernel<<<TOKELEM / 256, 256>>>(px, patch_pos, func_pos, xh, xl);

    for (int l = 0; l < NLAYER; l++) {
        const __nv_bfloat16* qh = wh + W_QKV + (size_t)l * 1536 * 512;
        const __nv_bfloat16* ql = wl + W_QKV + (size_t)l * 1536 * 512;
        const __nv_bfloat16* oh = wh + W_WO  + (size_t)l * 512 * 512;
        const __nv_bfloat16* ol = wl + W_WO  + (size_t)l * 512 * 512;
        const __nv_bfloat16* f1h = wh + W_W1 + (size_t)l * 2048 * 512;
        const __nv_bfloat16* f1l = wl + W_W1 + (size_t)l * 2048 * 512;
        const __nv_bfloat16* f2h = wh + W_W2 + (size_t)l * 512 * 2048;
        const __nv_bfloat16* f2l = wl + W_W2 + (size_t)l * 512 * 2048;
        const float* bqkv_l = bqkv + (size_t)l * 1536;
        const float* bo_l   = bo   + (size_t)l * DMODEL;
        const float* b1_l   = b1   + (size_t)l * DFFN;
        const float* b2_l   = b2   + (size_t)l * DMODEL;

        gemm_bf<<<dim3(1536 / 64, NTOK / 128), 128, GB_SMEM>>>(
            xh, xl, qh, ql, bqkv_l, nullptr, qhb, qlb, 512, 1536, 3);
        flash_mma<<<dim3(SEQ / 64, NHEAD, BSZ), 128, FL_SMEM>>>(qhb, qlb, ah, al);
        gemm_bf<<<dim3(DMODEL / 64, NTOK / 128), 128, GB_SMEM>>>(
            ah, al, oh, ol, bo_l, po, nullptr, nullptr, 512, DMODEL, 0);
        add_ln_kernel<<<NTOK, 256>>>(px, po, ln1s + (size_t)l * DMODEL,
                                     ln1b + (size_t)l * DMODEL, xh, xl);
        gemm_bf<<<dim3(DFFN / 64, NTOK / 128), 128, GB_SMEM>>>(
            xh, xl, f1h, f1l, b1_l, nullptr, hh, hl, 512, DFFN, 2);
        gemm_bf<<<dim3(DMODEL / 64, NTOK / 128), 128, GB_SMEM>>>(
            hh, hl, f2h, f2l, b2_l, po, nullptr, nullptr, 2048, DMODEL, 0);
        add_ln_kernel<<<NTOK, 256>>>(px, po, ln2s + (size_t)l * DMODEL,
                                     ln2b + (size_t)l * DMODEL, xh, xl);
    }

    // output head
    gather_kernel<<<(NSEL * DMODEL) / 256, 256>>>(px, inh, inl);
    gemm_bf<<<dim3(DMODEL / 64, NSEL / 128), 128, GB_SMEM>>>(
        inh, inl, wh + W_POST, wl + W_POST, post_b, po, nullptr, nullptr, 512, DMODEL, 0);
    depatch_kernel<<<(BSZ * PAIRS * CCH * HWDIM * HWDIM) / 256, 256>>>(po, out);
}

// round 17
// speedup vs baseline: 4.2792x; 1.3904x over previous
#include <cuda_runtime.h>
#include <cuda_fp16.h>
#include <math.h>
#include <stdint.h>

// ---------------- problem constants ----------------
#define BSZ     8
#define PAIRS   5
#define CCH     2
#define PGRID   8          // P
#define RRES    16         // R
#define HWDIM   128        // P*R
#define SEQ     640        // PAIRS*2*P*P
#define DMODEL  512
#define NHEAD   8
#define DHEAD   64
#define DFFN    2048
#define NLAYER  6
#define NTOK    (BSZ*SEQ)  // 5120
#define NSEL    (BSZ*PAIRS*PGRID*PGRID)  // 2560

// ---------------- weight hi/lo buffer offsets ----------------
#define W_PRE   0
#define W_QKV   (W_PRE  + 512*512)
#define W_WO    (W_QKV  + 6*1536*512)
#define W_W1    (W_WO   + 6*512*512)
#define W_W2    (W_W1   + 6*2048*512)
#define W_POST  (W_W2   + 6*512*2048)
#define W_TOT   (W_POST + 512*512)

// ---------------- scratch (device globals; no allocation allowed) ----------
__device__ float g_x  [NTOK*DMODEL];          // token stream f (fp32, residual)
__device__ float g_o  [NTOK*DMODEL];          // gemm fp32 output (Wo / W2 / post)
__device__ __half g_wh[W_TOT], g_wl[W_TOT];               // weights hi/lo (fp16)
__device__ __half g_qh[NTOK*3*DMODEL], g_ql[NTOK*3*DMODEL]; // qkv hi/lo (Q pre-scaled)
__device__ __half g_in[NTOK*DMODEL];          // patchify / gather out (act, fp16)
__device__ __half g_xa[NTOK*DMODEL];          // x activations (fp16)
__device__ __half g_aa[NTOK*DMODEL];          // attention out (fp16)
__device__ __half g_ha[NTOK*DFFN];            // FF hidden (fp16)

// ================= helpers =================
__device__ __forceinline__ uint32_t smem_u32(const void* p) {
    uint32_t a;
    asm("{ .reg .u64 t; cvta.to.shared.u64 t, %1; cvt.u32.u64 %0, t; }" : "=r"(a) : "l"(p));
    return a;
}

__device__ __forceinline__ void split2h(float a, float b, __half2& h, __half2& l)
{
    h = __floats2half2_rn(a, b);
    l = __floats2half2_rn(a - __half2float(__low2half(h)),
                          b - __half2float(__high2half(h)));
}

#define LDM_X4(r, addr) \
    asm volatile("ldmatrix.sync.aligned.m8n8.x4.shared.b16 {%0,%1,%2,%3}, [%4];" \
        : "=r"((r)[0]), "=r"((r)[1]), "=r"((r)[2]), "=r"((r)[3]) : "r"(addr))

#define LDM_X4_T(r, addr) \
    asm volatile("ldmatrix.sync.aligned.m8n8.x4.trans.shared.b16 {%0,%1,%2,%3}, [%4];" \
        : "=r"((r)[0]), "=r"((r)[1]), "=r"((r)[2]), "=r"((r)[3]) : "r"(addr))

#define MMA16816H(c, a, b) \
    asm volatile("mma.sync.aligned.m16n8k16.row.col.f32.f16.f16.f32 " \
        "{%0,%1,%2,%3}, {%4,%5,%6,%7}, {%8,%9}, {%0,%1,%2,%3};" \
        : "+f"((c)[0]), "+f"((c)[1]), "+f"((c)[2]), "+f"((c)[3]) \
        : "r"((a)[0]), "r"((a)[1]), "r"((a)[2]), "r"((a)[3]), "r"((b)[0]), "r"((b)[1]))

#define CP16(saddr, gptr) \
    asm volatile("cp.async.cg.shared.global [%0], [%1], 16;" :: "r"(saddr), "l"(gptr) : "memory")
#define CP_COMMIT() asm volatile("cp.async.commit_group;" ::: "memory")

// ---------------- weight fp32 -> fp16 hi/lo converter ----------------
__global__ void cvt_w(const float* __restrict__ src, __half* __restrict__ dh,
                      __half* __restrict__ dl, int n4)
{
    int i = blockIdx.x * 256 + threadIdx.x;
    if (i >= n4) return;
    float4 v = ((const float4*)src)[i];
    __half2 h0, l0, h1, l1;
    split2h(v.x, v.y, h0, l0);
    split2h(v.z, v.w, h1, l1);
    *(__half2*)(dh + 4 * (size_t)i)     = h0;
    *(__half2*)(dh + 4 * (size_t)i + 2) = h1;
    *(__half2*)(dl + 4 * (size_t)i)     = l0;
    *(__half2*)(dl + 4 * (size_t)i + 2) = l1;
}

// ---------------- patchify: (init,end) -> fp16 [5120, 512] -----------
__global__ void patchify_kernel(const float* __restrict__ initp,
                                const float* __restrict__ endp,
                                __half* __restrict__ X)
{
    int idx = blockIdx.x * blockDim.x + threadIdx.x;
    int fi = idx & 511;
    int n  = idx >> 9;
    int b  = n / SEQ;
    int s  = n - b * SEQ;
    int fn = s >> 6;
    int patch = s & 63;
    int pair = fn >> 1, io = fn & 1;
    int pr = patch >> 3, pc = patch & 7;
    int ch = fi >> 8;
    int rem = fi & 255;
    int i = rem >> 4, j = rem & 15;
    const float* src = io ? endp : initp;
    int h = pr * RRES + i, w = pc * RRES + j;
    float v = src[((((size_t)b * PAIRS + pair) * CCH + ch) * HWDIM + h) * HWDIM + w];
    X[idx] = __float2half_rn(v);
}

// ---------------- positional add (updates fp32 x, emits fp16) --------------
__global__ void add_pos_kernel(float* __restrict__ x,
                               const float* __restrict__ patch_pos,
                               const float* __restrict__ func_pos,
                               __half* __restrict__ xa)
{
    int idx = blockIdx.x * blockDim.x + threadIdx.x;
    int d = idx & 511;
    int n = idx >> 9;
    int s = n % SEQ;
    int fn = s >> 6;
    int patch = s & 63;
    float v = x[idx] + patch_pos[patch * DMODEL + d] + func_pos[fn * DMODEL + d];
    x[idx] = v;
    xa[idx] = __float2half_rn(v);
}

// =============== fp16 MMA GEMM: C = A[N,K] @ W[J,K]^T + bias ==============
// A plain fp16; W as fp16 hi/lo. 2 MMA passes: A*Wh + A*Wl (= A*W exact in W).
// Block tile 128x64, 128 threads / 4 warps (2x2), warp tile 64x32, K-chunk 32.
// cp.async 2-stage, one sync per chunk.
// mode 0: fp32 out. mode 2: GELU + fp16 out (Ch). mode 3: qkv fp16 hi/lo out
// (cols < 512 scaled by 0.125).
#define GS     40                       // padded smem stride (fp16)
#define ATB    (128 * GS * 2)           // 10240 B A tile
#define WTB    (64 * GS * 2)            // 5120 B per W tile
#define STAGE  (ATB + 2 * WTB)          // 20480 B
#define GB_SMEM (2 * STAGE)             // 40960 B

__global__ __launch_bounds__(128, 1)
void gemm_hf(const __half* __restrict__ A,
             const __half* __restrict__ Wh, const __half* __restrict__ Wl,
             const float* __restrict__ bias,
             float* __restrict__ Cf,
             __half* __restrict__ Ch, __half* __restrict__ Cl,
             int K, int J, int mode)
{
    extern __shared__ char smem[];
    const uint32_t sbase = smem_u32(smem);
    const int t = threadIdx.x;
    const int lane = t & 31, wid = t >> 5;
    const int wr = wid >> 1, wc = wid & 1;          // warp grid 2 x 2
    const int n0 = blockIdx.y * 128, j0 = blockIdx.x * 64;

    float acc[4][4][4];
#pragma unroll
    for (int mi = 0; mi < 4; mi++)
#pragma unroll
        for (int ni = 0; ni < 4; ni++)
#pragma unroll
            for (int e = 0; e < 4; e++) acc[mi][ni][e] = 0.0f;

    const int aoff = ((wr * 64 + (lane & 15)) * GS + ((lane >> 4) << 3)) * 2;
    const int boff = ((wc * 32 + (lane & 7) + ((lane >> 4) << 3)) * GS
                      + (((lane >> 3) & 1) << 3)) * 2;

    const int NC = K >> 5;

    auto issue = [&](int c) {
        uint32_t st = sbase + (uint32_t)(c & 1) * STAGE;
        int kc = c << 5;
#pragma unroll
        for (int u = 0; u < 4; u++) {               // A: 512 segs of 16B
            int s = u * 128 + t;
            int row = s >> 2, seg = s & 3;
            size_t g = (size_t)(n0 + row) * K + kc + seg * 8;
            CP16(st + (uint32_t)(row * 80 + seg * 16), A + g);
        }
#pragma unroll
        for (int u = 0; u < 2; u++) {               // W: 256 segs of 16B
            int s = u * 128 + t;
            int row = s >> 2, seg = s & 3;
            size_t g = (size_t)(j0 + row) * K + kc + seg * 8;
            uint32_t sw = st + ATB + (uint32_t)(row * 80 + seg * 16);
            CP16(sw,       Wh + g);
            CP16(sw + WTB, Wl + g);
        }
        CP_COMMIT();
    };

    issue(0);
    for (int c = 0; c < NC; c++) {
        asm volatile("cp.async.wait_group 0;" ::: "memory");
        __syncthreads();
        if (c + 1 < NC) issue(c + 1);

        const uint32_t sb = sbase + (uint32_t)(c & 1) * STAGE;
        const uint32_t uA = sb;
        const uint32_t uWh = sb + ATB, uWl = sb + ATB + WTB;

#pragma unroll
        for (int ks = 0; ks < 32; ks += 16) {
            uint32_t Af[4][4], Bhf[4][2], Blf[4][2];
#pragma unroll
            for (int mi = 0; mi < 4; mi++) {
                int d = (mi * 16 * GS + ks) * 2;
                LDM_X4(Af[mi], uA + aoff + d);
            }
#pragma unroll
            for (int pi = 0; pi < 2; pi++) {
                int d = (pi * 16 * GS + ks) * 2;
                uint32_t r[4];
                LDM_X4(r, uWh + boff + d);
                Bhf[2*pi][0] = r[0]; Bhf[2*pi][1] = r[1];
                Bhf[2*pi+1][0] = r[2]; Bhf[2*pi+1][1] = r[3];
                LDM_X4(r, uWl + boff + d);
                Blf[2*pi][0] = r[0]; Blf[2*pi][1] = r[1];
                Blf[2*pi+1][0] = r[2]; Blf[2*pi+1][1] = r[3];
            }
#pragma unroll
            for (int mi = 0; mi < 4; mi++)
#pragma unroll
                for (int ni = 0; ni < 4; ni++) {
                    MMA16816H(acc[mi][ni], Af[mi], Bhf[ni]);
                    MMA16816H(acc[mi][ni], Af[mi], Blf[ni]);
                }
        }
    }

#pragma unroll
    for (int mi = 0; mi < 4; mi++) {
        int r0 = n0 + wr * 64 + mi * 16 + (lane >> 2);
#pragma unroll
        for (int ni = 0; ni < 4; ni++) {
            int col = j0 + wc * 32 + ni * 8 + (lane & 3) * 2;
            float b0v = bias[col], b1v = bias[col + 1];
            float v0 = acc[mi][ni][0] + b0v;
            float v1 = acc[mi][ni][1] + b1v;
            float v2 = acc[mi][ni][2] + b0v;
            float v3 = acc[mi][ni][3] + b1v;
            if (mode == 0) {
                *(float2*)(Cf + (size_t)r0 * J + col)       = make_float2(v0, v1);
                *(float2*)(Cf + (size_t)(r0 + 8) * J + col) = make_float2(v2, v3);
            } else if (mode == 2) {
                v0 = 0.5f * v0 * (1.0f + erff(v0 * 0.70710678118654752f));
                v1 = 0.5f * v1 * (1.0f + erff(v1 * 0.70710678118654752f));
                v2 = 0.5f * v2 * (1.0f + erff(v2 * 0.70710678118654752f));
                v3 = 0.5f * v3 * (1.0f + erff(v3 * 0.70710678118654752f));
                *(__half2*)(Ch + (size_t)r0 * J + col)       = __floats2half2_rn(v0, v1);
                *(__half2*)(Ch + (size_t)(r0 + 8) * J + col) = __floats2half2_rn(v2, v3);
            } else {                       // mode 3: qkv hi/lo, scale Q columns
                float sc = (col < 512) ? 0.125f : 1.0f;
                v0 *= sc; v1 *= sc; v2 *= sc; v3 *= sc;
                __half2 h01, l01, h23, l23;
                split2h(v0, v1, h01, l01);
                split2h(v2, v3, h23, l23);
                *(__half2*)(Ch + (size_t)r0 * J + col)       = h01;
                *(__half2*)(Cl + (size_t)r0 * J + col)       = l01;
                *(__half2*)(Ch + (size_t)(r0 + 8) * J + col) = h23;
                *(__half2*)(Cl + (size_t)(r0 + 8) * J + col) = l23;
            }
        }
    }
}

// =============== MMA flash attention, block-causal (64-token blocks) ======
// Inputs: qkv fp16 hi/lo [b, s, 1536] (Q pre-scaled by 0.125).
// 3-pass hi/lo MMA for S and PV (score precision ~2^-22).
// Output: plain fp16 attention activations.
#define FS   72                    // smem stride (fp16 elems)
#define FTB  (64 * FS * 2)         // 9216 B per tile
#define FKV_OFF (2 * FTB)
#define FSTG (4 * FTB)             // Khi,Klo,Vhi,Vlo = 36864 B
#define FL_SMEM (2 * FTB + 2 * FSTG)   // 92160 B

__global__ __launch_bounds__(128)
void flash_mma(const __half* __restrict__ qh, const __half* __restrict__ ql,
               __half* __restrict__ outa)
{
    extern __shared__ char fsm[];
    const uint32_t sb = smem_u32(fsm);
    const int qb = blockIdx.x, h = blockIdx.y, b = blockIdx.z;
    const int t = threadIdx.x, lane = t & 31, w = t >> 5;

    const uint32_t uQh = sb, uQl = sb + FTB;

    {
        size_t qbase = (size_t)(b * SEQ + qb * 64) * 1536 + h * 64;
#pragma unroll
        for (int u = 0; u < 4; u++) {
            int s = u * 128 + t;
            int row = s >> 3, seg = s & 7;
            uint32_t d = (uint32_t)(row * 144 + seg * 16);
            size_t g = qbase + (size_t)row * 1536 + seg * 8;
            CP16(uQh + d, qh + g);
            CP16(uQl + d, ql + g);
        }
        CP_COMMIT();
    }

    auto issue_kv = [&](int kb) {
        uint32_t st = sb + FKV_OFF + (uint32_t)(kb & 1) * FSTG;
        size_t kbase = (size_t)(b * SEQ + kb * 64) * 1536 + 512 + h * 64;
#pragma unroll
        for (int u = 0; u < 4; u++) {
            int s = u * 128 + t;
            int row = s >> 3, seg = s & 7;
            uint32_t d = (uint32_t)(row * 144 + seg * 16);
            size_t gk = kbase + (size_t)row * 1536 + seg * 8;
            CP16(st + d,           qh + gk);
            CP16(st + FTB + d,     ql + gk);
            CP16(st + 2*FTB + d,   qh + gk + 512);
            CP16(st + 3*FTB + d,   ql + gk + 512);
        }
        CP_COMMIT();
    };
    issue_kv(0);

    asm volatile("cp.async.wait_group 1;" ::: "memory");
    __syncthreads();

    uint32_t qh_f[4][4], ql_f[4][4];
    {
        int ro = (w * 16 + (lane & 15)) * FS + ((lane >> 4) << 3);
#pragma unroll
        for (int ks = 0; ks < 4; ks++) {
            LDM_X4(qh_f[ks], uQh + (ro + ks * 16) * 2);
            LDM_X4(ql_f[ks], uQl + (ro + ks * 16) * 2);
        }
    }

    float oacc[8][4];
#pragma unroll
    for (int ni = 0; ni < 8; ni++)
#pragma unroll
        for (int e = 0; e < 4; e++) oacc[ni][e] = 0.0f;
    float m0 = -INFINITY, m1 = -INFINITY, l0s = 0.0f, l1s = 0.0f;

    const int krowp = (lane & 7) + ((lane >> 4) << 3);
    const int kcolp = ((lane >> 3) & 1) << 3;
    const int vro = (lane & 15);
    const int vco = ((lane >> 4) << 3);

    for (int kb = 0; kb <= qb; kb++) {
        asm volatile("cp.async.wait_group 0;" ::: "memory");
        __syncthreads();
        if (kb < qb) issue_kv(kb + 1);

        const uint32_t uKh = sb + FKV_OFF + (uint32_t)(kb & 1) * FSTG;
        const uint32_t uKl = uKh + FTB, uVh = uKh + 2 * FTB, uVl = uKh + 3 * FTB;

        float sacc[8][4];
#pragma unroll
        for (int ni = 0; ni < 8; ni++)
#pragma unroll
            for (int e = 0; e < 4; e++) sacc[ni][e] = 0.0f;

#pragma unroll
        for (int ks = 0; ks < 4; ks++) {
#pragma unroll
            for (int ni2 = 0; ni2 < 4; ni2++) {
                int off = ((ni2 * 16 + krowp) * FS + ks * 16 + kcolp) * 2;
                uint32_t bh[4], bl[4];
                LDM_X4(bh, uKh + off);
                LDM_X4(bl, uKl + off);
                uint32_t b0h[2] = {bh[0], bh[1]}, b1h[2] = {bh[2], bh[3]};
                uint32_t b0l[2] = {bl[0], bl[1]}, b1l[2] = {bl[2], bl[3]};
                MMA16816H(sacc[ni2*2],   qh_f[ks], b0h);
                MMA16816H(sacc[ni2*2],   qh_f[ks], b0l);
                MMA16816H(sacc[ni2*2],   ql_f[ks], b0h);
                MMA16816H(sacc[ni2*2+1], qh_f[ks], b1h);
                MMA16816H(sacc[ni2*2+1], qh_f[ks], b1l);
                MMA16816H(sacc[ni2*2+1], ql_f[ks], b1h);
            }
        }

        float mx0 = -INFINITY, mx1 = -INFINITY;
#pragma unroll
        for (int ni = 0; ni < 8; ni++) {
            mx0 = fmaxf(mx0, fmaxf(sacc[ni][0], sacc[ni][1]));
            mx1 = fmaxf(mx1, fmaxf(sacc[ni][2], sacc[ni][3]));
        }
        mx0 = fmaxf(mx0, __shfl_xor_sync(0xffffffffu, mx0, 1));
        mx0 = fmaxf(mx0, __shfl_xor_sync(0xffffffffu, mx0, 2));
        mx1 = fmaxf(mx1, __shfl_xor_sync(0xffffffffu, mx1, 1));
        mx1 = fmaxf(mx1, __shfl_xor_sync(0xffffffffu, mx1, 2));

        float mn0 = fmaxf(m0, mx0), mn1 = fmaxf(m1, mx1);
        float a0 = __expf(m0 - mn0), a1 = __expf(m1 - mn1);
        float s0 = 0.0f, s1 = 0.0f;
#pragma unroll
        for (int ni = 0; ni < 8; ni++) {
            sacc[ni][0] = __expf(sacc[ni][0] - mn0);
            sacc[ni][1] = __expf(sacc[ni][1] - mn0);
            sacc[ni][2] = __expf(sacc[ni][2] - mn1);
            sacc[ni][3] = __expf(sacc[ni][3] - mn1);
            s0 += sacc[ni][0] + sacc[ni][1];
            s1 += sacc[ni][2] + sacc[ni][3];
        }
        s0 += __shfl_xor_sync(0xffffffffu, s0, 1);
        s0 += __shfl_xor_sync(0xffffffffu, s0, 2);
        s1 += __shfl_xor_sync(0xffffffffu, s1, 1);
        s1 += __shfl_xor_sync(0xffffffffu, s1, 2);
        l0s = l0s * a0 + s0;
        l1s = l1s * a1 + s1;
        m0 = mn0; m1 = mn1;
#pragma unroll
        for (int ni = 0; ni < 8; ni++) {
            oacc[ni][0] *= a0; oacc[ni][1] *= a0;
            oacc[ni][2] *= a1; oacc[ni][3] *= a1;
        }

#pragma unroll
        for (int ksv = 0; ksv < 4; ksv++) {
            uint32_t ph[4], pl[4];
            {
                __half2 hx, lx;
                split2h(sacc[2*ksv][0],   sacc[2*ksv][1],   hx, lx);
                ph[0] = *(uint32_t*)&hx; pl[0] = *(uint32_t*)&lx;
                split2h(sacc[2*ksv][2],   sacc[2*ksv][3],   hx, lx);
                ph[1] = *(uint32_t*)&hx; pl[1] = *(uint32_t*)&lx;
                split2h(sacc[2*ksv+1][0], sacc[2*ksv+1][1], hx, lx);
                ph[2] = *(uint32_t*)&hx; pl[2] = *(uint32_t*)&lx;
                split2h(sacc[2*ksv+1][2], sacc[2*ksv+1][3], hx, lx);
                ph[3] = *(uint32_t*)&hx; pl[3] = *(uint32_t*)&lx;
            }
#pragma unroll
            for (int db = 0; db < 4; db++) {
                int off = ((ksv * 16 + vro) * FS + db * 16 + vco) * 2;
                uint32_t vh4[4], vl4[4];
                LDM_X4_T(vh4, uVh + off);
                LDM_X4_T(vl4, uVl + off);
                uint32_t b0h[2] = {vh4[0], vh4[1]}, b1h[2] = {vh4[2], vh4[3]};
                uint32_t b0l[2] = {vl4[0], vl4[1]}, b1l[2] = {vl4[2], vl4[3]};
                MMA16816H(oacc[db*2],   ph, b0h);
                MMA16816H(oacc[db*2],   ph, b0l);
                MMA16816H(oacc[db*2],   pl, b0h);
                MMA16816H(oacc[db*2+1], ph, b1h);
                MMA16816H(oacc[db*2+1], ph, b1l);
                MMA16816H(oacc[db*2+1], pl, b1h);
            }
        }
    }

    float inv0 = 1.0f / l0s, inv1 = 1.0f / l1s;
    size_t r0g = (size_t)(b * SEQ + qb * 64 + w * 16 + (lane >> 2));
#pragma unroll
    for (int ni = 0; ni < 8; ni++) {
        int col = h * 64 + ni * 8 + (lane & 3) * 2;
        *(__half2*)(outa + r0g * DMODEL + col) =
            __floats2half2_rn(oacc[ni][0] * inv0, oacc[ni][1] * inv0);
        *(__half2*)(outa + (r0g + 8) * DMODEL + col) =
            __floats2half2_rn(oacc[ni][2] * inv1, oacc[ni][3] * inv1);
    }
}

// -------- residual add + LayerNorm (in place on x; emits fp16) ------------
__global__ __launch_bounds__(256)
void add_ln_kernel(float* __restrict__ x, const float* __restrict__ o,
                   const float* __restrict__ sc, const float* __restrict__ bi,
                   __half* __restrict__ xa)
{
    int tok = blockIdx.x;
    int t = threadIdx.x;
    size_t base = (size_t)tok * DMODEL;
    float v0 = x[base + t]       + o[base + t];
    float v1 = x[base + t + 256] + o[base + t + 256];

    __shared__ float red[8];
    int warp = t >> 5, lane = t & 31;

    float s = v0 + v1;
#pragma unroll
    for (int off = 16; off; off >>= 1) s += __shfl_xor_sync(0xffffffffu, s, off);
    if (lane == 0) red[warp] = s;
    __syncthreads();
    float tot = 0.0f;
#pragma unroll
    for (int w = 0; w < 8; w++) tot += red[w];
    float mean = tot * (1.0f / 512.0f);

    float d0 = v0 - mean, d1 = v1 - mean;
    float q = d0 * d0 + d1 * d1;
#pragma unroll
    for (int off = 16; off; off >>= 1) q += __shfl_xor_sync(0xffffffffu, q, off);
    __syncthreads();
    if (lane == 0) red[warp] = q;
    __syncthreads();
    float tq = 0.0f;
#pragma unroll
    for (int w = 0; w < 8; w++) tq += red[w];
    float inv = rsqrtf(tq * (1.0f / 512.0f) + 1e-5f);

    float y0 = d0 * inv * sc[t]       + bi[t];
    float y1 = d1 * inv * sc[t + 256] + bi[t + 256];
    x[base + t]       = y0;
    x[base + t + 256] = y1;
    xa[base + t]       = __float2half_rn(y0);
    xa[base + t + 256] = __float2half_rn(y1);
}

// ------- gather init slots -> fp16 [2560, 512] ----------------------------
__global__ void gather_kernel(const float* __restrict__ x, __half* __restrict__ y)
{
    int idx = blockIdx.x * blockDim.x + threadIdx.x;
    int d = idx & 511;
    int row = idx >> 9;
    int b = row / (PAIRS * 64);
    int r2 = row - b * (PAIRS * 64);
    int pair = r2 >> 6;
    int patch = r2 & 63;
    int s = pair * 128 + patch;
    y[idx] = __float2half_rn(x[((size_t)(b * SEQ + s)) * DMODEL + d]);
}

// ---------------- depatchify to output --------------------------------
__global__ void depatch_kernel(const float* __restrict__ y, float* __restrict__ out)
{
    int idx = blockIdx.x * blockDim.x + threadIdx.x;
    int w = idx & 127;
    int h = (idx >> 7) & 127;
    int ch = (idx >> 14) & 1;
    int rest = idx >> 15;
    int pr = h >> 4, i = h & 15;
    int pc = w >> 4, j = w & 15;
    int row = rest * 64 + pr * 8 + pc;
    int fi = ch * 256 + i * 16 + j;
    out[idx] = y[(size_t)row * DMODEL + fi];
}

// ---------------- host launcher ----------------------------------------
extern "C" void kernel_launch(void* const* d_in, const int* in_sizes, int n_in,
                              void* d_out, int out_size)
{
    const float* initp     = (const float*)d_in[0];
    const float* endp      = (const float*)d_in[1];
    // d_in[2] = c_mask (bool) — unused by the reference forward
    const float* pre_W     = (const float*)d_in[3];
    const float* pre_b     = (const float*)d_in[4];
    const float* post_W    = (const float*)d_in[5];
    const float* post_b    = (const float*)d_in[6];
    const float* patch_pos = (const float*)d_in[7];
    const float* func_pos  = (const float*)d_in[8];
    const float* Wqkv      = (const float*)d_in[9];
    const float* bqkv      = (const float*)d_in[10];
    const float* Wo        = (const float*)d_in[11];
    const float* bo        = (const float*)d_in[12];
    const float* ln1s      = (const float*)d_in[13];
    const float* ln1b      = (const float*)d_in[14];
    const float* ln2s      = (const float*)d_in[15];
    const float* ln2b      = (const float*)d_in[16];
    const float* W1        = (const float*)d_in[17];
    const float* b1        = (const float*)d_in[18];
    const float* W2        = (const float*)d_in[19];
    const float* b2        = (const float*)d_in[20];
    float* out = (float*)d_out;

    float *px, *po;
    __half *wh, *wl, *qhb, *qlb, *pin, *pxa, *paa, *pha;
    cudaGetSymbolAddress((void**)&px,   g_x);
    cudaGetSymbolAddress((void**)&po,   g_o);
    cudaGetSymbolAddress((void**)&wh,   g_wh);
    cudaGetSymbolAddress((void**)&wl,   g_wl);
    cudaGetSymbolAddress((void**)&qhb,  g_qh);
    cudaGetSymbolAddress((void**)&qlb,  g_ql);
    cudaGetSymbolAddress((void**)&pin,  g_in);
    cudaGetSymbolAddress((void**)&pxa,  g_xa);
    cudaGetSymbolAddress((void**)&paa,  g_aa);
    cudaGetSymbolAddress((void**)&pha,  g_ha);

    static bool attr_set = false;
    if (!attr_set) {
        cudaFuncSetAttribute(gemm_hf, cudaFuncAttributeMaxDynamicSharedMemorySize, GB_SMEM);
        cudaFuncSetAttribute(flash_mma, cudaFuncAttributeMaxDynamicSharedMemorySize, FL_SMEM);
        attr_set = true;
    }

    const int TOKELEM = NTOK * DMODEL;

    // ---- weight hi/lo conversion ----
    {
        struct { const float* s; int off; int n; } wjobs[6] = {
            {pre_W,  W_PRE,  512*512},
            {Wqkv,   W_QKV,  6*1536*512},
            {Wo,     W_WO,   6*512*512},
            {W1,     W_W1,   6*2048*512},
            {W2,     W_W2,   6*512*2048},
            {post_W, W_POST, 512*512},
        };
        for (int i = 0; i < 6; i++) {
            int n4 = wjobs[i].n >> 2;
            cvt_w<<<(n4 + 255) / 256, 256>>>(wjobs[i].s, wh + wjobs[i].off, wl + wjobs[i].off, n4);
        }
    }

    // embed
    patchify_kernel<<<TOKELEM / 256, 256>>>(initp, endp, pin);
    gemm_hf<<<dim3(DMODEL / 64, NTOK / 128), 128, GB_SMEM>>>(
        pin, wh + W_PRE, wl + W_PRE, pre_b, px, nullptr, nullptr, 512, DMODEL, 0);
    add_pos_kernel<<<TOKELEM / 256, 256>>>(px, patch_pos, func_pos, pxa);

    for (int l = 0; l < NLAYER; l++) {
        const __half* qwh = wh + W_QKV + (size_t)l * 1536 * 512;
        const __half* qwl = wl + W_QKV + (size_t)l * 1536 * 512;
        const __half* owh = wh + W_WO  + (size_t)l * 512 * 512;
        const __half* owl = wl + W_WO  + (size_t)l * 512 * 512;
        const __half* f1h = wh + W_W1 + (size_t)l * 2048 * 512;
        const __half* f1l = wl + W_W1 + (size_t)l * 2048 * 512;
        const __half* f2h = wh + W_W2 + (size_t)l * 512 * 2048;
        const __half* f2l = wl + W_W2 + (size_t)l * 512 * 2048;
        const float* bqkv_l = bqkv + (size_t)l * 1536;
        const float* bo_l   = bo   + (size_t)l * DMODEL;
        const float* b1_l   = b1   + (size_t)l * DFFN;
        const float* b2_l   = b2   + (size_t)l * DMODEL;

        gemm_hf<<<dim3(1536 / 64, NTOK / 128), 128, GB_SMEM>>>(
            pxa, qwh, qwl, bqkv_l, nullptr, qhb, qlb, 512, 1536, 3);
        flash_mma<<<dim3(SEQ / 64, NHEAD, BSZ), 128, FL_SMEM>>>(qhb, qlb, paa);
        gemm_hf<<<dim3(DMODEL / 64, NTOK / 128), 128, GB_SMEM>>>(
            paa, owh, owl, bo_l, po, nullptr, nullptr, 512, DMODEL, 0);
        add_ln_kernel<<<NTOK, 256>>>(px, po, ln1s + (size_t)l * DMODEL,
                                     ln1b + (size_t)l * DMODEL, pxa);
        gemm_hf<<<dim3(DFFN / 64, NTOK / 128), 128, GB_SMEM>>>(
            pxa, f1h, f1l, b1_l, nullptr, pha, nullptr, 512, DFFN, 2);
        gemm_hf<<<dim3(DMODEL / 64, NTOK / 128), 128, GB_SMEM>>>(
            pha, f2h, f2l, b2_l, po, nullptr, nullptr, 2048, DMODEL, 0);
        add_ln_kernel<<<NTOK, 256>>>(px, po, ln2s + (size_t)l * DMODEL,
                                     ln2b + (size_t)l * DMODEL, pxa);
    }

    // output head
    gather_kernel<<<(NSEL * DMODEL) / 256, 256>>>(px, pin);
    gemm_hf<<<dim3(DMODEL / 64, NSEL / 128), 128, GB_SMEM>>>(
        pin, wh + W_POST, wl + W_POST, post_b, po, nullptr, nullptr, 512, DMODEL, 0);
    depatch_kernel<<<(BSZ * PAIRS * CCH * HWDIM * HWDIM) / 256, 256>>>(po, out);
}